// round 2
// baseline (speedup 1.0000x reference)
#include <cuda_runtime.h>
#include <math.h>

#define NB 4
#define NS 2048
#define ND 1024
#define NH 16
#define NDK 64
#define NDF 4096
#define NM (NB*NS)          // 8192 rows
#define LN_EPS 1e-5f

// ---------------- scratch (static device globals; no allocation allowed) ----
static __device__ float g_q[(size_t)NM*ND];       // [B,H,S,DK]
static __device__ float g_k[(size_t)NM*ND];
static __device__ float g_v[(size_t)NM*ND];
static __device__ float g_concat[(size_t)NM*ND];  // [B,S,D] attention context
static __device__ float g_tmp[(size_t)NM*ND];     // attn_out, later FFN2 out
static __device__ float g_x1[(size_t)NM*ND];      // after LN1
static __device__ float g_ffn[(size_t)NM*NDF];    // FFN hidden
static __device__ float g_g21[NH];                // softplus(gamma)/21

// ---------------- prep: softplus(gammas)/21 --------------------------------
__global__ void prep_kernel(const float* __restrict__ gammas) {
    int h = threadIdx.x;
    if (h < NH) {
        float x = gammas[h];
        float sp = (x > 0.f) ? (x + log1pf(expf(-x))) : log1pf(expf(x));
        g_g21[h] = sp * (1.0f / 21.0f);
    }
}

// ---------------- generic tiled GEMM: out = A[M,K] @ W[K,N] + bias ---------
// MODE 0: plain   MODE 1: relu   MODE 2: write to [B,H,S,DK] head-major
template<int MODE>
__global__ void __launch_bounds__(256)
gemm_kernel(const float* __restrict__ A, const float* __restrict__ W,
            const float* __restrict__ bias, float* __restrict__ out,
            int K, int N)
{
    __shared__ float As[2][16][132];
    __shared__ float Bs[2][16][132];

    const int t  = threadIdx.x;
    const int bm = blockIdx.y, bn = blockIdx.x;

    const int arow = t >> 2, acol = (t & 3) << 2;   // A: 128 rows x 16 k
    const int brow = t >> 5, bcol = (t & 31) << 2;  // B: 16 k x 128 cols

    const float* Ab = A + (size_t)(bm * 128) * K;
    const float* Wb = W + bn * 128;

    float4 a0, a1, b0, b1;
    // prologue: tile 0
    a0 = *(const float4*)(Ab + (size_t)arow * K + acol);
    a1 = *(const float4*)(Ab + (size_t)(arow + 64) * K + acol);
    b0 = *(const float4*)(Wb + (size_t)brow * N + bcol);
    b1 = *(const float4*)(Wb + (size_t)(brow + 8) * N + bcol);
    As[0][acol+0][arow] = a0.x; As[0][acol+1][arow] = a0.y;
    As[0][acol+2][arow] = a0.z; As[0][acol+3][arow] = a0.w;
    As[0][acol+0][arow+64] = a1.x; As[0][acol+1][arow+64] = a1.y;
    As[0][acol+2][arow+64] = a1.z; As[0][acol+3][arow+64] = a1.w;
    *(float4*)&Bs[0][brow][bcol]   = b0;
    *(float4*)&Bs[0][brow+8][bcol] = b1;
    __syncthreads();

    const int ty = t >> 4, tx = t & 15;
    float acc[8][8];
    #pragma unroll
    for (int i = 0; i < 8; i++)
        #pragma unroll
        for (int j = 0; j < 8; j++) acc[i][j] = 0.f;

    const int KT = K >> 4;
    int buf = 0;
    for (int kt = 0; kt < KT; ++kt) {
        if (kt + 1 < KT) {
            int k0 = (kt + 1) << 4;
            a0 = *(const float4*)(Ab + (size_t)arow * K + k0 + acol);
            a1 = *(const float4*)(Ab + (size_t)(arow + 64) * K + k0 + acol);
            b0 = *(const float4*)(Wb + (size_t)(k0 + brow) * N + bcol);
            b1 = *(const float4*)(Wb + (size_t)(k0 + brow + 8) * N + bcol);
        }
        #pragma unroll
        for (int k = 0; k < 16; k++) {
            float4 xa = *(const float4*)&As[buf][k][ty*8];
            float4 xb = *(const float4*)&As[buf][k][ty*8+4];
            float4 ya = *(const float4*)&Bs[buf][k][tx*8];
            float4 yb = *(const float4*)&Bs[buf][k][tx*8+4];
            float ar[8] = {xa.x,xa.y,xa.z,xa.w,xb.x,xb.y,xb.z,xb.w};
            float br[8] = {ya.x,ya.y,ya.z,ya.w,yb.x,yb.y,yb.z,yb.w};
            #pragma unroll
            for (int i = 0; i < 8; i++)
                #pragma unroll
                for (int j = 0; j < 8; j++)
                    acc[i][j] = fmaf(ar[i], br[j], acc[i][j]);
        }
        if (kt + 1 < KT) {
            int nb = buf ^ 1;
            As[nb][acol+0][arow] = a0.x; As[nb][acol+1][arow] = a0.y;
            As[nb][acol+2][arow] = a0.z; As[nb][acol+3][arow] = a0.w;
            As[nb][acol+0][arow+64] = a1.x; As[nb][acol+1][arow+64] = a1.y;
            As[nb][acol+2][arow+64] = a1.z; As[nb][acol+3][arow+64] = a1.w;
            *(float4*)&Bs[nb][brow][bcol]   = b0;
            *(float4*)&Bs[nb][brow+8][bcol] = b1;
        }
        __syncthreads();
        buf ^= 1;
    }

    const int gc0 = bn * 128 + tx * 8;
    #pragma unroll
    for (int i = 0; i < 8; i++) {
        int gr = bm * 128 + ty * 8 + i;
        if (MODE == 2) {
            int h = gc0 >> 6, d = gc0 & 63;        // 8 cols stay in one head
            int b = gr >> 11, s = gr & 2047;
            float* op = out + ((((size_t)b * NH + h) * NS + s) * NDK + d);
            #pragma unroll
            for (int j = 0; j < 8; j++) op[j] = acc[i][j] + bias[gc0 + j];
        } else {
            float* op = out + (size_t)gr * N + gc0;
            #pragma unroll
            for (int j = 0; j < 8; j++) {
                float vv = acc[i][j] + bias[gc0 + j];
                if (MODE == 1) vv = fmaxf(vv, 0.f);
                op[j] = vv;
            }
        }
    }
}

// ---------------- fused attention: scores + decay + causal softmax + ctx ---
// grid: (S/8, B*H), block 256. Each warp owns one query row of the 8-row tile.
// dyn smem: sc[8][2048] | kv[128][64] (XOR-swizzled granules) | qs[8][64]
#define ATTN_SMEM ((8*2048 + 128*64 + 8*64) * 4)

__global__ void __launch_bounds__(256)
attn_kernel(float* __restrict__ attw)
{
    extern __shared__ float sm[];
    float* sc  = sm;                 // 16384 floats
    float* kvf = sm + 8 * 2048;      // 8192 floats, swizzled
    float* qs  = kvf + 128 * 64;     // 512 floats

    const int t = threadIdx.x, lane = t & 31, r = t >> 5;
    const int bh = blockIdx.y;
    const int hh = bh & 15, bb = bh >> 4;
    const int qi0 = blockIdx.x << 3;
    const int qi  = qi0 + r;

    const float* qb = g_q + (size_t)bh * NS * NDK;
    const float* kb = g_k + (size_t)bh * NS * NDK;
    const float* vb = g_v + (size_t)bh * NS * NDK;
    const float g21 = g_g21[hh];

    if (t < 128) {
        int rr = t >> 4, d4 = (t & 15) << 2;
        *(float4*)&qs[(rr << 6) + d4] =
            *(const float4*)(qb + (size_t)(qi0 + rr) * NDK + d4);
    }
    __syncthreads();

    const int nch = (qi0 >> 7) + 1;   // chunks of 128 keys covering [0, qi0+7]

    // ---- phase 1: scores (decay + causal applied) into sc -----------------
    for (int ch = 0; ch < nch; ++ch) {
        int c0 = ch << 7;
        #pragma unroll
        for (int i = 0; i < 8; i++) {              // load K chunk, swizzled
            int f4 = t + (i << 8);
            int c = f4 >> 4, gd = f4 & 15;
            float4 val = *(const float4*)(kb + (size_t)(c0 + c) * NDK + (gd << 2));
            *(float4*)&kvf[(c << 6) + ((gd ^ (c & 15)) << 2)] = val;
        }
        __syncthreads();

        float acc[4] = {0.f, 0.f, 0.f, 0.f};
        const int sw = lane & 15;
        #pragma unroll
        for (int gd = 0; gd < 16; ++gd) {
            float4 qv = *(const float4*)&qs[(r << 6) + (gd << 2)];
            int g2 = (gd ^ sw) << 2;
            #pragma unroll
            for (int j = 0; j < 4; j++) {
                float4 kv = *(const float4*)&kvf[((lane + (j << 5)) << 6) + g2];
                acc[j] += qv.x*kv.x + qv.y*kv.y + qv.z*kv.z + qv.w*kv.w;
            }
        }
        #pragma unroll
        for (int j = 0; j < 4; j++) {
            int c = c0 + lane + (j << 5);
            float s;
            if (c <= qi) {
                float eff = fminf(__expf((float)(qi - c) * g21), 1e5f);
                s = acc[j] * 0.125f * eff;
            } else {
                s = -3.0e38f;
            }
            sc[(r << 11) + c] = s;
        }
        __syncthreads();
    }

    // ---- phase 2: per-row softmax, write normalized weights ---------------
    float mx = -3.0e38f;
    for (int c = lane; c <= qi; c += 32) mx = fmaxf(mx, sc[(r << 11) + c]);
    #pragma unroll
    for (int o = 16; o; o >>= 1) mx = fmaxf(mx, __shfl_xor_sync(0xffffffffu, mx, o));

    float sum = 0.f;
    for (int c = lane; c <= qi; c += 32) {
        float e = __expf(sc[(r << 11) + c] - mx);
        sc[(r << 11) + c] = e;
        sum += e;
    }
    #pragma unroll
    for (int o = 16; o; o >>= 1) sum += __shfl_xor_sync(0xffffffffu, sum, o);
    float inv = 1.0f / sum;

    float* arow_g = attw + ((size_t)bh * NS + qi) * NS;
    for (int c = lane; c < NS; c += 32) {
        float w = (c <= qi) ? sc[(r << 11) + c] * inv : 0.f;
        sc[(r << 11) + c] = w;
        arow_g[c] = w;
    }
    __syncthreads();

    // ---- phase 3: ctx = weights @ V ---------------------------------------
    float ax = 0.f, ay = 0.f;
    const int gd3 = lane >> 1, half = (lane & 1) << 1;
    for (int ch = 0; ch < nch; ++ch) {
        int c0 = ch << 7;
        #pragma unroll
        for (int i = 0; i < 8; i++) {              // load V chunk, swizzled
            int f4 = t + (i << 8);
            int c = f4 >> 4, gd = f4 & 15;
            float4 val = *(const float4*)(vb + (size_t)(c0 + c) * NDK + (gd << 2));
            *(float4*)&kvf[(c << 6) + ((gd ^ (c & 15)) << 2)] = val;
        }
        __syncthreads();
        #pragma unroll 4
        for (int c = 0; c < 128; c++) {
            float w = sc[(r << 11) + c0 + c];
            float2 vv = *(const float2*)&kvf[(c << 6) + ((gd3 ^ (c & 15)) << 2) + half];
            ax = fmaf(w, vv.x, ax);
            ay = fmaf(w, vv.y, ay);
        }
        __syncthreads();
    }
    float2 res; res.x = ax; res.y = ay;
    *(float2*)&g_concat[((size_t)bb * NS + qi) * ND + hh * NDK + (lane << 1)] = res;
}

// ---------------- residual + layernorm: out = LN(xa + xb) * s + b ----------
__global__ void __launch_bounds__(256)
ln_kernel(const float* __restrict__ xa, const float* __restrict__ xb,
          const float* __restrict__ sg, const float* __restrict__ bg,
          float* __restrict__ out)
{
    __shared__ float red[16];
    const int row = blockIdx.x, t = threadIdx.x;
    const int lane = t & 31, wid = t >> 5;
    const size_t base = (size_t)row * ND;

    float v[4];
    #pragma unroll
    for (int i = 0; i < 4; i++) {
        int idx = t + (i << 8);
        v[i] = xa[base + idx] + xb[base + idx];
    }
    float s = v[0] + v[1] + v[2] + v[3];
    #pragma unroll
    for (int o = 16; o; o >>= 1) s += __shfl_xor_sync(0xffffffffu, s, o);
    if (lane == 0) red[wid] = s;
    __syncthreads();
    if (t == 0) {
        float tot = 0.f;
        for (int i = 0; i < 8; i++) tot += red[i];
        red[8] = tot;
    }
    __syncthreads();
    const float mean = red[8] * (1.0f / ND);

    float q = 0.f;
    #pragma unroll
    for (int i = 0; i < 4; i++) { float d = v[i] - mean; q += d * d; }
    #pragma unroll
    for (int o = 16; o; o >>= 1) q += __shfl_xor_sync(0xffffffffu, q, o);
    if (lane == 0) red[wid] = q;
    __syncthreads();
    if (t == 0) {
        float tot = 0.f;
        for (int i = 0; i < 8; i++) tot += red[i];
        red[9] = tot;
    }
    __syncthreads();
    const float rs = rsqrtf(red[9] * (1.0f / ND) + LN_EPS);

    #pragma unroll
    for (int i = 0; i < 4; i++) {
        int idx = t + (i << 8);
        out[base + idx] = (v[i] - mean) * rs * sg[idx] + bg[idx];
    }
}

// ---------------- launcher --------------------------------------------------
extern "C" void kernel_launch(void* const* d_in, const int* in_sizes, int n_in,
                              void* d_out, int out_size)
{
    const float* query  = (const float*)d_in[0];
    const float* key    = (const float*)d_in[1];
    const float* values = (const float*)d_in[2];
    const float* Wk     = (const float*)d_in[3];
    const float* bk     = (const float*)d_in[4];
    const float* Wv     = (const float*)d_in[5];
    const float* bv     = (const float*)d_in[6];
    const float* Wout   = (const float*)d_in[7];
    const float* bout   = (const float*)d_in[8];
    const float* gammas = (const float*)d_in[9];
    const float* ln1_s  = (const float*)d_in[10];
    const float* ln1_b  = (const float*)d_in[11];
    const float* W1     = (const float*)d_in[12];
    const float* b1     = (const float*)d_in[13];
    const float* W2     = (const float*)d_in[14];
    const float* b2     = (const float*)d_in[15];
    const float* ln2_s  = (const float*)d_in[16];
    const float* ln2_b  = (const float*)d_in[17];

    float* out  = (float*)d_out;                       // x: [B,S,D]
    float* attw = out + (size_t)NM * ND;               // att_weight: [B,H,S,S]

    float *pq, *pk, *pv, *pcat, *ptmp, *px1, *pffn;
    cudaGetSymbolAddress((void**)&pq,   g_q);
    cudaGetSymbolAddress((void**)&pk,   g_k);
    cudaGetSymbolAddress((void**)&pv,   g_v);
    cudaGetSymbolAddress((void**)&pcat, g_concat);
    cudaGetSymbolAddress((void**)&ptmp, g_tmp);
    cudaGetSymbolAddress((void**)&px1,  g_x1);
    cudaGetSymbolAddress((void**)&pffn, g_ffn);

    cudaFuncSetAttribute(attn_kernel,
                         cudaFuncAttributeMaxDynamicSharedMemorySize, ATTN_SMEM);

    prep_kernel<<<1, 32>>>(gammas);

    // projections (q & k share Wk/bk per reference)
    gemm_kernel<2><<<dim3(8, 64), 256>>>(query,  Wk, bk, pq, ND, ND);
    gemm_kernel<2><<<dim3(8, 64), 256>>>(key,    Wk, bk, pk, ND, ND);
    gemm_kernel<2><<<dim3(8, 64), 256>>>(values, Wv, bv, pv, ND, ND);

    attn_kernel<<<dim3(NS / 8, NB * NH), 256, ATTN_SMEM>>>(attw);

    gemm_kernel<0><<<dim3(8, 64), 256>>>(pcat, Wout, bout, ptmp, ND, ND);
    ln_kernel<<<NM, 256>>>(query, ptmp, ln1_s, ln1_b, px1);

    gemm_kernel<1><<<dim3(32, 64), 256>>>(px1,  W1, b1, pffn, ND, NDF);
    gemm_kernel<0><<<dim3(8, 64),  256>>>(pffn, W2, b2, ptmp, NDF, ND);
    ln_kernel<<<NM, 256>>>(px1, ptmp, ln2_s, ln2_b, out);
}

// round 5
// speedup vs baseline: 1.3730x; 1.3730x over previous
#include <cuda_runtime.h>
#include <cuda_bf16.h>
#include <math.h>
#include <stdint.h>

#define NB 4
#define NS 2048
#define ND 1024
#define NH 16
#define NDK 64
#define NDF 4096
#define NM (NB*NS)          // 8192 rows
#define LN_EPS 1e-5f

// ---------------- scratch (static device globals; no allocation allowed) ----
static __device__ float g_q[(size_t)NM*ND];       // [B,H,S,DK]
static __device__ float g_k[(size_t)NM*ND];
static __device__ float g_v[(size_t)NM*ND];
static __device__ float g_concat[(size_t)NM*ND];  // [B,S,D] attention context
static __device__ float g_tmp[(size_t)NM*ND];     // attn_out, later FFN2 out
static __device__ float g_x1[(size_t)NM*ND];      // after LN1
static __device__ float g_ffn[(size_t)NM*NDF];    // FFN hidden
static __device__ float g_g21[NH];                // softplus(gamma)/21
// bf16 split planes
static __device__ __nv_bfloat16 g_ah[(size_t)NM*NDF];   // A hi plane
static __device__ __nv_bfloat16 g_al[(size_t)NM*NDF];   // A lo plane
static __device__ __nv_bfloat16 g_wh[(size_t)NDF*ND];   // W^T hi plane
static __device__ __nv_bfloat16 g_wl[(size_t)NDF*ND];   // W^T lo plane

// =================== PTX helpers (compute_103-safe) =========================
__device__ __forceinline__ uint32_t smem_u32(const void* p) {
    uint32_t a;
    asm("{ .reg .u64 t; cvta.to.shared.u64 t, %1; cvt.u32.u64 %0, t; }"
        : "=r"(a) : "l"(p));
    return a;
}
#define CP_ASYNC16(dst, src) \
    asm volatile("cp.async.cg.shared.global [%0], [%1], 16;" \
                 :: "r"(dst), "l"(src) : "memory")
#define CP_COMMIT() asm volatile("cp.async.commit_group;" ::: "memory")
#define CP_WAIT0()  asm volatile("cp.async.wait_group 0;" ::: "memory")
#define CP_WAIT1()  asm volatile("cp.async.wait_group 1;" ::: "memory")

__device__ __forceinline__ void ldsm4(uint32_t& r0, uint32_t& r1,
                                      uint32_t& r2, uint32_t& r3, uint32_t a) {
    asm volatile("ldmatrix.sync.aligned.m8n8.x4.shared.b16 {%0,%1,%2,%3}, [%4];"
                 : "=r"(r0), "=r"(r1), "=r"(r2), "=r"(r3) : "r"(a));
}
__device__ __forceinline__ void mma16816(float* c, const uint32_t* a,
                                         const uint32_t* b) {
    asm volatile("mma.sync.aligned.m16n8k16.row.col.f32.bf16.bf16.f32 "
                 "{%0,%1,%2,%3}, {%4,%5,%6,%7}, {%8,%9}, {%0,%1,%2,%3};"
                 : "+f"(c[0]), "+f"(c[1]), "+f"(c[2]), "+f"(c[3])
                 : "r"(a[0]), "r"(a[1]), "r"(a[2]), "r"(a[3]),
                   "r"(b[0]), "r"(b[1]));
}

// ---------------- prep: softplus(gammas)/21 --------------------------------
__global__ void prep_kernel(const float* __restrict__ gammas) {
    int h = threadIdx.x;
    if (h < NH) {
        float x = gammas[h];
        float sp = (x > 0.f) ? (x + log1pf(expf(-x))) : log1pf(expf(x));
        g_g21[h] = sp * (1.0f / 21.0f);
    }
}

// ---------------- fp32 FFMA GEMM (precision path for Q/K) ------------------
// out = A[M,K] @ W[K,N] + bias.  MODE 2: scatter to [B,H,S,DK] head-major
template<int MODE>
__global__ void __launch_bounds__(256)
gemm_f32(const float* __restrict__ A, const float* __restrict__ W,
         const float* __restrict__ bias, float* __restrict__ out,
         int K, int N)
{
    __shared__ float As[2][16][132];
    __shared__ float Bs[2][16][132];

    const int t  = threadIdx.x;
    const int bm = blockIdx.y, bn = blockIdx.x;

    const int arow = t >> 2, acol = (t & 3) << 2;
    const int brow = t >> 5, bcol = (t & 31) << 2;

    const float* Ab = A + (size_t)(bm * 128) * K;
    const float* Wb = W + bn * 128;

    float4 a0, a1, b0, b1;
    a0 = *(const float4*)(Ab + (size_t)arow * K + acol);
    a1 = *(const float4*)(Ab + (size_t)(arow + 64) * K + acol);
    b0 = *(const float4*)(Wb + (size_t)brow * N + bcol);
    b1 = *(const float4*)(Wb + (size_t)(brow + 8) * N + bcol);
    As[0][acol+0][arow] = a0.x; As[0][acol+1][arow] = a0.y;
    As[0][acol+2][arow] = a0.z; As[0][acol+3][arow] = a0.w;
    As[0][acol+0][arow+64] = a1.x; As[0][acol+1][arow+64] = a1.y;
    As[0][acol+2][arow+64] = a1.z; As[0][acol+3][arow+64] = a1.w;
    *(float4*)&Bs[0][brow][bcol]   = b0;
    *(float4*)&Bs[0][brow+8][bcol] = b1;
    __syncthreads();

    const int ty = t >> 4, tx = t & 15;
    float acc[8][8];
    #pragma unroll
    for (int i = 0; i < 8; i++)
        #pragma unroll
        for (int j = 0; j < 8; j++) acc[i][j] = 0.f;

    const int KT = K >> 4;
    int buf = 0;
    for (int kt = 0; kt < KT; ++kt) {
        if (kt + 1 < KT) {
            int k0 = (kt + 1) << 4;
            a0 = *(const float4*)(Ab + (size_t)arow * K + k0 + acol);
            a1 = *(const float4*)(Ab + (size_t)(arow + 64) * K + k0 + acol);
            b0 = *(const float4*)(Wb + (size_t)(k0 + brow) * N + bcol);
            b1 = *(const float4*)(Wb + (size_t)(k0 + brow + 8) * N + bcol);
        }
        #pragma unroll
        for (int k = 0; k < 16; k++) {
            float4 xa = *(const float4*)&As[buf][k][ty*8];
            float4 xb = *(const float4*)&As[buf][k][ty*8+4];
            float4 ya = *(const float4*)&Bs[buf][k][tx*8];
            float4 yb = *(const float4*)&Bs[buf][k][tx*8+4];
            float ar[8] = {xa.x,xa.y,xa.z,xa.w,xb.x,xb.y,xb.z,xb.w};
            float br[8] = {ya.x,ya.y,ya.z,ya.w,yb.x,yb.y,yb.z,yb.w};
            #pragma unroll
            for (int i = 0; i < 8; i++)
                #pragma unroll
                for (int j = 0; j < 8; j++)
                    acc[i][j] = fmaf(ar[i], br[j], acc[i][j]);
        }
        if (kt + 1 < KT) {
            int nb = buf ^ 1;
            As[nb][acol+0][arow] = a0.x; As[nb][acol+1][arow] = a0.y;
            As[nb][acol+2][arow] = a0.z; As[nb][acol+3][arow] = a0.w;
            As[nb][acol+0][arow+64] = a1.x; As[nb][acol+1][arow+64] = a1.y;
            As[nb][acol+2][arow+64] = a1.z; As[nb][acol+3][arow+64] = a1.w;
            *(float4*)&Bs[nb][brow][bcol]   = b0;
            *(float4*)&Bs[nb][brow+8][bcol] = b1;
        }
        __syncthreads();
        buf ^= 1;
    }

    const int gc0 = bn * 128 + tx * 8;
    #pragma unroll
    for (int i = 0; i < 8; i++) {
        int gr = bm * 128 + ty * 8 + i;
        if (MODE == 2) {
            int h = gc0 >> 6, d = gc0 & 63;
            int b = gr >> 11, s = gr & 2047;
            float* op = out + ((((size_t)b * NH + h) * NS + s) * NDK + d);
            #pragma unroll
            for (int j = 0; j < 8; j++) op[j] = acc[i][j] + bias[gc0 + j];
        } else {
            float* op = out + (size_t)gr * N + gc0;
            #pragma unroll
            for (int j = 0; j < 8; j++) op[j] = acc[i][j] + bias[gc0 + j];
        }
    }
}

// ---------------- fp32 -> bf16 hi/lo plane conversion ----------------------
__global__ void __launch_bounds__(256)
a_convert(const float* __restrict__ x, __nv_bfloat16* __restrict__ ph,
          __nv_bfloat16* __restrict__ pl)
{
    size_t i = ((size_t)blockIdx.x * 256 + threadIdx.x) * 8;
    float4 v0 = *(const float4*)(x + i);
    float4 v1 = *(const float4*)(x + i + 4);
    float vv[8] = {v0.x, v0.y, v0.z, v0.w, v1.x, v1.y, v1.z, v1.w};
    __align__(16) __nv_bfloat16 hh[8], ll[8];
    #pragma unroll
    for (int j = 0; j < 8; j++) {
        __nv_bfloat16 h = __float2bfloat16(vv[j]);
        hh[j] = h;
        ll[j] = __float2bfloat16(vv[j] - __bfloat162float(h));
    }
    *(uint4*)(ph + i) = *(uint4*)hh;
    *(uint4*)(pl + i) = *(uint4*)ll;
}

// ---------------- W[K,N] fp32 -> W^T[N,K] bf16 hi/lo -----------------------
__global__ void __launch_bounds__(256)
wt_convert(const float* __restrict__ W, __nv_bfloat16* __restrict__ th,
           __nv_bfloat16* __restrict__ tl, int K, int N)
{
    __shared__ float tile[32][33];
    int n0 = blockIdx.x * 32, k0 = blockIdx.y * 32;
    int tx = threadIdx.x & 31, ty = threadIdx.x >> 5;
    #pragma unroll
    for (int i = 0; i < 4; i++)
        tile[ty + i * 8][tx] = W[(size_t)(k0 + ty + i * 8) * N + n0 + tx];
    __syncthreads();
    #pragma unroll
    for (int i = 0; i < 4; i++) {
        float v = tile[tx][ty + i * 8];           // = W[k0+tx][n0+ty+i*8]
        size_t o = (size_t)(n0 + ty + i * 8) * K + k0 + tx;
        __nv_bfloat16 h = __float2bfloat16(v);
        th[o] = h;
        tl[o] = __float2bfloat16(v - __bfloat162float(h));
    }
}

// ---------------- split-bf16 HMMA GEMM --------------------------------------
// out[M,Nt] = A[M,K] @ W[K,Nt] + bias via Ahi*Bhi + Ahi*Blo + Alo*Bhi.
// CTA tile 128x128, K-chunk 32. 8 warps (4x2), warp tile 32x64.
#define PLANE_B 10240                       // 128 * 80
#define STAGE_B (4 * PLANE_B)               // Ahi|Alo|Bhi|Blo = 40 KB
#define GSMEM   (2 * STAGE_B)               // 80 KB

template<int MODE>   // 0 plain, 1 relu, 2 scatter to [B,H,S,DK]
__global__ void __launch_bounds__(256, 1)
mma_gemm(const __nv_bfloat16* __restrict__ ah, const __nv_bfloat16* __restrict__ al,
         const __nv_bfloat16* __restrict__ bh, const __nv_bfloat16* __restrict__ bl,
         const float* __restrict__ bias, float* __restrict__ out, int K, int Nt)
{
    extern __shared__ char dsm[];
    const uint32_t sb = smem_u32(dsm);

    const int t = threadIdx.x, wid = t >> 5, lane = t & 31;
    const int warp_m = wid & 3, warp_n = wid >> 2;
    const int m0 = blockIdx.y * 128, n0 = blockIdx.x * 128;

    const __nv_bfloat16* srcs[4] = {
        ah + (size_t)m0 * K, al + (size_t)m0 * K,
        bh + (size_t)n0 * K, bl + (size_t)n0 * K };

    uint32_t dsts[8];
    uint32_t rowK[8], segO[8];
    #pragma unroll
    for (int u = 0; u < 8; u++) {
        int g = t + (u << 8);
        int plane = g >> 9, rem = g & 511;
        int row = rem >> 2, seg = rem & 3;
        dsts[u] = plane * PLANE_B + row * 80 + seg * 16;
        rowK[u] = row; segO[u] = seg << 3;
    }

    const int a_row = warp_m * 32 + (lane & 15);
    const uint32_t a_col = (lane >> 4) * 16;
    const int b_row = warp_n * 64 + ((lane >> 4) << 3) + (lane & 7);
    const uint32_t b_col = ((lane >> 3) & 1) * 16;

    float acc[2][8][4];
    #pragma unroll
    for (int i = 0; i < 2; i++)
        #pragma unroll
        for (int j = 0; j < 8; j++)
            #pragma unroll
            for (int q = 0; q < 4; q++) acc[i][j][q] = 0.f;

    const int KT = K >> 5;
    int buf = 0;

    #pragma unroll
    for (int u = 0; u < 8; u++) {
        int plane = (t + (u << 8)) >> 9;
        const __nv_bfloat16* src = srcs[plane] + (size_t)rowK[u] * K + segO[u];
        CP_ASYNC16(sb + dsts[u], src);
    }
    CP_COMMIT();

    for (int kt = 0; kt < KT; ++kt) {
        if (kt + 1 < KT) {
            const int k0 = (kt + 1) << 5;
            const uint32_t base = sb + (buf ^ 1) * STAGE_B;
            #pragma unroll
            for (int u = 0; u < 8; u++) {
                int plane = (t + (u << 8)) >> 9;
                const __nv_bfloat16* src = srcs[plane] + (size_t)rowK[u] * K + k0 + segO[u];
                CP_ASYNC16(base + dsts[u], src);
            }
            CP_COMMIT();
            CP_WAIT1();
        } else {
            CP_WAIT0();
        }
        __syncthreads();

        const uint32_t st = sb + buf * STAGE_B;
        #pragma unroll
        for (int ks = 0; ks < 2; ++ks) {
            const uint32_t kb = ks * 32;
            uint32_t ahf[2][4], alf[2][4];
            #pragma unroll
            for (int i = 0; i < 2; i++) {
                uint32_t ra = st + (a_row + i * 16) * 80 + kb + a_col;
                ldsm4(ahf[i][0], ahf[i][1], ahf[i][2], ahf[i][3], ra);
                ldsm4(alf[i][0], alf[i][1], alf[i][2], alf[i][3], ra + PLANE_B);
            }
            uint32_t bhf[8][2], blf[8][2];
            #pragma unroll
            for (int jj = 0; jj < 4; jj++) {
                uint32_t rb = st + 2 * PLANE_B + (b_row + jj * 16) * 80 + kb + b_col;
                ldsm4(bhf[2*jj][0], bhf[2*jj][1], bhf[2*jj+1][0], bhf[2*jj+1][1], rb);
                ldsm4(blf[2*jj][0], blf[2*jj][1], blf[2*jj+1][0], blf[2*jj+1][1],
                      rb + PLANE_B);
            }
            #pragma unroll
            for (int i = 0; i < 2; i++)
                #pragma unroll
                for (int j = 0; j < 8; j++) {
                    mma16816(acc[i][j], ahf[i], bhf[j]);
                    mma16816(acc[i][j], ahf[i], blf[j]);
                    mma16816(acc[i][j], alf[i], bhf[j]);
                }
        }
        __syncthreads();
        buf ^= 1;
    }

    const int rb0 = m0 + warp_m * 32 + (lane >> 2);
    const int cb0 = n0 + warp_n * 64 + (lane & 3) * 2;
    #pragma unroll
    for (int i = 0; i < 2; i++) {
        #pragma unroll
        for (int j = 0; j < 8; j++) {
            const int col = cb0 + j * 8;
            const float b0 = bias[col], b1 = bias[col + 1];
            #pragma unroll
            for (int half = 0; half < 2; half++) {
                const int row = rb0 + i * 16 + half * 8;
                float v0 = acc[i][j][half * 2 + 0] + b0;
                float v1 = acc[i][j][half * 2 + 1] + b1;
                if (MODE == 1) { v0 = fmaxf(v0, 0.f); v1 = fmaxf(v1, 0.f); }
                float* op;
                if (MODE == 2) {
                    int h = col >> 6, d = col & 63;
                    int b = row >> 11, s = row & 2047;
                    op = out + ((((size_t)b * NH + h) * NS + s) * NDK + d);
                } else {
                    op = out + (size_t)row * Nt + col;
                }
                float2 r2; r2.x = v0; r2.y = v1;
                *(float2*)op = r2;
            }
        }
    }
}

// ---------------- fused attention: scores + decay + causal softmax + ctx ---
#define ATTN_SMEM ((8*2048 + 128*64 + 8*64) * 4)

__global__ void __launch_bounds__(256)
attn_kernel(float* __restrict__ attw)
{
    extern __shared__ float sm[];
    float* sc  = sm;                 // 16384 floats
    float* kvf = sm + 8 * 2048;      // 8192 floats, swizzled
    float* qs  = kvf + 128 * 64;     // 512 floats

    const int t = threadIdx.x, lane = t & 31, r = t >> 5;
    const int bh = blockIdx.y;
    const int hh = bh & 15, bb = bh >> 4;
    const int qi0 = blockIdx.x << 3;
    const int qi  = qi0 + r;

    const float* qb = g_q + (size_t)bh * NS * NDK;
    const float* kb = g_k + (size_t)bh * NS * NDK;
    const float* vb = g_v + (size_t)bh * NS * NDK;
    const float g21 = g_g21[hh];

    if (t < 128) {
        int rr = t >> 4, d4 = (t & 15) << 2;
        *(float4*)&qs[(rr << 6) + d4] =
            *(const float4*)(qb + (size_t)(qi0 + rr) * NDK + d4);
    }
    __syncthreads();

    const int nch = (qi0 >> 7) + 1;

    for (int ch = 0; ch < nch; ++ch) {
        int c0 = ch << 7;
        #pragma unroll
        for (int i = 0; i < 8; i++) {
            int f4 = t + (i << 8);
            int c = f4 >> 4, gd = f4 & 15;
            float4 val = *(const float4*)(kb + (size_t)(c0 + c) * NDK + (gd << 2));
            *(float4*)&kvf[(c << 6) + ((gd ^ (c & 15)) << 2)] = val;
        }
        __syncthreads();

        float acc[4] = {0.f, 0.f, 0.f, 0.f};
        const int sw = lane & 15;
        #pragma unroll
        for (int gd = 0; gd < 16; ++gd) {
            float4 qv = *(const float4*)&qs[(r << 6) + (gd << 2)];
            int g2 = (gd ^ sw) << 2;
            #pragma unroll
            for (int j = 0; j < 4; j++) {
                float4 kv = *(const float4*)&kvf[((lane + (j << 5)) << 6) + g2];
                acc[j] += qv.x*kv.x + qv.y*kv.y + qv.z*kv.z + qv.w*kv.w;
            }
        }
        #pragma unroll
        for (int j = 0; j < 4; j++) {
            int c = c0 + lane + (j << 5);
            float s;
            if (c <= qi) {
                float eff = fminf(__expf((float)(qi - c) * g21), 1e5f);
                s = acc[j] * 0.125f * eff;
            } else {
                s = -3.0e38f;
            }
            sc[(r << 11) + c] = s;
        }
        __syncthreads();
    }

    float mx = -3.0e38f;
    for (int c = lane; c <= qi; c += 32) mx = fmaxf(mx, sc[(r << 11) + c]);
    #pragma unroll
    for (int o = 16; o; o >>= 1) mx = fmaxf(mx, __shfl_xor_sync(0xffffffffu, mx, o));

    float sum = 0.f;
    for (int c = lane; c <= qi; c += 32) {
        float e = __expf(sc[(r << 11) + c] - mx);
        sc[(r << 11) + c] = e;
        sum += e;
    }
    #pragma unroll
    for (int o = 16; o; o >>= 1) sum += __shfl_xor_sync(0xffffffffu, sum, o);
    float inv = 1.0f / sum;

    float* arow_g = attw + ((size_t)bh * NS + qi) * NS;
    for (int c = lane; c < NS; c += 32) {
        float w = (c <= qi) ? sc[(r << 11) + c] * inv : 0.f;
        sc[(r << 11) + c] = w;
        arow_g[c] = w;
    }
    __syncthreads();

    float ax = 0.f, ay = 0.f;
    const int gd3 = lane >> 1, half = (lane & 1) << 1;
    for (int ch = 0; ch < nch; ++ch) {
        int c0 = ch << 7;
        #pragma unroll
        for (int i = 0; i < 8; i++) {
            int f4 = t + (i << 8);
            int c = f4 >> 4, gd = f4 & 15;
            float4 val = *(const float4*)(vb + (size_t)(c0 + c) * NDK + (gd << 2));
            *(float4*)&kvf[(c << 6) + ((gd ^ (c & 15)) << 2)] = val;
        }
        __syncthreads();
        #pragma unroll 4
        for (int c = 0; c < 128; c++) {
            float w = sc[(r << 11) + c0 + c];
            float2 vv = *(const float2*)&kvf[(c << 6) + ((gd3 ^ (c & 15)) << 2) + half];
            ax = fmaf(w, vv.x, ax);
            ay = fmaf(w, vv.y, ay);
        }
        __syncthreads();
    }
    float2 res; res.x = ax; res.y = ay;
    *(float2*)&g_concat[((size_t)bb * NS + qi) * ND + hh * NDK + (lane << 1)] = res;
}

// ---------------- residual + layernorm -------------------------------------
__global__ void __launch_bounds__(256)
ln_kernel(const float* __restrict__ xa, const float* __restrict__ xb,
          const float* __restrict__ sg, const float* __restrict__ bg,
          float* __restrict__ out)
{
    __shared__ float red[16];
    const int row = blockIdx.x, t = threadIdx.x;
    const int lane = t & 31, wid = t >> 5;
    const size_t base = (size_t)row * ND;

    float v[4];
    #pragma unroll
    for (int i = 0; i < 4; i++) {
        int idx = t + (i << 8);
        v[i] = xa[base + idx] + xb[base + idx];
    }
    float s = v[0] + v[1] + v[2] + v[3];
    #pragma unroll
    for (int o = 16; o; o >>= 1) s += __shfl_xor_sync(0xffffffffu, s, o);
    if (lane == 0) red[wid] = s;
    __syncthreads();
    if (t == 0) {
        float tot = 0.f;
        for (int i = 0; i < 8; i++) tot += red[i];
        red[8] = tot;
    }
    __syncthreads();
    const float mean = red[8] * (1.0f / ND);

    float q = 0.f;
    #pragma unroll
    for (int i = 0; i < 4; i++) { float d = v[i] - mean; q += d * d; }
    #pragma unroll
    for (int o = 16; o; o >>= 1) q += __shfl_xor_sync(0xffffffffu, q, o);
    if (lane == 0) red[wid] = q;
    __syncthreads();
    if (t == 0) {
        float tot = 0.f;
        for (int i = 0; i < 8; i++) tot += red[i];
        red[9] = tot;
    }
    __syncthreads();
    const float rs = rsqrtf(red[9] * (1.0f / ND) + LN_EPS);

    #pragma unroll
    for (int i = 0; i < 4; i++) {
        int idx = t + (i << 8);
        out[base + idx] = (v[i] - mean) * rs * sg[idx] + bg[idx];
    }
}

// ---------------- launcher --------------------------------------------------
extern "C" void kernel_launch(void* const* d_in, const int* in_sizes, int n_in,
                              void* d_out, int out_size)
{
    const float* query  = (const float*)d_in[0];
    const float* key    = (const float*)d_in[1];
    const float* values = (const float*)d_in[2];
    const float* Wk     = (const float*)d_in[3];
    const float* bk     = (const float*)d_in[4];
    const float* Wv     = (const float*)d_in[5];
    const float* bv     = (const float*)d_in[6];
    const float* Wout   = (const float*)d_in[7];
    const float* bout   = (const float*)d_in[8];
    const float* gammas = (const float*)d_in[9];
    const float* ln1_s  = (const float*)d_in[10];
    const float* ln1_b  = (const float*)d_in[11];
    const float* W1     = (const float*)d_in[12];
    const float* b1     = (const float*)d_in[13];
    const float* W2     = (const float*)d_in[14];
    const float* b2     = (const float*)d_in[15];
    const float* ln2_s  = (const float*)d_in[16];
    const float* ln2_b  = (const float*)d_in[17];

    float* out  = (float*)d_out;                       // x: [B,S,D]
    float* attw = out + (size_t)NM * ND;               // att_weight: [B,H,S,S]

    float *pq, *pk, *pv, *pcat, *ptmp, *px1, *pffn;
    __nv_bfloat16 *pah, *pal, *pwh, *pwl;
    cudaGetSymbolAddress((void**)&pq,   g_q);
    cudaGetSymbolAddress((void**)&pk,   g_k);
    cudaGetSymbolAddress((void**)&pv,   g_v);
    cudaGetSymbolAddress((void**)&pcat, g_concat);
    cudaGetSymbolAddress((void**)&ptmp, g_tmp);
    cudaGetSymbolAddress((void**)&px1,  g_x1);
    cudaGetSymbolAddress((void**)&pffn, g_ffn);
    cudaGetSymbolAddress((void**)&pah,  g_ah);
    cudaGetSymbolAddress((void**)&pal,  g_al);
    cudaGetSymbolAddress((void**)&pwh,  g_wh);
    cudaGetSymbolAddress((void**)&pwl,  g_wl);

    cudaFuncSetAttribute(attn_kernel,
                         cudaFuncAttributeMaxDynamicSharedMemorySize, ATTN_SMEM);
    cudaFuncSetAttribute(mma_gemm<0>,
                         cudaFuncAttributeMaxDynamicSharedMemorySize, GSMEM);
    cudaFuncSetAttribute(mma_gemm<1>,
                         cudaFuncAttributeMaxDynamicSharedMemorySize, GSMEM);
    cudaFuncSetAttribute(mma_gemm<2>,
                         cudaFuncAttributeMaxDynamicSharedMemorySize, GSMEM);

    prep_kernel<<<1, 32>>>(gammas);

    const int CONV_A = (int)(((size_t)NM * ND) / 2048);     // 4096 blocks
    const int CONV_F = (int)(((size_t)NM * NDF) / 2048);    // 16384 blocks

    // ---- Q/K projections in fp32 (precision-critical: amplified by decay) --
    gemm_f32<2><<<dim3(8, 64), 256>>>(query, Wk, bk, pq, ND, ND);
    gemm_f32<2><<<dim3(8, 64), 256>>>(key,   Wk, bk, pk, ND, ND);

    // ---- V projection via split-bf16 HMMA ----
    wt_convert<<<dim3(32, 32), 256>>>(Wv, pwh, pwl, ND, ND);
    a_convert<<<CONV_A, 256>>>(values, pah, pal);
    mma_gemm<2><<<dim3(8, 64), 256, GSMEM>>>(pah, pal, pwh, pwl, bv, pv, ND, ND);

    attn_kernel<<<dim3(NS / 8, NB * NH), 256, ATTN_SMEM>>>(attw);

    // ---- Wout + LN1 ----
    wt_convert<<<dim3(32, 32), 256>>>(Wout, pwh, pwl, ND, ND);
    a_convert<<<CONV_A, 256>>>(pcat, pah, pal);
    mma_gemm<0><<<dim3(8, 64), 256, GSMEM>>>(pah, pal, pwh, pwl, bout, ptmp, ND, ND);
    ln_kernel<<<NM, 256>>>(query, ptmp, ln1_s, ln1_b, px1);

    // ---- FFN ----
    wt_convert<<<dim3(128, 32), 256>>>(W1, pwh, pwl, ND, NDF);
    a_convert<<<CONV_A, 256>>>(px1, pah, pal);
    mma_gemm<1><<<dim3(32, 64), 256, GSMEM>>>(pah, pal, pwh, pwl, b1, pffn, ND, NDF);
    wt_convert<<<dim3(32, 128), 256>>>(W2, pwh, pwl, NDF, ND);
    a_convert<<<CONV_F, 256>>>(pffn, pah, pal);
    mma_gemm<0><<<dim3(8, 64), 256, GSMEM>>>(pah, pal, pwh, pwl, b2, ptmp, NDF, ND);
    ln_kernel<<<NM, 256>>>(px1, ptmp, ln2_s, ln2_b, out);
}

// round 7
// speedup vs baseline: 1.3743x; 1.0010x over previous
#include <cuda_runtime.h>
#include <cuda_bf16.h>
#include <math.h>
#include <stdint.h>

#define NB 4
#define NS 2048
#define ND 1024
#define NH 16
#define NDK 64
#define NDF 4096
#define NM (NB*NS)          // 8192 rows
#define LN_EPS 1e-5f

// ---------------- scratch (static device globals; no allocation allowed) ----
static __device__ float g_q[(size_t)NM*ND];       // [B,H,S,DK]
static __device__ float g_k[(size_t)NM*ND];
static __device__ float g_v[(size_t)NM*ND];
static __device__ float g_concat[(size_t)NM*ND];  // [B,S,D] attention context
static __device__ float g_tmp[(size_t)NM*ND];     // attn_out, later FFN2 out
static __device__ float g_x1[(size_t)NM*ND];      // after LN1
static __device__ float g_ffn[(size_t)NM*NDF];    // FFN hidden
static __device__ float g_g21[NH];                // softplus(gamma)/21
// bf16 split planes
static __device__ __nv_bfloat16 g_ah[(size_t)NM*NDF];   // A hi plane
static __device__ __nv_bfloat16 g_al[(size_t)NM*NDF];   // A lo plane
static __device__ __nv_bfloat16 g_wh[(size_t)NDF*ND];   // W^T hi plane
static __device__ __nv_bfloat16 g_wl[(size_t)NDF*ND];   // W^T lo plane

// =================== PTX helpers (compute_103-safe) =========================
__device__ __forceinline__ uint32_t smem_u32(const void* p) {
    uint32_t a;
    asm("{ .reg .u64 t; cvta.to.shared.u64 t, %1; cvt.u32.u64 %0, t; }"
        : "=r"(a) : "l"(p));
    return a;
}
#define CP_ASYNC16(dst, src) \
    asm volatile("cp.async.cg.shared.global [%0], [%1], 16;" \
                 :: "r"(dst), "l"(src) : "memory")
#define CP_COMMIT() asm volatile("cp.async.commit_group;" ::: "memory")
#define CP_WAIT0()  asm volatile("cp.async.wait_group 0;" ::: "memory")
#define CP_WAIT1()  asm volatile("cp.async.wait_group 1;" ::: "memory")

__device__ __forceinline__ void ldsm4(uint32_t& r0, uint32_t& r1,
                                      uint32_t& r2, uint32_t& r3, uint32_t a) {
    asm volatile("ldmatrix.sync.aligned.m8n8.x4.shared.b16 {%0,%1,%2,%3}, [%4];"
                 : "=r"(r0), "=r"(r1), "=r"(r2), "=r"(r3) : "r"(a));
}
__device__ __forceinline__ void mma16816(float* c, const uint32_t* a,
                                         const uint32_t* b) {
    asm volatile("mma.sync.aligned.m16n8k16.row.col.f32.bf16.bf16.f32 "
                 "{%0,%1,%2,%3}, {%4,%5,%6,%7}, {%8,%9}, {%0,%1,%2,%3};"
                 : "+f"(c[0]), "+f"(c[1]), "+f"(c[2]), "+f"(c[3])
                 : "r"(a[0]), "r"(a[1]), "r"(a[2]), "r"(a[3]),
                   "r"(b[0]), "r"(b[1]));
}

// ---------------- prep: softplus(gammas)/21 --------------------------------
__global__ void prep_kernel(const float* __restrict__ gammas) {
    int h = threadIdx.x;
    if (h < NH) {
        float x = gammas[h];
        float sp = (x > 0.f) ? (x + log1pf(expf(-x))) : log1pf(expf(x));
        g_g21[h] = sp * (1.0f / 21.0f);
    }
}

// ---------------- fp32 FFMA GEMM (precision path for Q/K) ------------------
// out = A[M,K] @ W[K,N] + bias.  MODE 2: scatter to [B,H,S,DK] head-major
template<int MODE>
__global__ void __launch_bounds__(256)
gemm_f32(const float* __restrict__ A, const float* __restrict__ W,
         const float* __restrict__ bias, float* __restrict__ out,
         int K, int N)
{
    __shared__ float As[2][16][132];
    __shared__ float Bs[2][16][132];

    const int t  = threadIdx.x;
    const int bm = blockIdx.y, bn = blockIdx.x;

    const int arow = t >> 2, acol = (t & 3) << 2;
    const int brow = t >> 5, bcol = (t & 31) << 2;

    const float* Ab = A + (size_t)(bm * 128) * K;
    const float* Wb = W + bn * 128;

    float4 a0, a1, b0, b1;
    a0 = *(const float4*)(Ab + (size_t)arow * K + acol);
    a1 = *(const float4*)(Ab + (size_t)(arow + 64) * K + acol);
    b0 = *(const float4*)(Wb + (size_t)brow * N + bcol);
    b1 = *(const float4*)(Wb + (size_t)(brow + 8) * N + bcol);
    As[0][acol+0][arow] = a0.x; As[0][acol+1][arow] = a0.y;
    As[0][acol+2][arow] = a0.z; As[0][acol+3][arow] = a0.w;
    As[0][acol+0][arow+64] = a1.x; As[0][acol+1][arow+64] = a1.y;
    As[0][acol+2][arow+64] = a1.z; As[0][acol+3][arow+64] = a1.w;
    *(float4*)&Bs[0][brow][bcol]   = b0;
    *(float4*)&Bs[0][brow+8][bcol] = b1;
    __syncthreads();

    const int ty = t >> 4, tx = t & 15;
    float acc[8][8];
    #pragma unroll
    for (int i = 0; i < 8; i++)
        #pragma unroll
        for (int j = 0; j < 8; j++) acc[i][j] = 0.f;

    const int KT = K >> 4;
    int buf = 0;
    for (int kt = 0; kt < KT; ++kt) {
        if (kt + 1 < KT) {
            int k0 = (kt + 1) << 4;
            a0 = *(const float4*)(Ab + (size_t)arow * K + k0 + acol);
            a1 = *(const float4*)(Ab + (size_t)(arow + 64) * K + k0 + acol);
            b0 = *(const float4*)(Wb + (size_t)(k0 + brow) * N + bcol);
            b1 = *(const float4*)(Wb + (size_t)(k0 + brow + 8) * N + bcol);
        }
        #pragma unroll
        for (int k = 0; k < 16; k++) {
            float4 xa = *(const float4*)&As[buf][k][ty*8];
            float4 xb = *(const float4*)&As[buf][k][ty*8+4];
            float4 ya = *(const float4*)&Bs[buf][k][tx*8];
            float4 yb = *(const float4*)&Bs[buf][k][tx*8+4];
            float ar[8] = {xa.x,xa.y,xa.z,xa.w,xb.x,xb.y,xb.z,xb.w};
            float br[8] = {ya.x,ya.y,ya.z,ya.w,yb.x,yb.y,yb.z,yb.w};
            #pragma unroll
            for (int i = 0; i < 8; i++)
                #pragma unroll
                for (int j = 0; j < 8; j++)
                    acc[i][j] = fmaf(ar[i], br[j], acc[i][j]);
        }
        if (kt + 1 < KT) {
            int nb = buf ^ 1;
            As[nb][acol+0][arow] = a0.x; As[nb][acol+1][arow] = a0.y;
            As[nb][acol+2][arow] = a0.z; As[nb][acol+3][arow] = a0.w;
            As[nb][acol+0][arow+64] = a1.x; As[nb][acol+1][arow+64] = a1.y;
            As[nb][acol+2][arow+64] = a1.z; As[nb][acol+3][arow+64] = a1.w;
            *(float4*)&Bs[nb][brow][bcol]   = b0;
            *(float4*)&Bs[nb][brow+8][bcol] = b1;
        }
        __syncthreads();
        buf ^= 1;
    }

    const int gc0 = bn * 128 + tx * 8;
    #pragma unroll
    for (int i = 0; i < 8; i++) {
        int gr = bm * 128 + ty * 8 + i;
        if (MODE == 2) {
            int h = gc0 >> 6, d = gc0 & 63;
            int b = gr >> 11, s = gr & 2047;
            float* op = out + ((((size_t)b * NH + h) * NS + s) * NDK + d);
            #pragma unroll
            for (int j = 0; j < 8; j++) op[j] = acc[i][j] + bias[gc0 + j];
        } else {
            float* op = out + (size_t)gr * N + gc0;
            #pragma unroll
            for (int j = 0; j < 8; j++) op[j] = acc[i][j] + bias[gc0 + j];
        }
    }
}

// ---------------- fp32 -> bf16 hi/lo plane conversion ----------------------
__global__ void __launch_bounds__(256)
a_convert(const float* __restrict__ x, __nv_bfloat16* __restrict__ ph,
          __nv_bfloat16* __restrict__ pl)
{
    size_t i = ((size_t)blockIdx.x * 256 + threadIdx.x) * 8;
    float4 v0 = *(const float4*)(x + i);
    float4 v1 = *(const float4*)(x + i + 4);
    float vv[8] = {v0.x, v0.y, v0.z, v0.w, v1.x, v1.y, v1.z, v1.w};
    __align__(16) __nv_bfloat16 hh[8], ll[8];
    #pragma unroll
    for (int j = 0; j < 8; j++) {
        __nv_bfloat16 h = __float2bfloat16(vv[j]);
        hh[j] = h;
        ll[j] = __float2bfloat16(vv[j] - __bfloat162float(h));
    }
    *(uint4*)(ph + i) = *(uint4*)hh;
    *(uint4*)(pl + i) = *(uint4*)ll;
}

// ---------------- W[K,N] fp32 -> W^T[N,K] bf16 hi/lo -----------------------
__global__ void __launch_bounds__(256)
wt_convert(const float* __restrict__ W, __nv_bfloat16* __restrict__ th,
           __nv_bfloat16* __restrict__ tl, int K, int N)
{
    __shared__ float tile[32][33];
    int n0 = blockIdx.x * 32, k0 = blockIdx.y * 32;
    int tx = threadIdx.x & 31, ty = threadIdx.x >> 5;
    #pragma unroll
    for (int i = 0; i < 4; i++)
        tile[ty + i * 8][tx] = W[(size_t)(k0 + ty + i * 8) * N + n0 + tx];
    __syncthreads();
    #pragma unroll
    for (int i = 0; i < 4; i++) {
        float v = tile[tx][ty + i * 8];           // = W[k0+tx][n0+ty+i*8]
        size_t o = (size_t)(n0 + ty + i * 8) * K + k0 + tx;
        __nv_bfloat16 h = __float2bfloat16(v);
        th[o] = h;
        tl[o] = __float2bfloat16(v - __bfloat162float(h));
    }
}

// ---------------- split-bf16 HMMA GEMM --------------------------------------
// out[M,Nt] = A[M,K] @ W[K,Nt] + bias via Ahi*Bhi + Ahi*Blo + Alo*Bhi.
// CTA tile 128x128, K-chunk 32. 8 warps (4x2), warp tile 32x64.
#define PLANE_B 10240                       // 128 * 80
#define STAGE_B (4 * PLANE_B)               // Ahi|Alo|Bhi|Blo = 40 KB
#define GSMEM   (2 * STAGE_B)               // 80 KB

template<int MODE>   // 0 plain, 1 relu, 2 scatter to [B,H,S,DK]
__global__ void __launch_bounds__(256, 1)
mma_gemm(const __nv_bfloat16* __restrict__ ah, const __nv_bfloat16* __restrict__ al,
         const __nv_bfloat16* __restrict__ bh, const __nv_bfloat16* __restrict__ bl,
         const float* __restrict__ bias, float* __restrict__ out, int K, int Nt)
{
    extern __shared__ char dsm[];
    const uint32_t sb = smem_u32(dsm);

    const int t = threadIdx.x, wid = t >> 5, lane = t & 31;
    const int warp_m = wid & 3, warp_n = wid >> 2;
    const int m0 = blockIdx.y * 128, n0 = blockIdx.x * 128;

    const __nv_bfloat16* srcs[4] = {
        ah + (size_t)m0 * K, al + (size_t)m0 * K,
        bh + (size_t)n0 * K, bl + (size_t)n0 * K };

    uint32_t dsts[8];
    uint32_t rowK[8], segO[8];
    #pragma unroll
    for (int u = 0; u < 8; u++) {
        int g = t + (u << 8);
        int plane = g >> 9, rem = g & 511;
        int row = rem >> 2, seg = rem & 3;
        dsts[u] = plane * PLANE_B + row * 80 + seg * 16;
        rowK[u] = row; segO[u] = seg << 3;
    }

    const int a_row = warp_m * 32 + (lane & 15);
    const uint32_t a_col = (lane >> 4) * 16;
    const int b_row = warp_n * 64 + ((lane >> 4) << 3) + (lane & 7);
    const uint32_t b_col = ((lane >> 3) & 1) * 16;

    float acc[2][8][4];
    #pragma unroll
    for (int i = 0; i < 2; i++)
        #pragma unroll
        for (int j = 0; j < 8; j++)
            #pragma unroll
            for (int q = 0; q < 4; q++) acc[i][j][q] = 0.f;

    const int KT = K >> 5;
    int buf = 0;

    #pragma unroll
    for (int u = 0; u < 8; u++) {
        int plane = (t + (u << 8)) >> 9;
        const __nv_bfloat16* src = srcs[plane] + (size_t)rowK[u] * K + segO[u];
        CP_ASYNC16(sb + dsts[u], src);
    }
    CP_COMMIT();

    for (int kt = 0; kt < KT; ++kt) {
        if (kt + 1 < KT) {
            const int k0 = (kt + 1) << 5;
            const uint32_t base = sb + (buf ^ 1) * STAGE_B;
            #pragma unroll
            for (int u = 0; u < 8; u++) {
                int plane = (t + (u << 8)) >> 9;
                const __nv_bfloat16* src = srcs[plane] + (size_t)rowK[u] * K + k0 + segO[u];
                CP_ASYNC16(base + dsts[u], src);
            }
            CP_COMMIT();
            CP_WAIT1();
        } else {
            CP_WAIT0();
        }
        __syncthreads();

        const uint32_t st = sb + buf * STAGE_B;
        #pragma unroll
        for (int ks = 0; ks < 2; ++ks) {
            const uint32_t kb = ks * 32;
            uint32_t ahf[2][4], alf[2][4];
            #pragma unroll
            for (int i = 0; i < 2; i++) {
                uint32_t ra = st + (a_row + i * 16) * 80 + kb + a_col;
                ldsm4(ahf[i][0], ahf[i][1], ahf[i][2], ahf[i][3], ra);
                ldsm4(alf[i][0], alf[i][1], alf[i][2], alf[i][3], ra + PLANE_B);
            }
            uint32_t bhf[8][2], blf[8][2];
            #pragma unroll
            for (int jj = 0; jj < 4; jj++) {
                uint32_t rb = st + 2 * PLANE_B + (b_row + jj * 16) * 80 + kb + b_col;
                ldsm4(bhf[2*jj][0], bhf[2*jj][1], bhf[2*jj+1][0], bhf[2*jj+1][1], rb);
                ldsm4(blf[2*jj][0], blf[2*jj][1], blf[2*jj+1][0], blf[2*jj+1][1],
                      rb + PLANE_B);
            }
            #pragma unroll
            for (int i = 0; i < 2; i++)
                #pragma unroll
                for (int j = 0; j < 8; j++) {
                    mma16816(acc[i][j], ahf[i], bhf[j]);
                    mma16816(acc[i][j], ahf[i], blf[j]);
                    mma16816(acc[i][j], alf[i], bhf[j]);
                }
        }
        __syncthreads();
        buf ^= 1;
    }

    const int rb0 = m0 + warp_m * 32 + (lane >> 2);
    const int cb0 = n0 + warp_n * 64 + (lane & 3) * 2;
    #pragma unroll
    for (int i = 0; i < 2; i++) {
        #pragma unroll
        for (int j = 0; j < 8; j++) {
            const int col = cb0 + j * 8;
            const float b0 = bias[col], b1 = bias[col + 1];
            #pragma unroll
            for (int half = 0; half < 2; half++) {
                const int row = rb0 + i * 16 + half * 8;
                float v0 = acc[i][j][half * 2 + 0] + b0;
                float v1 = acc[i][j][half * 2 + 1] + b1;
                if (MODE == 1) { v0 = fmaxf(v0, 0.f); v1 = fmaxf(v1, 0.f); }
                float* op;
                if (MODE == 2) {
                    int h = col >> 6, d = col & 63;
                    int b = row >> 11, s = row & 2047;
                    op = out + ((((size_t)b * NH + h) * NS + s) * NDK + d);
                } else {
                    op = out + (size_t)row * Nt + col;
                }
                float2 r2; r2.x = v0; r2.y = v1;
                *(float2*)op = r2;
            }
        }
    }
}

// ---------------- fused attention: scores + decay + causal softmax + ctx ---
#define ATTN_SMEM ((8*2048 + 128*64 + 8*64) * 4)

__global__ void __launch_bounds__(256)
attn_kernel(float* __restrict__ attw)
{
    extern __shared__ float sm[];
    float* sc  = sm;                 // 16384 floats
    float* kvf = sm + 8 * 2048;      // 8192 floats, swizzled
    float* qs  = kvf + 128 * 64;     // 512 floats

    const int t = threadIdx.x, lane = t & 31, r = t >> 5;
    const int bh = blockIdx.y;
    const int hh = bh & 15, bb = bh >> 4;
    const int qi0 = blockIdx.x << 3;
    const int qi  = qi0 + r;

    const float* qb = g_q + (size_t)bh * NS * NDK;
    const float* kb = g_k + (size_t)bh * NS * NDK;
    const float* vb = g_v + (size_t)bh * NS * NDK;
    const float g21 = g_g21[hh];

    if (t < 128) {
        int rr = t >> 4, d4 = (t & 15) << 2;
        *(float4*)&qs[(rr << 6) + d4] =
            *(const float4*)(qb + (size_t)(qi0 + rr) * NDK + d4);
    }
    __syncthreads();

    const int nch = (qi0 >> 7) + 1;

    for (int ch = 0; ch < nch; ++ch) {
        int c0 = ch << 7;
        #pragma unroll
        for (int i = 0; i < 8; i++) {
            int f4 = t + (i << 8);
            int c = f4 >> 4, gd = f4 & 15;
            float4 val = *(const float4*)(kb + (size_t)(c0 + c) * NDK + (gd << 2));
            *(float4*)&kvf[(c << 6) + ((gd ^ (c & 15)) << 2)] = val;
        }
        __syncthreads();

        float acc[4] = {0.f, 0.f, 0.f, 0.f};
        const int sw = lane & 15;
        #pragma unroll
        for (int gd = 0; gd < 16; ++gd) {
            float4 qv = *(const float4*)&qs[(r << 6) + (gd << 2)];
            int g2 = (gd ^ sw) << 2;
            #pragma unroll
            for (int j = 0; j < 4; j++) {
                float4 kv = *(const float4*)&kvf[((lane + (j << 5)) << 6) + g2];
                acc[j] += qv.x*kv.x + qv.y*kv.y + qv.z*kv.z + qv.w*kv.w;
            }
        }
        #pragma unroll
        for (int j = 0; j < 4; j++) {
            int c = c0 + lane + (j << 5);
            float s;
            if (c <= qi) {
                float eff = fminf(__expf((float)(qi - c) * g21), 1e5f);
                s = acc[j] * 0.125f * eff;
            } else {
                s = -3.0e38f;
            }
            sc[(r << 11) + c] = s;
        }
        __syncthreads();
    }

    float mx = -3.0e38f;
    for (int c = lane; c <= qi; c += 32) mx = fmaxf(mx, sc[(r << 11) + c]);
    #pragma unroll
    for (int o = 16; o; o >>= 1) mx = fmaxf(mx, __shfl_xor_sync(0xffffffffu, mx, o));

    float sum = 0.f;
    for (int c = lane; c <= qi; c += 32) {
        float e = __expf(sc[(r << 11) + c] - mx);
        sc[(r << 11) + c] = e;
        sum += e;
    }
    #pragma unroll
    for (int o = 16; o; o >>= 1) sum += __shfl_xor_sync(0xffffffffu, sum, o);
    float inv = 1.0f / sum;

    float* arow_g = attw + ((size_t)bh * NS + qi) * NS;
    for (int c = lane; c < NS; c += 32) {
        float w = (c <= qi) ? sc[(r << 11) + c] * inv : 0.f;
        sc[(r << 11) + c] = w;
        arow_g[c] = w;
    }
    __syncthreads();

    float ax = 0.f, ay = 0.f;
    const int gd3 = lane >> 1, half = (lane & 1) << 1;
    for (int ch = 0; ch < nch; ++ch) {
        int c0 = ch << 7;
        #pragma unroll
        for (int i = 0; i < 8; i++) {
            int f4 = t + (i << 8);
            int c = f4 >> 4, gd = f4 & 15;
            float4 val = *(const float4*)(vb + (size_t)(c0 + c) * NDK + (gd << 2));
            *(float4*)&kvf[(c << 6) + ((gd ^ (c & 15)) << 2)] = val;
        }
        __syncthreads();
        #pragma unroll 4
        for (int c = 0; c < 128; c++) {
            float w = sc[(r << 11) + c0 + c];
            float2 vv = *(const float2*)&kvf[(c << 6) + ((gd3 ^ (c & 15)) << 2) + half];
            ax = fmaf(w, vv.x, ax);
            ay = fmaf(w, vv.y, ay);
        }
        __syncthreads();
    }
    float2 res; res.x = ax; res.y = ay;
    *(float2*)&g_concat[((size_t)bb * NS + qi) * ND + hh * NDK + (lane << 1)] = res;
}

// ---------------- residual + layernorm -------------------------------------
__global__ void __launch_bounds__(256)
ln_kernel(const float* __restrict__ xa, const float* __restrict__ xb,
          const float* __restrict__ sg, const float* __restrict__ bg,
          float* __restrict__ out)
{
    __shared__ float red[16];
    const int row = blockIdx.x, t = threadIdx.x;
    const int lane = t & 31, wid = t >> 5;
    const size_t base = (size_t)row * ND;

    float v[4];
    #pragma unroll
    for (int i = 0; i < 4; i++) {
        int idx = t + (i << 8);
        v[i] = xa[base + idx] + xb[base + idx];
    }
    float s = v[0] + v[1] + v[2] + v[3];
    #pragma unroll
    for (int o = 16; o; o >>= 1) s += __shfl_xor_sync(0xffffffffu, s, o);
    if (lane == 0) red[wid] = s;
    __syncthreads();
    if (t == 0) {
        float tot = 0.f;
        for (int i = 0; i < 8; i++) tot += red[i];
        red[8] = tot;
    }
    __syncthreads();
    const float mean = red[8] * (1.0f / ND);

    float q = 0.f;
    #pragma unroll
    for (int i = 0; i < 4; i++) { float d = v[i] - mean; q += d * d; }
    #pragma unroll
    for (int o = 16; o; o >>= 1) q += __shfl_xor_sync(0xffffffffu, q, o);
    if (lane == 0) red[wid] = q;
    __syncthreads();
    if (t == 0) {
        float tot = 0.f;
        for (int i = 0; i < 8; i++) tot += red[i];
        red[9] = tot;
    }
    __syncthreads();
    const float rs = rsqrtf(red[9] * (1.0f / ND) + LN_EPS);

    #pragma unroll
    for (int i = 0; i < 4; i++) {
        int idx = t + (i << 8);
        out[base + idx] = (v[i] - mean) * rs * sg[idx] + bg[idx];
    }
}

// ---------------- launcher --------------------------------------------------
extern "C" void kernel_launch(void* const* d_in, const int* in_sizes, int n_in,
                              void* d_out, int out_size)
{
    const float* query  = (const float*)d_in[0];
    const float* key    = (const float*)d_in[1];
    const float* values = (const float*)d_in[2];
    const float* Wk     = (const float*)d_in[3];
    const float* bk     = (const float*)d_in[4];
    const float* Wv     = (const float*)d_in[5];
    const float* bv     = (const float*)d_in[6];
    const float* Wout   = (const float*)d_in[7];
    const float* bout   = (const float*)d_in[8];
    const float* gammas = (const float*)d_in[9];
    const float* ln1_s  = (const float*)d_in[10];
    const float* ln1_b  = (const float*)d_in[11];
    const float* W1     = (const float*)d_in[12];
    const float* b1     = (const float*)d_in[13];
    const float* W2     = (const float*)d_in[14];
    const float* b2     = (const float*)d_in[15];
    const float* ln2_s  = (const float*)d_in[16];
    const float* ln2_b  = (const float*)d_in[17];

    float* out  = (float*)d_out;                       // x: [B,S,D]
    float* attw = out + (size_t)NM * ND;               // att_weight: [B,H,S,S]

    float *pq, *pk, *pv, *pcat, *ptmp, *px1, *pffn;
    __nv_bfloat16 *pah, *pal, *pwh, *pwl;
    cudaGetSymbolAddress((void**)&pq,   g_q);
    cudaGetSymbolAddress((void**)&pk,   g_k);
    cudaGetSymbolAddress((void**)&pv,   g_v);
    cudaGetSymbolAddress((void**)&pcat, g_concat);
    cudaGetSymbolAddress((void**)&ptmp, g_tmp);
    cudaGetSymbolAddress((void**)&px1,  g_x1);
    cudaGetSymbolAddress((void**)&pffn, g_ffn);
    cudaGetSymbolAddress((void**)&pah,  g_ah);
    cudaGetSymbolAddress((void**)&pal,  g_al);
    cudaGetSymbolAddress((void**)&pwh,  g_wh);
    cudaGetSymbolAddress((void**)&pwl,  g_wl);

    cudaFuncSetAttribute(attn_kernel,
                         cudaFuncAttributeMaxDynamicSharedMemorySize, ATTN_SMEM);
    cudaFuncSetAttribute(mma_gemm<0>,
                         cudaFuncAttributeMaxDynamicSharedMemorySize, GSMEM);
    cudaFuncSetAttribute(mma_gemm<1>,
                         cudaFuncAttributeMaxDynamicSharedMemorySize, GSMEM);
    cudaFuncSetAttribute(mma_gemm<2>,
                         cudaFuncAttributeMaxDynamicSharedMemorySize, GSMEM);

    prep_kernel<<<1, 32>>>(gammas);

    const int CONV_A = (int)(((size_t)NM * ND) / 2048);     // 4096 blocks
    const int CONV_F = (int)(((size_t)NM * NDF) / 2048);    // 16384 blocks

    // ---- Q/K projections in fp32 (precision-critical: amplified by decay) --
    gemm_f32<2><<<dim3(8, 64), 256>>>(query, Wk, bk, pq, ND, ND);
    gemm_f32<2><<<dim3(8, 64), 256>>>(key,   Wk, bk, pk, ND, ND);

    // ---- V projection via split-bf16 HMMA ----
    wt_convert<<<dim3(32, 32), 256>>>(Wv, pwh, pwl, ND, ND);
    a_convert<<<CONV_A, 256>>>(values, pah, pal);
    mma_gemm<2><<<dim3(8, 64), 256, GSMEM>>>(pah, pal, pwh, pwl, bv, pv, ND, ND);

    attn_kernel<<<dim3(NS / 8, NB * NH), 256, ATTN_SMEM>>>(attw);

    // ---- Wout + LN1 ----
    wt_convert<<<dim3(32, 32), 256>>>(Wout, pwh, pwl, ND, ND);
    a_convert<<<CONV_A, 256>>>(pcat, pah, pal);
    mma_gemm<0><<<dim3(8, 64), 256, GSMEM>>>(pah, pal, pwh, pwl, bout, ptmp, ND, ND);
    ln_kernel<<<NM, 256>>>(query, ptmp, ln1_s, ln1_b, px1);

    // ---- FFN ----
    wt_convert<<<dim3(128, 32), 256>>>(W1, pwh, pwl, ND, NDF);
    a_convert<<<CONV_A, 256>>>(px1, pah, pal);
    mma_gemm<1><<<dim3(32, 64), 256, GSMEM>>>(pah, pal, pwh, pwl, b1, pffn, ND, NDF);
    wt_convert<<<dim3(32, 128), 256>>>(W2, pwh, pwl, NDF, ND);
    a_convert<<<CONV_F, 256>>>(pffn, pah, pal);
    mma_gemm<0><<<dim3(8, 64), 256, GSMEM>>>(pah, pal, pwh, pwl, b2, ptmp, NDF, ND);
    ln_kernel<<<NM, 256>>>(px1, ptmp, ln2_s, ln2_b, out);
}

// round 8
// speedup vs baseline: 1.9053x; 1.3863x over previous
#include <cuda_runtime.h>
#include <cuda_bf16.h>
#include <math.h>
#include <stdint.h>

#define NB 4
#define NS 2048
#define ND 1024
#define NH 16
#define NDK 64
#define NDF 4096
#define NM (NB*NS)
#define LN_EPS 1e-5f

static __device__ float g_q[(size_t)NM*ND];
static __device__ float g_k[(size_t)NM*ND];
static __device__ float g_v[(size_t)NM*ND];
static __device__ float g_concat[(size_t)NM*ND];
static __device__ float g_tmp[(size_t)NM*ND];
static __device__ float g_x1[(size_t)NM*ND];
static __device__ float g_ffn[(size_t)NM*NDF];
static __device__ float g_decay[NH*NS];           // clip(exp(d*softplus(g)/21),1e5)
static __device__ __nv_bfloat16 g_ah[(size_t)NM*NDF];
static __device__ __nv_bfloat16 g_al[(size_t)NM*NDF];
static __device__ __nv_bfloat16 g_wh[(size_t)NDF*ND];
static __device__ __nv_bfloat16 g_wl[(size_t)NDF*ND];

__device__ __forceinline__ uint32_t smem_u32(const void* p) {
    uint32_t a;
    asm("{ .reg .u64 t; cvta.to.shared.u64 t, %1; cvt.u32.u64 %0, t; }"
        : "=r"(a) : "l"(p));
    return a;
}
#define CP_ASYNC16(dst, src) \
    asm volatile("cp.async.cg.shared.global [%0], [%1], 16;" \
                 :: "r"(dst), "l"(src) : "memory")
#define CP_COMMIT() asm volatile("cp.async.commit_group;" ::: "memory")
#define CP_WAIT0()  asm volatile("cp.async.wait_group 0;" ::: "memory")
#define CP_WAIT1()  asm volatile("cp.async.wait_group 1;" ::: "memory")

__device__ __forceinline__ void ldsm4(uint32_t& r0, uint32_t& r1,
                                      uint32_t& r2, uint32_t& r3, uint32_t a) {
    asm volatile("ldmatrix.sync.aligned.m8n8.x4.shared.b16 {%0,%1,%2,%3}, [%4];"
                 : "=r"(r0), "=r"(r1), "=r"(r2), "=r"(r3) : "r"(a));
}
__device__ __forceinline__ void mma16816(float* c, const uint32_t* a,
                                         const uint32_t* b) {
    asm volatile("mma.sync.aligned.m16n8k16.row.col.f32.bf16.bf16.f32 "
                 "{%0,%1,%2,%3}, {%4,%5,%6,%7}, {%8,%9}, {%0,%1,%2,%3};"
                 : "+f"(c[0]), "+f"(c[1]), "+f"(c[2]), "+f"(c[3])
                 : "r"(a[0]), "r"(a[1]), "r"(a[2]), "r"(a[3]),
                   "r"(b[0]), "r"(b[1]));
}

// ---------------- decay table ----------------------------------------------
__global__ void prep_decay(const float* __restrict__ gammas) {
    int h = blockIdx.x;
    float x = gammas[h];
    float sp = (x > 0.f) ? (x + log1pf(expf(-x))) : log1pf(expf(x));
    float g21 = sp * (1.0f / 21.0f);
    for (int i = threadIdx.x; i < NS; i += blockDim.x)
        g_decay[h * NS + i] = fminf(__expf((float)i * g21), 1e5f);
}

// ---------------- fp32 FFMA GEMM (Q/K precision path) ----------------------
template<int MODE>
__global__ void __launch_bounds__(256)
gemm_f32(const float* __restrict__ A, const float* __restrict__ W,
         const float* __restrict__ bias, float* __restrict__ out,
         int K, int N)
{
    __shared__ float As[2][16][132];
    __shared__ float Bs[2][16][132];
    const int t  = threadIdx.x;
    const int bm = blockIdx.y, bn = blockIdx.x;
    const int arow = t >> 2, acol = (t & 3) << 2;
    const int brow = t >> 5, bcol = (t & 31) << 2;
    const float* Ab = A + (size_t)(bm * 128) * K;
    const float* Wb = W + bn * 128;

    float4 a0, a1, b0, b1;
    a0 = *(const float4*)(Ab + (size_t)arow * K + acol);
    a1 = *(const float4*)(Ab + (size_t)(arow + 64) * K + acol);
    b0 = *(const float4*)(Wb + (size_t)brow * N + bcol);
    b1 = *(const float4*)(Wb + (size_t)(brow + 8) * N + bcol);
    As[0][acol+0][arow] = a0.x; As[0][acol+1][arow] = a0.y;
    As[0][acol+2][arow] = a0.z; As[0][acol+3][arow] = a0.w;
    As[0][acol+0][arow+64] = a1.x; As[0][acol+1][arow+64] = a1.y;
    As[0][acol+2][arow+64] = a1.z; As[0][acol+3][arow+64] = a1.w;
    *(float4*)&Bs[0][brow][bcol]   = b0;
    *(float4*)&Bs[0][brow+8][bcol] = b1;
    __syncthreads();

    const int ty = t >> 4, tx = t & 15;
    float acc[8][8];
    #pragma unroll
    for (int i = 0; i < 8; i++)
        #pragma unroll
        for (int j = 0; j < 8; j++) acc[i][j] = 0.f;

    const int KT = K >> 4;
    int buf = 0;
    for (int kt = 0; kt < KT; ++kt) {
        if (kt + 1 < KT) {
            int k0 = (kt + 1) << 4;
            a0 = *(const float4*)(Ab + (size_t)arow * K + k0 + acol);
            a1 = *(const float4*)(Ab + (size_t)(arow + 64) * K + k0 + acol);
            b0 = *(const float4*)(Wb + (size_t)(k0 + brow) * N + bcol);
            b1 = *(const float4*)(Wb + (size_t)(k0 + brow + 8) * N + bcol);
        }
        #pragma unroll
        for (int k = 0; k < 16; k++) {
            float4 xa = *(const float4*)&As[buf][k][ty*8];
            float4 xb = *(const float4*)&As[buf][k][ty*8+4];
            float4 ya = *(const float4*)&Bs[buf][k][tx*8];
            float4 yb = *(const float4*)&Bs[buf][k][tx*8+4];
            float ar[8] = {xa.x,xa.y,xa.z,xa.w,xb.x,xb.y,xb.z,xb.w};
            float br[8] = {ya.x,ya.y,ya.z,ya.w,yb.x,yb.y,yb.z,yb.w};
            #pragma unroll
            for (int i = 0; i < 8; i++)
                #pragma unroll
                for (int j = 0; j < 8; j++)
                    acc[i][j] = fmaf(ar[i], br[j], acc[i][j]);
        }
        if (kt + 1 < KT) {
            int nb = buf ^ 1;
            As[nb][acol+0][arow] = a0.x; As[nb][acol+1][arow] = a0.y;
            As[nb][acol+2][arow] = a0.z; As[nb][acol+3][arow] = a0.w;
            As[nb][acol+0][arow+64] = a1.x; As[nb][acol+1][arow+64] = a1.y;
            As[nb][acol+2][arow+64] = a1.z; As[nb][acol+3][arow+64] = a1.w;
            *(float4*)&Bs[nb][brow][bcol]   = b0;
            *(float4*)&Bs[nb][brow+8][bcol] = b1;
        }
        __syncthreads();
        buf ^= 1;
    }

    const int gc0 = bn * 128 + tx * 8;
    #pragma unroll
    for (int i = 0; i < 8; i++) {
        int gr = bm * 128 + ty * 8 + i;
        if (MODE == 2) {
            int h = gc0 >> 6, d = gc0 & 63;
            int b = gr >> 11, s = gr & 2047;
            float* op = out + ((((size_t)b * NH + h) * NS + s) * NDK + d);
            #pragma unroll
            for (int j = 0; j < 8; j++) op[j] = acc[i][j] + bias[gc0 + j];
        } else {
            float* op = out + (size_t)gr * N + gc0;
            #pragma unroll
            for (int j = 0; j < 8; j++) op[j] = acc[i][j] + bias[gc0 + j];
        }
    }
}

// ---------------- fp32 -> bf16 hi/lo planes --------------------------------
__global__ void __launch_bounds__(256)
a_convert(const float* __restrict__ x, __nv_bfloat16* __restrict__ ph,
          __nv_bfloat16* __restrict__ pl)
{
    size_t i = ((size_t)blockIdx.x * 256 + threadIdx.x) * 8;
    float4 v0 = *(const float4*)(x + i);
    float4 v1 = *(const float4*)(x + i + 4);
    float vv[8] = {v0.x, v0.y, v0.z, v0.w, v1.x, v1.y, v1.z, v1.w};
    __align__(16) __nv_bfloat16 hh[8], ll[8];
    #pragma unroll
    for (int j = 0; j < 8; j++) {
        __nv_bfloat16 h = __float2bfloat16(vv[j]);
        hh[j] = h;
        ll[j] = __float2bfloat16(vv[j] - __bfloat162float(h));
    }
    *(uint4*)(ph + i) = *(uint4*)hh;
    *(uint4*)(pl + i) = *(uint4*)ll;
}

__global__ void __launch_bounds__(256)
wt_convert(const float* __restrict__ W, __nv_bfloat16* __restrict__ th,
           __nv_bfloat16* __restrict__ tl, int K, int N)
{
    __shared__ float tile[32][33];
    int n0 = blockIdx.x * 32, k0 = blockIdx.y * 32;
    int tx = threadIdx.x & 31, ty = threadIdx.x >> 5;
    #pragma unroll
    for (int i = 0; i < 4; i++)
        tile[ty + i * 8][tx] = W[(size_t)(k0 + ty + i * 8) * N + n0 + tx];
    __syncthreads();
    #pragma unroll
    for (int i = 0; i < 4; i++) {
        float v = tile[tx][ty + i * 8];
        size_t o = (size_t)(n0 + ty + i * 8) * K + k0 + tx;
        __nv_bfloat16 h = __float2bfloat16(v);
        th[o] = h;
        tl[o] = __float2bfloat16(v - __bfloat162float(h));
    }
}

// ---------------- split-bf16 HMMA GEMM -------------------------------------
#define PLANE_B 10240
#define STAGE_B (4 * PLANE_B)
#define GSMEM   (2 * STAGE_B)

template<int MODE>
__global__ void __launch_bounds__(256, 1)
mma_gemm(const __nv_bfloat16* __restrict__ ah, const __nv_bfloat16* __restrict__ al,
         const __nv_bfloat16* __restrict__ bh, const __nv_bfloat16* __restrict__ bl,
         const float* __restrict__ bias, float* __restrict__ out, int K, int Nt)
{
    extern __shared__ char dsm[];
    const uint32_t sb = smem_u32(dsm);
    const int t = threadIdx.x, wid = t >> 5, lane = t & 31;
    const int warp_m = wid & 3, warp_n = wid >> 2;
    const int m0 = blockIdx.y * 128, n0 = blockIdx.x * 128;

    const __nv_bfloat16* srcs[4] = {
        ah + (size_t)m0 * K, al + (size_t)m0 * K,
        bh + (size_t)n0 * K, bl + (size_t)n0 * K };

    uint32_t dsts[8], rowK[8], segO[8];
    #pragma unroll
    for (int u = 0; u < 8; u++) {
        int g = t + (u << 8);
        int plane = g >> 9, rem = g & 511;
        int row = rem >> 2, seg = rem & 3;
        dsts[u] = plane * PLANE_B + row * 80 + seg * 16;
        rowK[u] = row; segO[u] = seg << 3;
    }

    const int a_row = warp_m * 32 + (lane & 15);
    const uint32_t a_col = (lane >> 4) * 16;
    const int b_row = warp_n * 64 + ((lane >> 4) << 3) + (lane & 7);
    const uint32_t b_col = ((lane >> 3) & 1) * 16;

    float acc[2][8][4];
    #pragma unroll
    for (int i = 0; i < 2; i++)
        #pragma unroll
        for (int j = 0; j < 8; j++)
            #pragma unroll
            for (int q = 0; q < 4; q++) acc[i][j][q] = 0.f;

    const int KT = K >> 5;
    int buf = 0;
    #pragma unroll
    for (int u = 0; u < 8; u++) {
        int plane = (t + (u << 8)) >> 9;
        CP_ASYNC16(sb + dsts[u], srcs[plane] + (size_t)rowK[u] * K + segO[u]);
    }
    CP_COMMIT();

    for (int kt = 0; kt < KT; ++kt) {
        if (kt + 1 < KT) {
            const int k0 = (kt + 1) << 5;
            const uint32_t base = sb + (buf ^ 1) * STAGE_B;
            #pragma unroll
            for (int u = 0; u < 8; u++) {
                int plane = (t + (u << 8)) >> 9;
                CP_ASYNC16(base + dsts[u],
                           srcs[plane] + (size_t)rowK[u] * K + k0 + segO[u]);
            }
            CP_COMMIT();
            CP_WAIT1();
        } else {
            CP_WAIT0();
        }
        __syncthreads();

        const uint32_t st = sb + buf * STAGE_B;
        #pragma unroll
        for (int ks = 0; ks < 2; ++ks) {
            const uint32_t kb = ks * 32;
            uint32_t ahf[2][4], alf[2][4];
            #pragma unroll
            for (int i = 0; i < 2; i++) {
                uint32_t ra = st + (a_row + i * 16) * 80 + kb + a_col;
                ldsm4(ahf[i][0], ahf[i][1], ahf[i][2], ahf[i][3], ra);
                ldsm4(alf[i][0], alf[i][1], alf[i][2], alf[i][3], ra + PLANE_B);
            }
            uint32_t bhf[8][2], blf[8][2];
            #pragma unroll
            for (int jj = 0; jj < 4; jj++) {
                uint32_t rb = st + 2 * PLANE_B + (b_row + jj * 16) * 80 + kb + b_col;
                ldsm4(bhf[2*jj][0], bhf[2*jj][1], bhf[2*jj+1][0], bhf[2*jj+1][1], rb);
                ldsm4(blf[2*jj][0], blf[2*jj][1], blf[2*jj+1][0], blf[2*jj+1][1],
                      rb + PLANE_B);
            }
            #pragma unroll
            for (int i = 0; i < 2; i++)
                #pragma unroll
                for (int j = 0; j < 8; j++) {
                    mma16816(acc[i][j], ahf[i], bhf[j]);
                    mma16816(acc[i][j], ahf[i], blf[j]);
                    mma16816(acc[i][j], alf[i], bhf[j]);
                }
        }
        __syncthreads();
        buf ^= 1;
    }

    const int rb0 = m0 + warp_m * 32 + (lane >> 2);
    const int cb0 = n0 + warp_n * 64 + (lane & 3) * 2;
    #pragma unroll
    for (int i = 0; i < 2; i++) {
        #pragma unroll
        for (int j = 0; j < 8; j++) {
            const int col = cb0 + j * 8;
            const float b0 = bias[col], b1 = bias[col + 1];
            #pragma unroll
            for (int half = 0; half < 2; half++) {
                const int row = rb0 + i * 16 + half * 8;
                float v0 = acc[i][j][half * 2 + 0] + b0;
                float v1 = acc[i][j][half * 2 + 1] + b1;
                if (MODE == 1) { v0 = fmaxf(v0, 0.f); v1 = fmaxf(v1, 0.f); }
                float* op;
                if (MODE == 2) {
                    int h = col >> 6, d = col & 63;
                    int b = row >> 11, s = row & 2047;
                    op = out + ((((size_t)b * NH + h) * NS + s) * NDK + d);
                } else {
                    op = out + (size_t)row * Nt + col;
                }
                float2 r2; r2.x = v0; r2.y = v1;
                *(float2*)op = r2;
            }
        }
    }
}

// ---------------- flash attention: 32 rows/CTA, 4 rows/warp ----------------
#define AF_SMEM (25600 * 4)   // 100 KB

__device__ __forceinline__ void stage_kv(uint32_t dst, const float* __restrict__ src,
                                         int c0, int t) {
    #pragma unroll
    for (int i = 0; i < 8; i++) {
        int idx = t + (i << 8);
        int c = idx >> 4, gd = idx & 15;
        CP_ASYNC16(dst + (c << 8) + ((gd ^ (c & 15)) << 4),
                   src + (size_t)(c0 + c) * NDK + (gd << 2));
    }
}

__global__ void __launch_bounds__(256, 2)
attn_flash(float* __restrict__ attw)
{
    extern __shared__ float sm[];
    float* dtab = sm;            // 2048
    float* qs   = sm + 2048;     // 2048 (32 x 64)
    float* ksm  = sm + 4096;     // 8192
    float* vsm  = sm + 12288;    // 8192
    float* ws   = sm + 20480;    // 4096: per warp 512 = [c][r]
    float* mch  = sm + 24576;    // 512: 32 rows x 16 chunks
    float* fs   = sm + 25088;    // 512: per warp 64 = [r][ch]

    const int t = threadIdx.x, lane = t & 31, w = t >> 5;
    const int bh = blockIdx.y, hh = bh & 15, bb = bh >> 4;
    const int qi0 = blockIdx.x << 5;

    const float* qb = g_q + (size_t)bh * NS * NDK;
    const float* kb = g_k + (size_t)bh * NS * NDK;
    const float* vb = g_v + (size_t)bh * NS * NDK;
    const uint32_t ku = smem_u32(ksm), vu = smem_u32(vsm);
    const int nch = (qi0 >> 7) + 1;

    stage_kv(ku, kb, 0, t);
    stage_kv(vu, vb, 0, t);
    CP_COMMIT();

    {
        const float* dt = g_decay + hh * NS;
        *(float4*)&dtab[t * 8]     = *(const float4*)(dt + t * 8);
        *(float4*)&dtab[t * 8 + 4] = *(const float4*)(dt + t * 8 + 4);
        const float* qsrc = qb + (size_t)qi0 * NDK;
        *(float4*)&qs[t * 8]       = *(const float4*)(qsrc + t * 8);
        *(float4*)&qs[t * 8 + 4]   = *(const float4*)(qsrc + t * 8 + 4);
    }

    float m[4], Z[4], ax[4], ay[4];
    #pragma unroll
    for (int r = 0; r < 4; r++) { m[r] = -3.0e38f; Z[r] = 0.f; ax[r] = 0.f; ay[r] = 0.f; }

    const int gd3 = lane >> 1, half = (lane & 1) << 1;
    const int sw = lane & 15;
    float* wsw = ws + w * 512;

    for (int ch = 0; ch < nch; ++ch) {
        const int c0 = ch << 7;
        CP_WAIT0();
        __syncthreads();

        float acc[4][4];
        #pragma unroll
        for (int r = 0; r < 4; r++)
            #pragma unroll
            for (int j = 0; j < 4; j++) acc[r][j] = 0.f;

        #pragma unroll
        for (int gd = 0; gd < 16; ++gd) {
            float4 qv[4];
            #pragma unroll
            for (int r = 0; r < 4; r++)
                qv[r] = *(const float4*)&qs[((w * 4 + r) << 6) + (gd << 2)];
            const int g2 = (gd ^ sw) << 2;
            #pragma unroll
            for (int j = 0; j < 4; j++) {
                float4 kv = *(const float4*)&ksm[((lane + (j << 5)) << 6) + g2];
                #pragma unroll
                for (int r = 0; r < 4; r++)
                    acc[r][j] += qv[r].x*kv.x + qv[r].y*kv.y + qv[r].z*kv.z + qv[r].w*kv.w;
            }
        }

        #pragma unroll
        for (int r = 0; r < 4; r++) {
            const int qi = qi0 + w * 4 + r;
            float s[4];
            #pragma unroll
            for (int j = 0; j < 4; j++) {
                int c = c0 + lane + (j << 5);
                s[j] = (c <= qi) ? acc[r][j] * 0.125f * dtab[qi - c] : -3.0e38f;
            }
            float cm = fmaxf(fmaxf(s[0], s[1]), fmaxf(s[2], s[3]));
            #pragma unroll
            for (int o = 16; o; o >>= 1)
                cm = fmaxf(cm, __shfl_xor_sync(0xffffffffu, cm, o));
            const float mnew = fmaxf(m[r], cm);
            const float scale = __expf(m[r] - mnew);
            float e[4], zs = 0.f;
            #pragma unroll
            for (int j = 0; j < 4; j++) {
                int c = c0 + lane + (j << 5);
                e[j] = (c <= qi) ? __expf(s[j] - mnew) : 0.f;
                zs += e[j];
            }
            #pragma unroll
            for (int o = 16; o; o >>= 1)
                zs += __shfl_xor_sync(0xffffffffu, zs, o);
            Z[r] = Z[r] * scale + zs;
            ax[r] *= scale; ay[r] *= scale;
            m[r] = mnew;
            if (lane == 0) mch[(w * 4 + r) * 16 + ch] = mnew;
            float* arow = attw + ((size_t)bh * NS + qi) * NS + c0;
            #pragma unroll
            for (int j = 0; j < 4; j++) {
                wsw[((lane + (j << 5)) << 2) + r] = e[j];
                arow[lane + (j << 5)] = e[j];
            }
        }
        __syncwarp();

        #pragma unroll 2
        for (int c = 0; c < 128; ++c) {
            float4 wv = *(const float4*)&wsw[c << 2];
            float2 vv = *(const float2*)&vsm[(c << 6) + ((gd3 ^ (c & 15)) << 2) + half];
            ax[0] += wv.x * vv.x; ay[0] += wv.x * vv.y;
            ax[1] += wv.y * vv.x; ay[1] += wv.y * vv.y;
            ax[2] += wv.z * vv.x; ay[2] += wv.z * vv.y;
            ax[3] += wv.w * vv.x; ay[3] += wv.w * vv.y;
        }
        __syncthreads();
        if (ch + 1 < nch) {
            stage_kv(ku, kb, c0 + 128, t);
            stage_kv(vu, vb, c0 + 128, t);
            CP_COMMIT();
        }
    }

    // ctx out + per-chunk rescale factors
    #pragma unroll
    for (int r = 0; r < 4; r++) {
        const int qi = qi0 + w * 4 + r;
        const float iz = 1.0f / Z[r];
        float2 res; res.x = ax[r] * iz; res.y = ay[r] * iz;
        *(float2*)&g_concat[((size_t)bb * NS + qi) * ND + hh * NDK + (lane << 1)] = res;
    }
    #pragma unroll
    for (int u = 0; u < 2; u++) {
        int idx = lane + u * 32;             // 0..63 -> r2 = idx>>4, ch = idx&15
        int r2 = idx >> 4, ch = idx & 15;
        fs[w * 64 + idx] = __expf(mch[(w * 4 + r2) * 16 + ch] - m[r2]) / Z[r2];
    }
    __syncwarp();

    // in-place rescale of this block's attw rows: w = e * exp(m_ch - M) / Z
    #pragma unroll
    for (int r = 0; r < 4; r++) {
        const int qi = qi0 + w * 4 + r;
        float* arow = attw + ((size_t)bh * NS + qi) * NS;
        #pragma unroll 4
        for (int it = 0; it < 16; it++) {
            int c = it * 128 + lane * 4;
            float f = fs[w * 64 + r * 16 + it];
            float4 v = *(float4*)(arow + c);
            v.x = (c + 0 <= qi) ? v.x * f : 0.f;
            v.y = (c + 1 <= qi) ? v.y * f : 0.f;
            v.z = (c + 2 <= qi) ? v.z * f : 0.f;
            v.w = (c + 3 <= qi) ? v.w * f : 0.f;
            *(float4*)(arow + c) = v;
        }
    }
}

// ---------------- residual + layernorm -------------------------------------
__global__ void __launch_bounds__(256)
ln_kernel(const float* __restrict__ xa, const float* __restrict__ xb,
          const float* __restrict__ sg, const float* __restrict__ bg,
          float* __restrict__ out)
{
    __shared__ float red[16];
    const int row = blockIdx.x, t = threadIdx.x;
    const int lane = t & 31, wid = t >> 5;
    const size_t base = (size_t)row * ND;

    float v[4];
    #pragma unroll
    for (int i = 0; i < 4; i++) {
        int idx = t + (i << 8);
        v[i] = xa[base + idx] + xb[base + idx];
    }
    float s = v[0] + v[1] + v[2] + v[3];
    #pragma unroll
    for (int o = 16; o; o >>= 1) s += __shfl_xor_sync(0xffffffffu, s, o);
    if (lane == 0) red[wid] = s;
    __syncthreads();
    if (t == 0) {
        float tot = 0.f;
        for (int i = 0; i < 8; i++) tot += red[i];
        red[8] = tot;
    }
    __syncthreads();
    const float mean = red[8] * (1.0f / ND);

    float q = 0.f;
    #pragma unroll
    for (int i = 0; i < 4; i++) { float d = v[i] - mean; q += d * d; }
    #pragma unroll
    for (int o = 16; o; o >>= 1) q += __shfl_xor_sync(0xffffffffu, q, o);
    if (lane == 0) red[wid] = q;
    __syncthreads();
    if (t == 0) {
        float tot = 0.f;
        for (int i = 0; i < 8; i++) tot += red[i];
        red[9] = tot;
    }
    __syncthreads();
    const float rs = rsqrtf(red[9] * (1.0f / ND) + LN_EPS);

    #pragma unroll
    for (int i = 0; i < 4; i++) {
        int idx = t + (i << 8);
        out[base + idx] = (v[i] - mean) * rs * sg[idx] + bg[idx];
    }
}

// ---------------- launcher --------------------------------------------------
extern "C" void kernel_launch(void* const* d_in, const int* in_sizes, int n_in,
                              void* d_out, int out_size)
{
    const float* query  = (const float*)d_in[0];
    const float* key    = (const float*)d_in[1];
    const float* values = (const float*)d_in[2];
    const float* Wk     = (const float*)d_in[3];
    const float* bk     = (const float*)d_in[4];
    const float* Wv     = (const float*)d_in[5];
    const float* bv     = (const float*)d_in[6];
    const float* Wout   = (const float*)d_in[7];
    const float* bout   = (const float*)d_in[8];
    const float* gammas = (const float*)d_in[9];
    const float* ln1_s  = (const float*)d_in[10];
    const float* ln1_b  = (const float*)d_in[11];
    const float* W1     = (const float*)d_in[12];
    const float* b1     = (const float*)d_in[13];
    const float* W2     = (const float*)d_in[14];
    const float* b2     = (const float*)d_in[15];
    const float* ln2_s  = (const float*)d_in[16];
    const float* ln2_b  = (const float*)d_in[17];

    float* out  = (float*)d_out;
    float* attw = out + (size_t)NM * ND;

    float *pq, *pk, *pv, *pcat, *ptmp, *px1, *pffn;
    __nv_bfloat16 *pah, *pal, *pwh, *pwl;
    cudaGetSymbolAddress((void**)&pq,   g_q);
    cudaGetSymbolAddress((void**)&pk,   g_k);
    cudaGetSymbolAddress((void**)&pv,   g_v);
    cudaGetSymbolAddress((void**)&pcat, g_concat);
    cudaGetSymbolAddress((void**)&ptmp, g_tmp);
    cudaGetSymbolAddress((void**)&px1,  g_x1);
    cudaGetSymbolAddress((void**)&pffn, g_ffn);
    cudaGetSymbolAddress((void**)&pah,  g_ah);
    cudaGetSymbolAddress((void**)&pal,  g_al);
    cudaGetSymbolAddress((void**)&pwh,  g_wh);
    cudaGetSymbolAddress((void**)&pwl,  g_wl);

    cudaFuncSetAttribute(attn_flash,
                         cudaFuncAttributeMaxDynamicSharedMemorySize, AF_SMEM);
    cudaFuncSetAttribute(mma_gemm<0>,
                         cudaFuncAttributeMaxDynamicSharedMemorySize, GSMEM);
    cudaFuncSetAttribute(mma_gemm<1>,
                         cudaFuncAttributeMaxDynamicSharedMemorySize, GSMEM);
    cudaFuncSetAttribute(mma_gemm<2>,
                         cudaFuncAttributeMaxDynamicSharedMemorySize, GSMEM);

    prep_decay<<<NH, 256>>>(gammas);

    const int CONV_A = (int)(((size_t)NM * ND) / 2048);
    const int CONV_F = (int)(((size_t)NM * NDF) / 2048);

    // Q/K in fp32 (precision-critical), V via split-bf16 HMMA
    gemm_f32<2><<<dim3(8, 64), 256>>>(query, Wk, bk, pq, ND, ND);
    gemm_f32<2><<<dim3(8, 64), 256>>>(key,   Wk, bk, pk, ND, ND);
    wt_convert<<<dim3(32, 32), 256>>>(Wv, pwh, pwl, ND, ND);
    a_convert<<<CONV_A, 256>>>(values, pah, pal);
    mma_gemm<2><<<dim3(8, 64), 256, GSMEM>>>(pah, pal, pwh, pwl, bv, pv, ND, ND);

    attn_flash<<<dim3(NS / 32, NB * NH), 256, AF_SMEM>>>(attw);

    wt_convert<<<dim3(32, 32), 256>>>(Wout, pwh, pwl, ND, ND);
    a_convert<<<CONV_A, 256>>>(pcat, pah, pal);
    mma_gemm<0><<<dim3(8, 64), 256, GSMEM>>>(pah, pal, pwh, pwl, bout, ptmp, ND, ND);
    ln_kernel<<<NM, 256>>>(query, ptmp, ln1_s, ln1_b, px1);

    wt_convert<<<dim3(128, 32), 256>>>(W1, pwh, pwl, ND, NDF);
    a_convert<<<CONV_A, 256>>>(px1, pah, pal);
    mma_gemm<1><<<dim3(32, 64), 256, GSMEM>>>(pah, pal, pwh, pwl, b1, pffn, ND, NDF);
    wt_convert<<<dim3(32, 128), 256>>>(W2, pwh, pwl, NDF, ND);
    a_convert<<<CONV_F, 256>>>(pffn, pah, pal);
    mma_gemm<0><<<dim3(8, 64), 256, GSMEM>>>(pah, pal, pwh, pwl, b2, ptmp, NDF, ND);
    ln_kernel<<<NM, 256>>>(px1, ptmp, ln2_s, ln2_b, out);
}

// round 12
// speedup vs baseline: 2.0719x; 1.0875x over previous
#include <cuda_runtime.h>
#include <cuda_bf16.h>
#include <math.h>
#include <stdint.h>

#define NB 4
#define NS 2048
#define ND 1024
#define NH 16
#define NDK 64
#define NDF 4096
#define NM (NB*NS)
#define LN_EPS 1e-5f

static __device__ float g_q[(size_t)NM*ND];
static __device__ float g_k[(size_t)NM*ND];
static __device__ float g_v[(size_t)NM*ND];
static __device__ float g_concat[(size_t)NM*ND];
static __device__ float g_tmp[(size_t)NM*ND];
static __device__ float g_x1[(size_t)NM*ND];
static __device__ float g_decay[NH*NS];
static __device__ __nv_bfloat16 g_ah[(size_t)NM*ND];    // A hi plane (1024-wide)
static __device__ __nv_bfloat16 g_al[(size_t)NM*ND];    // A lo plane
static __device__ __nv_bfloat16 g_fh[(size_t)NM*NDF];   // FFN hidden hi plane
static __device__ __nv_bfloat16 g_fl[(size_t)NM*NDF];   // FFN hidden lo plane
static __device__ __nv_bfloat16 g_wh[(size_t)NDF*ND];   // W^T hi plane
static __device__ __nv_bfloat16 g_wl[(size_t)NDF*ND];   // W^T lo plane

__device__ __forceinline__ uint32_t smem_u32(const void* p) {
    uint32_t a;
    asm("{ .reg .u64 t; cvta.to.shared.u64 t, %1; cvt.u32.u64 %0, t; }"
        : "=r"(a) : "l"(p));
    return a;
}
#define CP_ASYNC16(dst, src) \
    asm volatile("cp.async.cg.shared.global [%0], [%1], 16;" \
                 :: "r"(dst), "l"(src) : "memory")
#define CP_COMMIT() asm volatile("cp.async.commit_group;" ::: "memory")
#define CP_WAIT0()  asm volatile("cp.async.wait_group 0;" ::: "memory")
#define CP_WAIT1()  asm volatile("cp.async.wait_group 1;" ::: "memory")

__device__ __forceinline__ void ldsm4(uint32_t& r0, uint32_t& r1,
                                      uint32_t& r2, uint32_t& r3, uint32_t a) {
    asm volatile("ldmatrix.sync.aligned.m8n8.x4.shared.b16 {%0,%1,%2,%3}, [%4];"
                 : "=r"(r0), "=r"(r1), "=r"(r2), "=r"(r3) : "r"(a));
}
__device__ __forceinline__ void mma16816(float* c, const uint32_t* a,
                                         const uint32_t* b) {
    asm volatile("mma.sync.aligned.m16n8k16.row.col.f32.bf16.bf16.f32 "
                 "{%0,%1,%2,%3}, {%4,%5,%6,%7}, {%8,%9}, {%0,%1,%2,%3};"
                 : "+f"(c[0]), "+f"(c[1]), "+f"(c[2]), "+f"(c[3])
                 : "r"(a[0]), "r"(a[1]), "r"(a[2]), "r"(a[3]),
                   "r"(b[0]), "r"(b[1]));
}

// ---------------- decay table ----------------------------------------------
__global__ void prep_decay(const float* __restrict__ gammas) {
    int h = blockIdx.x;
    float x = gammas[h];
    float sp = (x > 0.f) ? (x + log1pf(expf(-x))) : log1pf(expf(x));
    float g21 = sp * (1.0f / 21.0f);
    for (int i = threadIdx.x; i < NS; i += blockDim.x)
        g_decay[h * NS + i] = fminf(__expf((float)i * g21), 1e5f);
}

// ---------------- fp32 FFMA GEMM for Q+K (one launch, z selects) ----------
__global__ void __launch_bounds__(256)
gemm_f32qk(const float* __restrict__ A0, const float* __restrict__ A1,
           const float* __restrict__ W, const float* __restrict__ bias,
           float* __restrict__ out0, float* __restrict__ out1)
{
    const int K = ND, N = ND;
    __shared__ float As[2][16][132];
    __shared__ float Bs[2][16][132];
    const int t  = threadIdx.x;
    const int bm = blockIdx.y, bn = blockIdx.x;
    const float* A  = blockIdx.z ? A1 : A0;
    float* out      = blockIdx.z ? out1 : out0;
    const int arow = t >> 2, acol = (t & 3) << 2;
    const int brow = t >> 5, bcol = (t & 31) << 2;
    const float* Ab = A + (size_t)(bm * 128) * K;
    const float* Wb = W + bn * 128;

    float4 a0, a1, b0, b1;
    a0 = *(const float4*)(Ab + (size_t)arow * K + acol);
    a1 = *(const float4*)(Ab + (size_t)(arow + 64) * K + acol);
    b0 = *(const float4*)(Wb + (size_t)brow * N + bcol);
    b1 = *(const float4*)(Wb + (size_t)(brow + 8) * N + bcol);
    As[0][acol+0][arow] = a0.x; As[0][acol+1][arow] = a0.y;
    As[0][acol+2][arow] = a0.z; As[0][acol+3][arow] = a0.w;
    As[0][acol+0][arow+64] = a1.x; As[0][acol+1][arow+64] = a1.y;
    As[0][acol+2][arow+64] = a1.z; As[0][acol+3][arow+64] = a1.w;
    *(float4*)&Bs[0][brow][bcol]   = b0;
    *(float4*)&Bs[0][brow+8][bcol] = b1;
    __syncthreads();

    const int ty = t >> 4, tx = t & 15;
    float acc[8][8];
    #pragma unroll
    for (int i = 0; i < 8; i++)
        #pragma unroll
        for (int j = 0; j < 8; j++) acc[i][j] = 0.f;

    const int KT = K >> 4;
    int buf = 0;
    for (int kt = 0; kt < KT; ++kt) {
        if (kt + 1 < KT) {
            int k0 = (kt + 1) << 4;
            a0 = *(const float4*)(Ab + (size_t)arow * K + k0 + acol);
            a1 = *(const float4*)(Ab + (size_t)(arow + 64) * K + k0 + acol);
            b0 = *(const float4*)(Wb + (size_t)(k0 + brow) * N + bcol);
            b1 = *(const float4*)(Wb + (size_t)(k0 + brow + 8) * N + bcol);
        }
        #pragma unroll
        for (int k = 0; k < 16; k++) {
            float4 xa = *(const float4*)&As[buf][k][ty*8];
            float4 xb = *(const float4*)&As[buf][k][ty*8+4];
            float4 ya = *(const float4*)&Bs[buf][k][tx*8];
            float4 yb = *(const float4*)&Bs[buf][k][tx*8+4];
            float ar[8] = {xa.x,xa.y,xa.z,xa.w,xb.x,xb.y,xb.z,xb.w};
            float br[8] = {ya.x,ya.y,ya.z,ya.w,yb.x,yb.y,yb.z,yb.w};
            #pragma unroll
            for (int i = 0; i < 8; i++)
                #pragma unroll
                for (int j = 0; j < 8; j++)
                    acc[i][j] = fmaf(ar[i], br[j], acc[i][j]);
        }
        if (kt + 1 < KT) {
            int nb = buf ^ 1;
            As[nb][acol+0][arow] = a0.x; As[nb][acol+1][arow] = a0.y;
            As[nb][acol+2][arow] = a0.z; As[nb][acol+3][arow] = a0.w;
            As[nb][acol+0][arow+64] = a1.x; As[nb][acol+1][arow+64] = a1.y;
            As[nb][acol+2][arow+64] = a1.z; As[nb][acol+3][arow+64] = a1.w;
            *(float4*)&Bs[nb][brow][bcol]   = b0;
            *(float4*)&Bs[nb][brow+8][bcol] = b1;
        }
        __syncthreads();
        buf ^= 1;
    }

    const int gc0 = bn * 128 + tx * 8;
    #pragma unroll
    for (int i = 0; i < 8; i++) {
        int gr = bm * 128 + ty * 8 + i;
        int h = gc0 >> 6, d = gc0 & 63;
        int b = gr >> 11, s = gr & 2047;
        float* op = out + ((((size_t)b * NH + h) * NS + s) * NDK + d);
        #pragma unroll
        for (int j = 0; j < 8; j++) op[j] = acc[i][j] + bias[gc0 + j];
    }
}

// ---------------- fp32 -> bf16 hi/lo planes --------------------------------
__global__ void __launch_bounds__(256)
a_convert(const float* __restrict__ x, __nv_bfloat16* __restrict__ p0,
          __nv_bfloat16* __restrict__ p1)
{
    size_t i = ((size_t)blockIdx.x * 256 + threadIdx.x) * 8;
    float4 v0 = *(const float4*)(x + i);
    float4 v1 = *(const float4*)(x + i + 4);
    float vv[8] = {v0.x, v0.y, v0.z, v0.w, v1.x, v1.y, v1.z, v1.w};
    __align__(16) __nv_bfloat16 hh[8], ll[8];
    #pragma unroll
    for (int j = 0; j < 8; j++) {
        __nv_bfloat16 h = __float2bfloat16(vv[j]);
        hh[j] = h;
        ll[j] = __float2bfloat16(vv[j] - __bfloat162float(h));
    }
    *(uint4*)(p0 + i) = *(uint4*)hh;
    *(uint4*)(p1 + i) = *(uint4*)ll;
}

__global__ void __launch_bounds__(256)
wt_convert(const float* __restrict__ W, __nv_bfloat16* __restrict__ t0,
           __nv_bfloat16* __restrict__ t1, int K, int N)
{
    __shared__ float tile[32][33];
    int n0 = blockIdx.x * 32, k0 = blockIdx.y * 32;
    int tx = threadIdx.x & 31, ty = threadIdx.x >> 5;
    #pragma unroll
    for (int i = 0; i < 4; i++)
        tile[ty + i * 8][tx] = W[(size_t)(k0 + ty + i * 8) * N + n0 + tx];
    __syncthreads();
    #pragma unroll
    for (int i = 0; i < 4; i++) {
        float v = tile[tx][ty + i * 8];
        size_t o = (size_t)(n0 + ty + i * 8) * K + k0 + tx;
        __nv_bfloat16 h = __float2bfloat16(v);
        t0[o] = h;
        t1[o] = __float2bfloat16(v - __bfloat162float(h));
    }
}

// ---------------- split-bf16 HMMA GEMM (3-pass) ----------------------------
// MODE: 0 plain fp32, 2 scatter fp32 to [B,H,S,DK], 3 relu -> bf16 planes
#define PLANE_B 10240
#define STAGE_B (4 * PLANE_B)
#define GSMEM   (2 * STAGE_B)

template<int MODE>
__global__ void __launch_bounds__(256, 1)
mma_gemm(const __nv_bfloat16* __restrict__ ah, const __nv_bfloat16* __restrict__ al,
         const __nv_bfloat16* __restrict__ bh, const __nv_bfloat16* __restrict__ bl,
         const float* __restrict__ bias, float* __restrict__ out,
         __nv_bfloat16* __restrict__ ph, __nv_bfloat16* __restrict__ pl,
         int K, int Nt)
{
    extern __shared__ char dsm[];
    const uint32_t sb = smem_u32(dsm);
    const int t = threadIdx.x, wid = t >> 5, lane = t & 31;
    const int warp_m = wid & 3, warp_n = wid >> 2;
    const int m0 = blockIdx.y * 128, n0 = blockIdx.x * 128;

    const __nv_bfloat16* srcs[4] = {
        ah + (size_t)m0 * K, al + (size_t)m0 * K,
        bh + (size_t)n0 * K, bl + (size_t)n0 * K };

    uint32_t dsts[8], rowK[8], segO[8];
    #pragma unroll
    for (int u = 0; u < 8; u++) {
        int g = t + (u << 8);
        int plane = g >> 9, rem = g & 511;
        int row = rem >> 2, seg = rem & 3;
        dsts[u] = plane * PLANE_B + row * 80 + seg * 16;
        rowK[u] = row; segO[u] = seg << 3;
    }

    const int a_row = warp_m * 32 + (lane & 15);
    const uint32_t a_col = (lane >> 4) * 16;
    const int b_row = warp_n * 64 + ((lane >> 4) << 3) + (lane & 7);
    const uint32_t b_col = ((lane >> 3) & 1) * 16;

    float acc[2][8][4];
    #pragma unroll
    for (int i = 0; i < 2; i++)
        #pragma unroll
        for (int j = 0; j < 8; j++)
            #pragma unroll
            for (int q = 0; q < 4; q++) acc[i][j][q] = 0.f;

    const int KT = K >> 5;
    int buf = 0;
    #pragma unroll
    for (int u = 0; u < 8; u++) {
        int plane = (t + (u << 8)) >> 9;
        CP_ASYNC16(sb + dsts[u], srcs[plane] + (size_t)rowK[u] * K + segO[u]);
    }
    CP_COMMIT();

    for (int kt = 0; kt < KT; ++kt) {
        if (kt + 1 < KT) {
            const int k0 = (kt + 1) << 5;
            const uint32_t base = sb + (buf ^ 1) * STAGE_B;
            #pragma unroll
            for (int u = 0; u < 8; u++) {
                int plane = (t + (u << 8)) >> 9;
                CP_ASYNC16(base + dsts[u],
                           srcs[plane] + (size_t)rowK[u] * K + k0 + segO[u]);
            }
            CP_COMMIT();
            CP_WAIT1();
        } else {
            CP_WAIT0();
        }
        __syncthreads();

        const uint32_t st = sb + buf * STAGE_B;
        #pragma unroll
        for (int ks = 0; ks < 2; ++ks) {
            const uint32_t kb = ks * 32;
            uint32_t ahf[2][4], alf[2][4];
            #pragma unroll
            for (int i = 0; i < 2; i++) {
                uint32_t ra = st + (a_row + i * 16) * 80 + kb + a_col;
                ldsm4(ahf[i][0], ahf[i][1], ahf[i][2], ahf[i][3], ra);
                ldsm4(alf[i][0], alf[i][1], alf[i][2], alf[i][3], ra + PLANE_B);
            }
            uint32_t bhf[8][2], blf[8][2];
            #pragma unroll
            for (int jj = 0; jj < 4; jj++) {
                uint32_t rb = st + 2 * PLANE_B + (b_row + jj * 16) * 80 + kb + b_col;
                ldsm4(bhf[2*jj][0], bhf[2*jj][1], bhf[2*jj+1][0], bhf[2*jj+1][1], rb);
                ldsm4(blf[2*jj][0], blf[2*jj][1], blf[2*jj+1][0], blf[2*jj+1][1],
                      rb + PLANE_B);
            }
            #pragma unroll
            for (int i = 0; i < 2; i++)
                #pragma unroll
                for (int j = 0; j < 8; j++) {
                    mma16816(acc[i][j], ahf[i], bhf[j]);
                    mma16816(acc[i][j], ahf[i], blf[j]);
                    mma16816(acc[i][j], alf[i], bhf[j]);
                }
        }
        __syncthreads();
        buf ^= 1;
    }

    const int rb0 = m0 + warp_m * 32 + (lane >> 2);
    const int cb0 = n0 + warp_n * 64 + (lane & 3) * 2;
    #pragma unroll
    for (int i = 0; i < 2; i++) {
        #pragma unroll
        for (int j = 0; j < 8; j++) {
            const int col = cb0 + j * 8;
            const float bb0 = bias[col], bb1 = bias[col + 1];
            #pragma unroll
            for (int half = 0; half < 2; half++) {
                const int row = rb0 + i * 16 + half * 8;
                float v0 = acc[i][j][half * 2 + 0] + bb0;
                float v1 = acc[i][j][half * 2 + 1] + bb1;
                if (MODE == 3) {
                    v0 = fmaxf(v0, 0.f); v1 = fmaxf(v1, 0.f);
                    __nv_bfloat16 h0 = __float2bfloat16(v0);
                    __nv_bfloat16 h1 = __float2bfloat16(v1);
                    __nv_bfloat16 l0 = __float2bfloat16(v0 - __bfloat162float(h0));
                    __nv_bfloat16 l1 = __float2bfloat16(v1 - __bfloat162float(h1));
                    size_t o = (size_t)row * Nt + col;
                    __nv_bfloat162 hp; hp.x = h0; hp.y = h1;
                    __nv_bfloat162 lp; lp.x = l0; lp.y = l1;
                    *(__nv_bfloat162*)(ph + o) = hp;
                    *(__nv_bfloat162*)(pl + o) = lp;
                } else {
                    float* op;
                    if (MODE == 2) {
                        int h = col >> 6, d = col & 63;
                        int b = row >> 11, s = row & 2047;
                        op = out + ((((size_t)b * NH + h) * NS + s) * NDK + d);
                    } else {
                        op = out + (size_t)row * Nt + col;
                    }
                    float2 r2; r2.x = v0; r2.y = v1;
                    *(float2*)op = r2;
                }
            }
        }
    }
}

// ---------------- flash attention: 32 rows/CTA, 4 rows/warp ----------------
#define AF_SMEM (25600 * 4)

__device__ __forceinline__ void stage_kv(uint32_t dst, const float* __restrict__ src,
                                         int c0, int t) {
    #pragma unroll
    for (int i = 0; i < 8; i++) {
        int idx = t + (i << 8);
        int c = idx >> 4, gd = idx & 15;
        CP_ASYNC16(dst + (c << 8) + ((gd ^ (c & 15)) << 4),
                   src + (size_t)(c0 + c) * NDK + (gd << 2));
    }
}

__global__ void __launch_bounds__(256, 2)
attn_flash(float* __restrict__ attw)
{
    extern __shared__ float sm[];
    float* dtab = sm;            // 2048
    float* qs   = sm + 2048;     // 2048
    float* ksm  = sm + 4096;     // 8192
    float* vsm  = sm + 12288;    // 8192
    float* ws   = sm + 20480;    // 4096
    float* mch  = sm + 24576;    // 512
    float* fs   = sm + 25088;    // 512

    const int t = threadIdx.x, lane = t & 31, w = t >> 5;
    const int bh = blockIdx.y, hh = bh & 15, bb = bh >> 4;
    const int qi0 = blockIdx.x << 5;

    const float* qb = g_q + (size_t)bh * NS * NDK;
    const float* kb = g_k + (size_t)bh * NS * NDK;
    const float* vb = g_v + (size_t)bh * NS * NDK;
    const uint32_t ku = smem_u32(ksm), vu = smem_u32(vsm);
    const int nch = (qi0 >> 7) + 1;

    stage_kv(ku, kb, 0, t);
    stage_kv(vu, vb, 0, t);
    CP_COMMIT();

    {
        const float* dt = g_decay + hh * NS;
        *(float4*)&dtab[t * 8]     = *(const float4*)(dt + t * 8);
        *(float4*)&dtab[t * 8 + 4] = *(const float4*)(dt + t * 8 + 4);
        const float* qsrc = qb + (size_t)qi0 * NDK;
        *(float4*)&qs[t * 8]       = *(const float4*)(qsrc + t * 8);
        *(float4*)&qs[t * 8 + 4]   = *(const float4*)(qsrc + t * 8 + 4);
    }

    float m[4], Z[4], ax[4], ay[4];
    #pragma unroll
    for (int r = 0; r < 4; r++) { m[r] = -3.0e38f; Z[r] = 0.f; ax[r] = 0.f; ay[r] = 0.f; }

    const int gd3 = lane >> 1, half = (lane & 1) << 1;
    const int sw = lane & 15;
    float* wsw = ws + w * 512;

    for (int ch = 0; ch < nch; ++ch) {
        const int c0 = ch << 7;
        CP_WAIT0();
        __syncthreads();

        float acc[4][4];
        #pragma unroll
        for (int r = 0; r < 4; r++)
            #pragma unroll
            for (int j = 0; j < 4; j++) acc[r][j] = 0.f;

        #pragma unroll
        for (int gd = 0; gd < 16; ++gd) {
            float4 qv[4];
            #pragma unroll
            for (int r = 0; r < 4; r++)
                qv[r] = *(const float4*)&qs[((w * 4 + r) << 6) + (gd << 2)];
            const int g2 = (gd ^ sw) << 2;
            #pragma unroll
            for (int j = 0; j < 4; j++) {
                float4 kv = *(const float4*)&ksm[((lane + (j << 5)) << 6) + g2];
                #pragma unroll
                for (int r = 0; r < 4; r++)
                    acc[r][j] += qv[r].x*kv.x + qv[r].y*kv.y + qv[r].z*kv.z + qv[r].w*kv.w;
            }
        }

        #pragma unroll
        for (int r = 0; r < 4; r++) {
            const int qi = qi0 + w * 4 + r;
            float s[4];
            #pragma unroll
            for (int j = 0; j < 4; j++) {
                int c = c0 + lane + (j << 5);
                s[j] = (c <= qi) ? acc[r][j] * 0.125f * dtab[qi - c] : -3.0e38f;
            }
            float cm = fmaxf(fmaxf(s[0], s[1]), fmaxf(s[2], s[3]));
            #pragma unroll
            for (int o = 16; o; o >>= 1)
                cm = fmaxf(cm, __shfl_xor_sync(0xffffffffu, cm, o));
            const float mnew = fmaxf(m[r], cm);
            const float scale = __expf(m[r] - mnew);
            float e[4], zs = 0.f;
            #pragma unroll
            for (int j = 0; j < 4; j++) {
                int c = c0 + lane + (j << 5);
                e[j] = (c <= qi) ? __expf(s[j] - mnew) : 0.f;
                zs += e[j];
            }
            #pragma unroll
            for (int o = 16; o; o >>= 1)
                zs += __shfl_xor_sync(0xffffffffu, zs, o);
            Z[r] = Z[r] * scale + zs;
            ax[r] *= scale; ay[r] *= scale;
            m[r] = mnew;
            if (lane == 0) mch[(w * 4 + r) * 16 + ch] = mnew;
            float* arow = attw + ((size_t)bh * NS + qi) * NS + c0;
            #pragma unroll
            for (int j = 0; j < 4; j++) {
                wsw[((lane + (j << 5)) << 2) + r] = e[j];
                arow[lane + (j << 5)] = e[j];
            }
        }
        __syncwarp();

        #pragma unroll 2
        for (int c = 0; c < 128; ++c) {
            float4 wv = *(const float4*)&wsw[c << 2];
            float2 vv = *(const float2*)&vsm[(c << 6) + ((gd3 ^ (c & 15)) << 2) + half];
            ax[0] += wv.x * vv.x; ay[0] += wv.x * vv.y;
            ax[1] += wv.y * vv.x; ay[1] += wv.y * vv.y;
            ax[2] += wv.z * vv.x; ay[2] += wv.z * vv.y;
            ax[3] += wv.w * vv.x; ay[3] += wv.w * vv.y;
        }
        __syncthreads();
        if (ch + 1 < nch) {
            stage_kv(ku, kb, c0 + 128, t);
            stage_kv(vu, vb, c0 + 128, t);
            CP_COMMIT();
        }
    }

    #pragma unroll
    for (int r = 0; r < 4; r++) {
        const int qi = qi0 + w * 4 + r;
        const float iz = 1.0f / Z[r];
        float2 res; res.x = ax[r] * iz; res.y = ay[r] * iz;
        *(float2*)&g_concat[((size_t)bb * NS + qi) * ND + hh * NDK + (lane << 1)] = res;
    }
    #pragma unroll
    for (int u = 0; u < 2; u++) {
        int idx = lane + u * 32;
        int r2 = idx >> 4, ch = idx & 15;
        fs[w * 64 + idx] = __expf(mch[(w * 4 + r2) * 16 + ch] - m[r2]) / Z[r2];
    }
    __syncwarp();

    // in-place rescale; chunks beyond the causal boundary write zeros w/o read
    #pragma unroll
    for (int r = 0; r < 4; r++) {
        const int qi = qi0 + w * 4 + r;
        const int bch = qi >> 7;
        float* arow = attw + ((size_t)bh * NS + qi) * NS;
        #pragma unroll 4
        for (int it = 0; it < 16; it++) {
            int c = it * 128 + lane * 4;
            float4 v;
            if (it > bch) {
                v.x = 0.f; v.y = 0.f; v.z = 0.f; v.w = 0.f;
            } else {
                float f = fs[w * 64 + r * 16 + it];
                v = *(float4*)(arow + c);
                v.x = (c + 0 <= qi) ? v.x * f : 0.f;
                v.y = (c + 1 <= qi) ? v.y * f : 0.f;
                v.z = (c + 2 <= qi) ? v.z * f : 0.f;
                v.w = (c + 3 <= qi) ? v.w * f : 0.f;
            }
            *(float4*)(arow + c) = v;
        }
    }
}

// ---------------- residual + layernorm -------------------------------------
__global__ void __launch_bounds__(256)
ln_kernel(const float* __restrict__ xa, const float* __restrict__ xb,
          const float* __restrict__ sg, const float* __restrict__ bg,
          float* __restrict__ out)
{
    __shared__ float red[16];
    const int row = blockIdx.x, t = threadIdx.x;
    const int lane = t & 31, wid = t >> 5;
    const size_t base = (size_t)row * ND;

    float v[4];
    #pragma unroll
    for (int i = 0; i < 4; i++) {
        int idx = t + (i << 8);
        v[i] = xa[base + idx] + xb[base + idx];
    }
    float s = v[0] + v[1] + v[2] + v[3];
    #pragma unroll
    for (int o = 16; o; o >>= 1) s += __shfl_xor_sync(0xffffffffu, s, o);
    if (lane == 0) red[wid] = s;
    __syncthreads();
    if (t == 0) {
        float tot = 0.f;
        for (int i = 0; i < 8; i++) tot += red[i];
        red[8] = tot;
    }
    __syncthreads();
    const float mean = red[8] * (1.0f / ND);

    float q = 0.f;
    #pragma unroll
    for (int i = 0; i < 4; i++) { float d = v[i] - mean; q += d * d; }
    #pragma unroll
    for (int o = 16; o; o >>= 1) q += __shfl_xor_sync(0xffffffffu, q, o);
    if (lane == 0) red[wid] = q;
    __syncthreads();
    if (t == 0) {
        float tot = 0.f;
        for (int i = 0; i < 8; i++) tot += red[i];
        red[9] = tot;
    }
    __syncthreads();
    const float rs = rsqrtf(red[9] * (1.0f / ND) + LN_EPS);

    #pragma unroll
    for (int i = 0; i < 4; i++) {
        int idx = t + (i << 8);
        out[base + idx] = (v[i] - mean) * rs * sg[idx] + bg[idx];
    }
}

// ---------------- launcher --------------------------------------------------
extern "C" void kernel_launch(void* const* d_in, const int* in_sizes, int n_in,
                              void* d_out, int out_size)
{
    const float* query  = (const float*)d_in[0];
    const float* key    = (const float*)d_in[1];
    const float* values = (const float*)d_in[2];
    const float* Wk     = (const float*)d_in[3];
    const float* bk     = (const float*)d_in[4];
    const float* Wv     = (const float*)d_in[5];
    const float* bv     = (const float*)d_in[6];
    const float* Wout   = (const float*)d_in[7];
    const float* bout   = (const float*)d_in[8];
    const float* gammas = (const float*)d_in[9];
    const float* ln1_s  = (const float*)d_in[10];
    const float* ln1_b  = (const float*)d_in[11];
    const float* W1     = (const float*)d_in[12];
    const float* b1     = (const float*)d_in[13];
    const float* W2     = (const float*)d_in[14];
    const float* b2     = (const float*)d_in[15];
    const float* ln2_s  = (const float*)d_in[16];
    const float* ln2_b  = (const float*)d_in[17];

    float* out  = (float*)d_out;
    float* attw = out + (size_t)NM * ND;

    float *pq, *pk, *pv, *pcat, *ptmp, *px1;
    __nv_bfloat16 *pah, *pal, *pfh, *pfl, *pwh, *pwl;
    cudaGetSymbolAddress((void**)&pq,   g_q);
    cudaGetSymbolAddress((void**)&pk,   g_k);
    cudaGetSymbolAddress((void**)&pv,   g_v);
    cudaGetSymbolAddress((void**)&pcat, g_concat);
    cudaGetSymbolAddress((void**)&ptmp, g_tmp);
    cudaGetSymbolAddress((void**)&px1,  g_x1);
    cudaGetSymbolAddress((void**)&pah,  g_ah);
    cudaGetSymbolAddress((void**)&pal,  g_al);
    cudaGetSymbolAddress((void**)&pfh,  g_fh);
    cudaGetSymbolAddress((void**)&pfl,  g_fl);
    cudaGetSymbolAddress((void**)&pwh,  g_wh);
    cudaGetSymbolAddress((void**)&pwl,  g_wl);

    cudaFuncSetAttribute(attn_flash,
                         cudaFuncAttributeMaxDynamicSharedMemorySize, AF_SMEM);
    cudaFuncSetAttribute(mma_gemm<0>,
                         cudaFuncAttributeMaxDynamicSharedMemorySize, GSMEM);
    cudaFuncSetAttribute(mma_gemm<2>,
                         cudaFuncAttributeMaxDynamicSharedMemorySize, GSMEM);
    cudaFuncSetAttribute(mma_gemm<3>,
                         cudaFuncAttributeMaxDynamicSharedMemorySize, GSMEM);

    const int CONV_A = (int)(((size_t)NM * ND) / 2048);

    // V-chain first (independent) -> launch index 3 = mma_gemm (ncu slot)
    prep_decay<<<NH, 256>>>(gammas);                                     // 0
    wt_convert<<<dim3(32, 32), 256>>>(Wv, pwh, pwl, ND, ND);             // 1
    a_convert<<<CONV_A, 256>>>(values, pah, pal);                        // 2
    mma_gemm<2><<<dim3(8, 64), 256, GSMEM>>>(                            // 3 (ncu)
        pah, pal, pwh, pwl, bv, pv, nullptr, nullptr, ND, ND);

    // Q+K projections: fp32 FFMA (bit-exact precision path), one launch
    gemm_f32qk<<<dim3(8, 64, 2), 256>>>(query, key, Wk, bk, pq, pk);     // 4

    attn_flash<<<dim3(NS / 32, NB * NH), 256, AF_SMEM>>>(attw);          // 5

    wt_convert<<<dim3(32, 32), 256>>>(Wout, pwh, pwl, ND, ND);           // 6
    a_convert<<<CONV_A, 256>>>(pcat, pah, pal);                          // 7
    mma_gemm<0><<<dim3(8, 64), 256, GSMEM>>>(                            // 8
        pah, pal, pwh, pwl, bout, ptmp, nullptr, nullptr, ND, ND);
    ln_kernel<<<NM, 256>>>(query, ptmp, ln1_s, ln1_b, px1);              // 9

    wt_convert<<<dim3(128, 32), 256>>>(W1, pwh, pwl, ND, NDF);           // 10
    a_convert<<<CONV_A, 256>>>(px1, pah, pal);                           // 11
    mma_gemm<3><<<dim3(32, 64), 256, GSMEM>>>(                           // 12: FFN1 -> planes
        pah, pal, pwh, pwl, b1, nullptr, pfh, pfl, ND, NDF);
    wt_convert<<<dim3(32, 128), 256>>>(W2, pwh, pwl, NDF, ND);           // 13
    mma_gemm<0><<<dim3(8, 64), 256, GSMEM>>>(                            // 14: FFN2 reads planes
        pfh, pfl, pwh, pwl, b2, ptmp, nullptr, nullptr, NDF, ND);
    ln_kernel<<<NM, 256>>>(px1, ptmp, ln2_s, ln2_b, out);                // 15
}

// round 13
// speedup vs baseline: 2.2435x; 1.0828x over previous
#include <cuda_runtime.h>
#include <cuda_bf16.h>
#include <math.h>
#include <stdint.h>

#define NB 4
#define NS 2048
#define ND 1024
#define NH 16
#define NDK 64
#define NDF 4096
#define NM (NB*NS)
#define LN_EPS 1e-5f

static __device__ float g_q[(size_t)NM*ND];
static __device__ float g_k[(size_t)NM*ND];
static __device__ float g_v[(size_t)NM*ND];
static __device__ float g_concat[(size_t)NM*ND];
static __device__ float g_tmp[(size_t)NM*ND];
static __device__ float g_x1[(size_t)NM*ND];
static __device__ float g_decay[NH*NS];
static __device__ __nv_bfloat16 g_ah[(size_t)NM*ND];
static __device__ __nv_bfloat16 g_al[(size_t)NM*ND];
static __device__ __nv_bfloat16 g_fh[(size_t)NM*NDF];
static __device__ __nv_bfloat16 g_fl[(size_t)NM*NDF];
static __device__ __nv_bfloat16 g_wh[(size_t)NDF*ND];
static __device__ __nv_bfloat16 g_wl[(size_t)NDF*ND];

__device__ __forceinline__ uint32_t smem_u32(const void* p) {
    uint32_t a;
    asm("{ .reg .u64 t; cvta.to.shared.u64 t, %1; cvt.u32.u64 %0, t; }"
        : "=r"(a) : "l"(p));
    return a;
}
#define CP_ASYNC16(dst, src) \
    asm volatile("cp.async.cg.shared.global [%0], [%1], 16;" \
                 :: "r"(dst), "l"(src) : "memory")
#define CP_COMMIT() asm volatile("cp.async.commit_group;" ::: "memory")
#define CP_WAIT0()  asm volatile("cp.async.wait_group 0;" ::: "memory")
#define CP_WAIT1()  asm volatile("cp.async.wait_group 1;" ::: "memory")

__device__ __forceinline__ void ldsm4(uint32_t& r0, uint32_t& r1,
                                      uint32_t& r2, uint32_t& r3, uint32_t a) {
    asm volatile("ldmatrix.sync.aligned.m8n8.x4.shared.b16 {%0,%1,%2,%3}, [%4];"
                 : "=r"(r0), "=r"(r1), "=r"(r2), "=r"(r3) : "r"(a));
}
__device__ __forceinline__ void mma16816(float* c, const uint32_t* a,
                                         const uint32_t* b) {
    asm volatile("mma.sync.aligned.m16n8k16.row.col.f32.bf16.bf16.f32 "
                 "{%0,%1,%2,%3}, {%4,%5,%6,%7}, {%8,%9}, {%0,%1,%2,%3};"
                 : "+f"(c[0]), "+f"(c[1]), "+f"(c[2]), "+f"(c[3])
                 : "r"(a[0]), "r"(a[1]), "r"(a[2]), "r"(a[3]),
                   "r"(b[0]), "r"(b[1]));
}

// ---------------- decay table ----------------------------------------------
__global__ void prep_decay(const float* __restrict__ gammas) {
    int h = blockIdx.x;
    float x = gammas[h];
    float sp = (x > 0.f) ? (x + log1pf(expf(-x))) : log1pf(expf(x));
    float g21 = sp * (1.0f / 21.0f);
    for (int i = threadIdx.x; i < NS; i += blockDim.x)
        g_decay[h * NS + i] = fminf(__expf((float)i * g21), 1e5f);
}

// ---------------- fp32 FFMA GEMM for Q+K (one launch, z selects) ----------
__global__ void __launch_bounds__(256)
gemm_f32qk(const float* __restrict__ A0, const float* __restrict__ A1,
           const float* __restrict__ W, const float* __restrict__ bias,
           float* __restrict__ out0, float* __restrict__ out1)
{
    const int K = ND, N = ND;
    __shared__ float As[2][16][132];
    __shared__ float Bs[2][16][132];
    const int t  = threadIdx.x;
    const int bm = blockIdx.y, bn = blockIdx.x;
    const float* A  = blockIdx.z ? A1 : A0;
    float* out      = blockIdx.z ? out1 : out0;
    const int arow = t >> 2, acol = (t & 3) << 2;
    const int brow = t >> 5, bcol = (t & 31) << 2;
    const float* Ab = A + (size_t)(bm * 128) * K;
    const float* Wb = W + bn * 128;

    float4 a0, a1, b0, b1;
    a0 = *(const float4*)(Ab + (size_t)arow * K + acol);
    a1 = *(const float4*)(Ab + (size_t)(arow + 64) * K + acol);
    b0 = *(const float4*)(Wb + (size_t)brow * N + bcol);
    b1 = *(const float4*)(Wb + (size_t)(brow + 8) * N + bcol);
    As[0][acol+0][arow] = a0.x; As[0][acol+1][arow] = a0.y;
    As[0][acol+2][arow] = a0.z; As[0][acol+3][arow] = a0.w;
    As[0][acol+0][arow+64] = a1.x; As[0][acol+1][arow+64] = a1.y;
    As[0][acol+2][arow+64] = a1.z; As[0][acol+3][arow+64] = a1.w;
    *(float4*)&Bs[0][brow][bcol]   = b0;
    *(float4*)&Bs[0][brow+8][bcol] = b1;
    __syncthreads();

    const int ty = t >> 4, tx = t & 15;
    float acc[8][8];
    #pragma unroll
    for (int i = 0; i < 8; i++)
        #pragma unroll
        for (int j = 0; j < 8; j++) acc[i][j] = 0.f;

    const int KT = K >> 4;
    int buf = 0;
    for (int kt = 0; kt < KT; ++kt) {
        if (kt + 1 < KT) {
            int k0 = (kt + 1) << 4;
            a0 = *(const float4*)(Ab + (size_t)arow * K + k0 + acol);
            a1 = *(const float4*)(Ab + (size_t)(arow + 64) * K + k0 + acol);
            b0 = *(const float4*)(Wb + (size_t)(k0 + brow) * N + bcol);
            b1 = *(const float4*)(Wb + (size_t)(k0 + brow + 8) * N + bcol);
        }
        #pragma unroll
        for (int k = 0; k < 16; k++) {
            float4 xa = *(const float4*)&As[buf][k][ty*8];
            float4 xb = *(const float4*)&As[buf][k][ty*8+4];
            float4 ya = *(const float4*)&Bs[buf][k][tx*8];
            float4 yb = *(const float4*)&Bs[buf][k][tx*8+4];
            float ar[8] = {xa.x,xa.y,xa.z,xa.w,xb.x,xb.y,xb.z,xb.w};
            float br[8] = {ya.x,ya.y,ya.z,ya.w,yb.x,yb.y,yb.z,yb.w};
            #pragma unroll
            for (int i = 0; i < 8; i++)
                #pragma unroll
                for (int j = 0; j < 8; j++)
                    acc[i][j] = fmaf(ar[i], br[j], acc[i][j]);
        }
        if (kt + 1 < KT) {
            int nb = buf ^ 1;
            As[nb][acol+0][arow] = a0.x; As[nb][acol+1][arow] = a0.y;
            As[nb][acol+2][arow] = a0.z; As[nb][acol+3][arow] = a0.w;
            As[nb][acol+0][arow+64] = a1.x; As[nb][acol+1][arow+64] = a1.y;
            As[nb][acol+2][arow+64] = a1.z; As[nb][acol+3][arow+64] = a1.w;
            *(float4*)&Bs[nb][brow][bcol]   = b0;
            *(float4*)&Bs[nb][brow+8][bcol] = b1;
        }
        __syncthreads();
        buf ^= 1;
    }

    const int gc0 = bn * 128 + tx * 8;
    #pragma unroll
    for (int i = 0; i < 8; i++) {
        int gr = bm * 128 + ty * 8 + i;
        int h = gc0 >> 6, d = gc0 & 63;
        int b = gr >> 11, s = gr & 2047;
        float* op = out + ((((size_t)b * NH + h) * NS + s) * NDK + d);
        #pragma unroll
        for (int j = 0; j < 8; j++) op[j] = acc[i][j] + bias[gc0 + j];
    }
}

// ---------------- fp32 -> bf16 hi/lo planes --------------------------------
__global__ void __launch_bounds__(256)
a_convert(const float* __restrict__ x, __nv_bfloat16* __restrict__ p0,
          __nv_bfloat16* __restrict__ p1)
{
    size_t i = ((size_t)blockIdx.x * 256 + threadIdx.x) * 8;
    float4 v0 = *(const float4*)(x + i);
    float4 v1 = *(const float4*)(x + i + 4);
    float vv[8] = {v0.x, v0.y, v0.z, v0.w, v1.x, v1.y, v1.z, v1.w};
    __align__(16) __nv_bfloat16 hh[8], ll[8];
    #pragma unroll
    for (int j = 0; j < 8; j++) {
        __nv_bfloat16 h = __float2bfloat16(vv[j]);
        hh[j] = h;
        ll[j] = __float2bfloat16(vv[j] - __bfloat162float(h));
    }
    *(uint4*)(p0 + i) = *(uint4*)hh;
    *(uint4*)(p1 + i) = *(uint4*)ll;
}

__global__ void __launch_bounds__(256)
wt_convert(const float* __restrict__ W, __nv_bfloat16* __restrict__ t0,
           __nv_bfloat16* __restrict__ t1, int K, int N)
{
    __shared__ float tile[32][33];
    int n0 = blockIdx.x * 32, k0 = blockIdx.y * 32;
    int tx = threadIdx.x & 31, ty = threadIdx.x >> 5;
    #pragma unroll
    for (int i = 0; i < 4; i++)
        tile[ty + i * 8][tx] = W[(size_t)(k0 + ty + i * 8) * N + n0 + tx];
    __syncthreads();
    #pragma unroll
    for (int i = 0; i < 4; i++) {
        float v = tile[tx][ty + i * 8];
        size_t o = (size_t)(n0 + ty + i * 8) * K + k0 + tx;
        __nv_bfloat16 h = __float2bfloat16(v);
        t0[o] = h;
        t1[o] = __float2bfloat16(v - __bfloat162float(h));
    }
}

// ---------------- split-bf16 HMMA GEMM (3-pass), 128-thr CTA, 64x128 tile --
// 4 warps (2 m x 2 n), warp tile 32x64 (identical per-warp stream as before).
// smem stage: A-hi 64r | A-lo 64r | B-hi 128r | B-lo 128r, 80B pitch = 30 KB.
// Double-buffered 60 KB -> 2 CTAs/SM (regs 2*128*187 < 64K) for phase overlap.
#define A_PLANE 5120
#define B_PLANE 10240
#define STAGE_B 30720
#define GSMEM   (2 * STAGE_B)

template<int MODE>   // 0 plain fp32, 2 scatter [B,H,S,DK], 3 relu -> bf16 planes
__global__ void __launch_bounds__(128)
mma_gemm(const __nv_bfloat16* __restrict__ ah, const __nv_bfloat16* __restrict__ al,
         const __nv_bfloat16* __restrict__ bh, const __nv_bfloat16* __restrict__ bl,
         const float* __restrict__ bias, float* __restrict__ out,
         __nv_bfloat16* __restrict__ ph, __nv_bfloat16* __restrict__ pl,
         int K, int Nt)
{
    extern __shared__ char dsm[];
    const uint32_t sb = smem_u32(dsm);
    const int t = threadIdx.x, wid = t >> 5, lane = t & 31;
    const int warp_m = wid & 1, warp_n = wid >> 1;
    const int m0 = blockIdx.y * 64, n0 = blockIdx.x * 128;

    const __nv_bfloat16* srcs[4] = {
        ah + (size_t)m0 * K, al + (size_t)m0 * K,
        bh + (size_t)n0 * K, bl + (size_t)n0 * K };

    // loader: 384 rows x 4 segs = 1536 x 16B / 128 thr = 12 per thread
    uint32_t dsts[12], rowK[12], segO[12];
    int plid[12];
    #pragma unroll
    for (int u = 0; u < 12; u++) {
        int g = t + (u << 7);
        int rr = g >> 2, seg = g & 3;
        int pl_, row, off;
        if (rr < 64)       { pl_ = 0; row = rr;       off = 0; }
        else if (rr < 128) { pl_ = 1; row = rr - 64;  off = A_PLANE; }
        else if (rr < 256) { pl_ = 2; row = rr - 128; off = 2 * A_PLANE; }
        else               { pl_ = 3; row = rr - 256; off = 2 * A_PLANE + B_PLANE; }
        dsts[u] = off + row * 80 + seg * 16;
        rowK[u] = row; segO[u] = seg << 3; plid[u] = pl_;
    }

    const int a_row = warp_m * 32 + (lane & 15);
    const uint32_t a_col = (lane >> 4) * 16;
    const int b_row = warp_n * 64 + ((lane >> 4) << 3) + (lane & 7);
    const uint32_t b_col = ((lane >> 3) & 1) * 16;

    float acc[2][8][4];
    #pragma unroll
    for (int i = 0; i < 2; i++)
        #pragma unroll
        for (int j = 0; j < 8; j++)
            #pragma unroll
            for (int q = 0; q < 4; q++) acc[i][j][q] = 0.f;

    const int KT = K >> 5;
    int buf = 0;
    #pragma unroll
    for (int u = 0; u < 12; u++)
        CP_ASYNC16(sb + dsts[u], srcs[plid[u]] + (size_t)rowK[u] * K + segO[u]);
    CP_COMMIT();

    for (int kt = 0; kt < KT; ++kt) {
        if (kt + 1 < KT) {
            const int k0 = (kt + 1) << 5;
            const uint32_t base = sb + (buf ^ 1) * STAGE_B;
            #pragma unroll
            for (int u = 0; u < 12; u++)
                CP_ASYNC16(base + dsts[u],
                           srcs[plid[u]] + (size_t)rowK[u] * K + k0 + segO[u]);
            CP_COMMIT();
            CP_WAIT1();
        } else {
            CP_WAIT0();
        }
        __syncthreads();

        const uint32_t st = sb + buf * STAGE_B;
        #pragma unroll
        for (int ks = 0; ks < 2; ++ks) {
            const uint32_t kb = ks * 32;
            uint32_t ahf[2][4], alf[2][4];
            #pragma unroll
            for (int i = 0; i < 2; i++) {
                uint32_t ra = st + (a_row + i * 16) * 80 + kb + a_col;
                ldsm4(ahf[i][0], ahf[i][1], ahf[i][2], ahf[i][3], ra);
                ldsm4(alf[i][0], alf[i][1], alf[i][2], alf[i][3], ra + A_PLANE);
            }
            uint32_t bhf[8][2], blf[8][2];
            #pragma unroll
            for (int jj = 0; jj < 4; jj++) {
                uint32_t rb = st + 2 * A_PLANE + (b_row + jj * 16) * 80 + kb + b_col;
                ldsm4(bhf[2*jj][0], bhf[2*jj][1], bhf[2*jj+1][0], bhf[2*jj+1][1], rb);
                ldsm4(blf[2*jj][0], blf[2*jj][1], blf[2*jj+1][0], blf[2*jj+1][1],
                      rb + B_PLANE);
            }
            #pragma unroll
            for (int i = 0; i < 2; i++)
                #pragma unroll
                for (int j = 0; j < 8; j++) {
                    mma16816(acc[i][j], ahf[i], bhf[j]);
                    mma16816(acc[i][j], ahf[i], blf[j]);
                    mma16816(acc[i][j], alf[i], bhf[j]);
                }
        }
        __syncthreads();
        buf ^= 1;
    }

    const int rb0 = m0 + warp_m * 32 + (lane >> 2);
    const int cb0 = n0 + warp_n * 64 + (lane & 3) * 2;
    #pragma unroll
    for (int i = 0; i < 2; i++) {
        #pragma unroll
        for (int j = 0; j < 8; j++) {
            const int col = cb0 + j * 8;
            const float bb0 = bias[col], bb1 = bias[col + 1];
            #pragma unroll
            for (int half = 0; half < 2; half++) {
                const int row = rb0 + i * 16 + half * 8;
                float v0 = acc[i][j][half * 2 + 0] + bb0;
                float v1 = acc[i][j][half * 2 + 1] + bb1;
                if (MODE == 3) {
                    v0 = fmaxf(v0, 0.f); v1 = fmaxf(v1, 0.f);
                    __nv_bfloat16 h0 = __float2bfloat16(v0);
                    __nv_bfloat16 h1 = __float2bfloat16(v1);
                    __nv_bfloat16 l0 = __float2bfloat16(v0 - __bfloat162float(h0));
                    __nv_bfloat16 l1 = __float2bfloat16(v1 - __bfloat162float(h1));
                    size_t o = (size_t)row * Nt + col;
                    __nv_bfloat162 hp; hp.x = h0; hp.y = h1;
                    __nv_bfloat162 lp; lp.x = l0; lp.y = l1;
                    *(__nv_bfloat162*)(ph + o) = hp;
                    *(__nv_bfloat162*)(pl + o) = lp;
                } else {
                    float* op;
                    if (MODE == 2) {
                        int h = col >> 6, d = col & 63;
                        int b = row >> 11, s = row & 2047;
                        op = out + ((((size_t)b * NH + h) * NS + s) * NDK + d);
                    } else {
                        op = out + (size_t)row * Nt + col;
                    }
                    float2 r2; r2.x = v0; r2.y = v1;
                    *(float2*)op = r2;
                }
            }
        }
    }
}

// ---------------- flash attention: 32 rows/CTA, 4 rows/warp ----------------
#define AF_SMEM (25600 * 4)

__device__ __forceinline__ void stage_kv(uint32_t dst, const float* __restrict__ src,
                                         int c0, int t) {
    #pragma unroll
    for (int i = 0; i < 8; i++) {
        int idx = t + (i << 8);
        int c = idx >> 4, gd = idx & 15;
        CP_ASYNC16(dst + (c << 8) + ((gd ^ (c & 15)) << 4),
                   src + (size_t)(c0 + c) * NDK + (gd << 2));
    }
}

__global__ void __launch_bounds__(256, 2)
attn_flash(float* __restrict__ attw)
{
    extern __shared__ float sm[];
    float* dtab = sm;            // 2048
    float* qs   = sm + 2048;     // 2048
    float* ksm  = sm + 4096;     // 8192
    float* vsm  = sm + 12288;    // 8192
    float* ws   = sm + 20480;    // 4096
    float* mch  = sm + 24576;    // 512
    float* fs   = sm + 25088;    // 512

    const int t = threadIdx.x, lane = t & 31, w = t >> 5;
    const int bh = blockIdx.y, hh = bh & 15, bb = bh >> 4;
    const int qi0 = blockIdx.x << 5;

    const float* qb = g_q + (size_t)bh * NS * NDK;
    const float* kb = g_k + (size_t)bh * NS * NDK;
    const float* vb = g_v + (size_t)bh * NS * NDK;
    const uint32_t ku = smem_u32(ksm), vu = smem_u32(vsm);
    const int nch = (qi0 >> 7) + 1;

    stage_kv(ku, kb, 0, t);
    stage_kv(vu, vb, 0, t);
    CP_COMMIT();

    {
        const float* dt = g_decay + hh * NS;
        *(float4*)&dtab[t * 8]     = *(const float4*)(dt + t * 8);
        *(float4*)&dtab[t * 8 + 4] = *(const float4*)(dt + t * 8 + 4);
        const float* qsrc = qb + (size_t)qi0 * NDK;
        *(float4*)&qs[t * 8]       = *(const float4*)(qsrc + t * 8);
        *(float4*)&qs[t * 8 + 4]   = *(const float4*)(qsrc + t * 8 + 4);
    }

    float m[4], Z[4], ax[4], ay[4];
    #pragma unroll
    for (int r = 0; r < 4; r++) { m[r] = -3.0e38f; Z[r] = 0.f; ax[r] = 0.f; ay[r] = 0.f; }

    const int gd3 = lane >> 1, half = (lane & 1) << 1;
    const int sw = lane & 15;
    float* wsw = ws + w * 512;

    for (int ch = 0; ch < nch; ++ch) {
        const int c0 = ch << 7;
        CP_WAIT0();
        __syncthreads();

        float acc[4][4];
        #pragma unroll
        for (int r = 0; r < 4; r++)
            #pragma unroll
            for (int j = 0; j < 4; j++) acc[r][j] = 0.f;

        #pragma unroll
        for (int gd = 0; gd < 16; ++gd) {
            float4 qv[4];
            #pragma unroll
            for (int r = 0; r < 4; r++)
                qv[r] = *(const float4*)&qs[((w * 4 + r) << 6) + (gd << 2)];
            const int g2 = (gd ^ sw) << 2;
            #pragma unroll
            for (int j = 0; j < 4; j++) {
                float4 kv = *(const float4*)&ksm[((lane + (j << 5)) << 6) + g2];
                #pragma unroll
                for (int r = 0; r < 4; r++)
                    acc[r][j] += qv[r].x*kv.x + qv[r].y*kv.y + qv[r].z*kv.z + qv[r].w*kv.w;
            }
        }

        #pragma unroll
        for (int r = 0; r < 4; r++) {
            const int qi = qi0 + w * 4 + r;
            float s[4];
            #pragma unroll
            for (int j = 0; j < 4; j++) {
                int c = c0 + lane + (j << 5);
                s[j] = (c <= qi) ? acc[r][j] * 0.125f * dtab[qi - c] : -3.0e38f;
            }
            float cm = fmaxf(fmaxf(s[0], s[1]), fmaxf(s[2], s[3]));
            #pragma unroll
            for (int o = 16; o; o >>= 1)
                cm = fmaxf(cm, __shfl_xor_sync(0xffffffffu, cm, o));
            const float mnew = fmaxf(m[r], cm);
            const float scale = __expf(m[r] - mnew);
            float e[4], zs = 0.f;
            #pragma unroll
            for (int j = 0; j < 4; j++) {
                int c = c0 + lane + (j << 5);
                e[j] = (c <= qi) ? __expf(s[j] - mnew) : 0.f;
                zs += e[j];
            }
            #pragma unroll
            for (int o = 16; o; o >>= 1)
                zs += __shfl_xor_sync(0xffffffffu, zs, o);
            Z[r] = Z[r] * scale + zs;
            ax[r] *= scale; ay[r] *= scale;
            m[r] = mnew;
            if (lane == 0) mch[(w * 4 + r) * 16 + ch] = mnew;
            float* arow = attw + ((size_t)bh * NS + qi) * NS + c0;
            #pragma unroll
            for (int j = 0; j < 4; j++) {
                wsw[((lane + (j << 5)) << 2) + r] = e[j];
                arow[lane + (j << 5)] = e[j];
            }
        }
        __syncwarp();

        #pragma unroll 2
        for (int c = 0; c < 128; ++c) {
            float4 wv = *(const float4*)&wsw[c << 2];
            float2 vv = *(const float2*)&vsm[(c << 6) + ((gd3 ^ (c & 15)) << 2) + half];
            ax[0] += wv.x * vv.x; ay[0] += wv.x * vv.y;
            ax[1] += wv.y * vv.x; ay[1] += wv.y * vv.y;
            ax[2] += wv.z * vv.x; ay[2] += wv.z * vv.y;
            ax[3] += wv.w * vv.x; ay[3] += wv.w * vv.y;
        }
        __syncthreads();
        if (ch + 1 < nch) {
            stage_kv(ku, kb, c0 + 128, t);
            stage_kv(vu, vb, c0 + 128, t);
            CP_COMMIT();
        }
    }

    #pragma unroll
    for (int r = 0; r < 4; r++) {
        const int qi = qi0 + w * 4 + r;
        const float iz = 1.0f / Z[r];
        float2 res; res.x = ax[r] * iz; res.y = ay[r] * iz;
        *(float2*)&g_concat[((size_t)bb * NS + qi) * ND + hh * NDK + (lane << 1)] = res;
    }
    #pragma unroll
    for (int u = 0; u < 2; u++) {
        int idx = lane + u * 32;
        int r2 = idx >> 4, ch = idx & 15;
        fs[w * 64 + idx] = __expf(mch[(w * 4 + r2) * 16 + ch] - m[r2]) / Z[r2];
    }
    __syncwarp();

    #pragma unroll
    for (int r = 0; r < 4; r++) {
        const int qi = qi0 + w * 4 + r;
        const int bch = qi >> 7;
        float* arow = attw + ((size_t)bh * NS + qi) * NS;
        #pragma unroll 4
        for (int it = 0; it < 16; it++) {
            int c = it * 128 + lane * 4;
            float4 v;
            if (it > bch) {
                v.x = 0.f; v.y = 0.f; v.z = 0.f; v.w = 0.f;
            } else {
                float f = fs[w * 64 + r * 16 + it];
                v = *(float4*)(arow + c);
                v.x = (c + 0 <= qi) ? v.x * f : 0.f;
                v.y = (c + 1 <= qi) ? v.y * f : 0.f;
                v.z = (c + 2 <= qi) ? v.z * f : 0.f;
                v.w = (c + 3 <= qi) ? v.w * f : 0.f;
            }
            *(float4*)(arow + c) = v;
        }
    }
}

// ---------------- residual + layernorm -------------------------------------
__global__ void __launch_bounds__(256)
ln_kernel(const float* __restrict__ xa, const float* __restrict__ xb,
          const float* __restrict__ sg, const float* __restrict__ bg,
          float* __restrict__ out)
{
    __shared__ float red[16];
    const int row = blockIdx.x, t = threadIdx.x;
    const int lane = t & 31, wid = t >> 5;
    const size_t base = (size_t)row * ND;

    float v[4];
    #pragma unroll
    for (int i = 0; i < 4; i++) {
        int idx = t + (i << 8);
        v[i] = xa[base + idx] + xb[base + idx];
    }
    float s = v[0] + v[1] + v[2] + v[3];
    #pragma unroll
    for (int o = 16; o; o >>= 1) s += __shfl_xor_sync(0xffffffffu, s, o);
    if (lane == 0) red[wid] = s;
    __syncthreads();
    if (t == 0) {
        float tot = 0.f;
        for (int i = 0; i < 8; i++) tot += red[i];
        red[8] = tot;
    }
    __syncthreads();
    const float mean = red[8] * (1.0f / ND);

    float q = 0.f;
    #pragma unroll
    for (int i = 0; i < 4; i++) { float d = v[i] - mean; q += d * d; }
    #pragma unroll
    for (int o = 16; o; o >>= 1) q += __shfl_xor_sync(0xffffffffu, q, o);
    if (lane == 0) red[wid] = q;
    __syncthreads();
    if (t == 0) {
        float tot = 0.f;
        for (int i = 0; i < 8; i++) tot += red[i];
        red[9] = tot;
    }
    __syncthreads();
    const float rs = rsqrtf(red[9] * (1.0f / ND) + LN_EPS);

    #pragma unroll
    for (int i = 0; i < 4; i++) {
        int idx = t + (i << 8);
        out[base + idx] = (v[i] - mean) * rs * sg[idx] + bg[idx];
    }
}

// ---------------- launcher --------------------------------------------------
extern "C" void kernel_launch(void* const* d_in, const int* in_sizes, int n_in,
                              void* d_out, int out_size)
{
    const float* query  = (const float*)d_in[0];
    const float* key    = (const float*)d_in[1];
    const float* values = (const float*)d_in[2];
    const float* Wk     = (const float*)d_in[3];
    const float* bk     = (const float*)d_in[4];
    const float* Wv     = (const float*)d_in[5];
    const float* bv     = (const float*)d_in[6];
    const float* Wout   = (const float*)d_in[7];
    const float* bout   = (const float*)d_in[8];
    const float* gammas = (const float*)d_in[9];
    const float* ln1_s  = (const float*)d_in[10];
    const float* ln1_b  = (const float*)d_in[11];
    const float* W1     = (const float*)d_in[12];
    const float* b1     = (const float*)d_in[13];
    const float* W2     = (const float*)d_in[14];
    const float* b2     = (const float*)d_in[15];
    const float* ln2_s  = (const float*)d_in[16];
    const float* ln2_b  = (const float*)d_in[17];

    float* out  = (float*)d_out;
    float* attw = out + (size_t)NM * ND;

    float *pq, *pk, *pv, *pcat, *ptmp, *px1;
    __nv_bfloat16 *pah, *pal, *pfh, *pfl, *pwh, *pwl;
    cudaGetSymbolAddress((void**)&pq,   g_q);
    cudaGetSymbolAddress((void**)&pk,   g_k);
    cudaGetSymbolAddress((void**)&pv,   g_v);
    cudaGetSymbolAddress((void**)&pcat, g_concat);
    cudaGetSymbolAddress((void**)&ptmp, g_tmp);
    cudaGetSymbolAddress((void**)&px1,  g_x1);
    cudaGetSymbolAddress((void**)&pah,  g_ah);
    cudaGetSymbolAddress((void**)&pal,  g_al);
    cudaGetSymbolAddress((void**)&pfh,  g_fh);
    cudaGetSymbolAddress((void**)&pfl,  g_fl);
    cudaGetSymbolAddress((void**)&pwh,  g_wh);
    cudaGetSymbolAddress((void**)&pwl,  g_wl);

    cudaFuncSetAttribute(attn_flash,
                         cudaFuncAttributeMaxDynamicSharedMemorySize, AF_SMEM);
    cudaFuncSetAttribute(mma_gemm<0>,
                         cudaFuncAttributeMaxDynamicSharedMemorySize, GSMEM);
    cudaFuncSetAttribute(mma_gemm<2>,
                         cudaFuncAttributeMaxDynamicSharedMemorySize, GSMEM);
    cudaFuncSetAttribute(mma_gemm<3>,
                         cudaFuncAttributeMaxDynamicSharedMemorySize, GSMEM);

    const int CONV_A = (int)(((size_t)NM * ND) / 2048);

    // V-chain first (independent) -> launch index 3 = mma_gemm (ncu slot)
    prep_decay<<<NH, 256>>>(gammas);                                     // 0
    wt_convert<<<dim3(32, 32), 256>>>(Wv, pwh, pwl, ND, ND);             // 1
    a_convert<<<CONV_A, 256>>>(values, pah, pal);                        // 2
    mma_gemm<2><<<dim3(8, 128), 128, GSMEM>>>(                           // 3 (ncu)
        pah, pal, pwh, pwl, bv, pv, nullptr, nullptr, ND, ND);

    // Q+K projections: fp32 FFMA (bit-exact precision path), one launch
    gemm_f32qk<<<dim3(8, 64, 2), 256>>>(query, key, Wk, bk, pq, pk);     // 4

    attn_flash<<<dim3(NS / 32, NB * NH), 256, AF_SMEM>>>(attw);          // 5

    wt_convert<<<dim3(32, 32), 256>>>(Wout, pwh, pwl, ND, ND);           // 6
    a_convert<<<CONV_A, 256>>>(pcat, pah, pal);                          // 7
    mma_gemm<0><<<dim3(8, 128), 128, GSMEM>>>(                           // 8
        pah, pal, pwh, pwl, bout, ptmp, nullptr, nullptr, ND, ND);
    ln_kernel<<<NM, 256>>>(query, ptmp, ln1_s, ln1_b, px1);              // 9

    wt_convert<<<dim3(128, 32), 256>>>(W1, pwh, pwl, ND, NDF);           // 10
    a_convert<<<CONV_A, 256>>>(px1, pah, pal);                           // 11
    mma_gemm<3><<<dim3(32, 128), 128, GSMEM>>>(                          // 12: FFN1 -> planes
        pah, pal, pwh, pwl, b1, nullptr, pfh, pfl, ND, NDF);
    wt_convert<<<dim3(32, 128), 256>>>(W2, pwh, pwl, NDF, ND);           // 13
    mma_gemm<0><<<dim3(8, 128), 128, GSMEM>>>(                           // 14: FFN2 reads planes
        pfh, pfl, pwh, pwl, b2, ptmp, nullptr, nullptr, NDF, ND);
    ln_kernel<<<NM, 256>>>(px1, ptmp, ln2_s, ln2_b, out);                // 15
}

// round 14
// speedup vs baseline: 2.2668x; 1.0104x over previous
#include <cuda_runtime.h>
#include <cuda_bf16.h>
#include <math.h>
#include <stdint.h>

#define NB 4
#define NS 2048
#define ND 1024
#define NH 16
#define NDK 64
#define NDF 4096
#define NM (NB*NS)
#define LN_EPS 1e-5f

static __device__ float g_q[(size_t)NM*ND];
static __device__ float g_k[(size_t)NM*ND];
static __device__ float g_v[(size_t)NM*ND];
static __device__ float g_tmp[(size_t)NM*ND];
static __device__ float g_x1[(size_t)NM*ND];
static __device__ float g_decay[NH*NS];
static __device__ __nv_bfloat16 g_ah[(size_t)NM*ND];    // A hi plane
static __device__ __nv_bfloat16 g_al[(size_t)NM*ND];    // A lo plane
static __device__ __nv_bfloat16 g_fh[(size_t)NM*NDF];   // FFN hidden hi
static __device__ __nv_bfloat16 g_fl[(size_t)NM*NDF];   // FFN hidden lo
static __device__ __nv_bfloat16 g_wh[(size_t)NDF*ND];   // W^T hi
static __device__ __nv_bfloat16 g_wl[(size_t)NDF*ND];   // W^T lo

__device__ __forceinline__ uint32_t smem_u32(const void* p) {
    uint32_t a;
    asm("{ .reg .u64 t; cvta.to.shared.u64 t, %1; cvt.u32.u64 %0, t; }"
        : "=r"(a) : "l"(p));
    return a;
}
#define CP_ASYNC16(dst, src) \
    asm volatile("cp.async.cg.shared.global [%0], [%1], 16;" \
                 :: "r"(dst), "l"(src) : "memory")
#define CP_COMMIT() asm volatile("cp.async.commit_group;" ::: "memory")
#define CP_WAIT0()  asm volatile("cp.async.wait_group 0;" ::: "memory")
#define CP_WAIT1()  asm volatile("cp.async.wait_group 1;" ::: "memory")

__device__ __forceinline__ void ldsm4(uint32_t& r0, uint32_t& r1,
                                      uint32_t& r2, uint32_t& r3, uint32_t a) {
    asm volatile("ldmatrix.sync.aligned.m8n8.x4.shared.b16 {%0,%1,%2,%3}, [%4];"
                 : "=r"(r0), "=r"(r1), "=r"(r2), "=r"(r3) : "r"(a));
}
__device__ __forceinline__ void mma16816(float* c, const uint32_t* a,
                                         const uint32_t* b) {
    asm volatile("mma.sync.aligned.m16n8k16.row.col.f32.bf16.bf16.f32 "
                 "{%0,%1,%2,%3}, {%4,%5,%6,%7}, {%8,%9}, {%0,%1,%2,%3};"
                 : "+f"(c[0]), "+f"(c[1]), "+f"(c[2]), "+f"(c[3])
                 : "r"(a[0]), "r"(a[1]), "r"(a[2]), "r"(a[3]),
                   "r"(b[0]), "r"(b[1]));
}

// ---------------- decay table ----------------------------------------------
__global__ void prep_decay(const float* __restrict__ gammas) {
    int h = blockIdx.x;
    float x = gammas[h];
    float sp = (x > 0.f) ? (x + log1pf(expf(-x))) : log1pf(expf(x));
    float g21 = sp * (1.0f / 21.0f);
    for (int i = threadIdx.x; i < NS; i += blockDim.x)
        g_decay[h * NS + i] = fminf(__expf((float)i * g21), 1e5f);
}

// ---------------- fp32 FFMA GEMM for Q+K (one launch, z selects) ----------
__global__ void __launch_bounds__(256)
gemm_f32qk(const float* __restrict__ A0, const float* __restrict__ A1,
           const float* __restrict__ W, const float* __restrict__ bias,
           float* __restrict__ out0, float* __restrict__ out1)
{
    const int K = ND, N = ND;
    __shared__ float As[2][16][132];
    __shared__ float Bs[2][16][132];
    const int t  = threadIdx.x;
    const int bm = blockIdx.y, bn = blockIdx.x;
    const float* A  = blockIdx.z ? A1 : A0;
    float* out      = blockIdx.z ? out1 : out0;
    const int arow = t >> 2, acol = (t & 3) << 2;
    const int brow = t >> 5, bcol = (t & 31) << 2;
    const float* Ab = A + (size_t)(bm * 128) * K;
    const float* Wb = W + bn * 128;

    float4 a0, a1, b0, b1;
    a0 = *(const float4*)(Ab + (size_t)arow * K + acol);
    a1 = *(const float4*)(Ab + (size_t)(arow + 64) * K + acol);
    b0 = *(const float4*)(Wb + (size_t)brow * N + bcol);
    b1 = *(const float4*)(Wb + (size_t)(brow + 8) * N + bcol);
    As[0][acol+0][arow] = a0.x; As[0][acol+1][arow] = a0.y;
    As[0][acol+2][arow] = a0.z; As[0][acol+3][arow] = a0.w;
    As[0][acol+0][arow+64] = a1.x; As[0][acol+1][arow+64] = a1.y;
    As[0][acol+2][arow+64] = a1.z; As[0][acol+3][arow+64] = a1.w;
    *(float4*)&Bs[0][brow][bcol]   = b0;
    *(float4*)&Bs[0][brow+8][bcol] = b1;
    __syncthreads();

    const int ty = t >> 4, tx = t & 15;
    float acc[8][8];
    #pragma unroll
    for (int i = 0; i < 8; i++)
        #pragma unroll
        for (int j = 0; j < 8; j++) acc[i][j] = 0.f;

    const int KT = K >> 4;
    int buf = 0;
    for (int kt = 0; kt < KT; ++kt) {
        if (kt + 1 < KT) {
            int k0 = (kt + 1) << 4;
            a0 = *(const float4*)(Ab + (size_t)arow * K + k0 + acol);
            a1 = *(const float4*)(Ab + (size_t)(arow + 64) * K + k0 + acol);
            b0 = *(const float4*)(Wb + (size_t)(k0 + brow) * N + bcol);
            b1 = *(const float4*)(Wb + (size_t)(k0 + brow + 8) * N + bcol);
        }
        #pragma unroll
        for (int k = 0; k < 16; k++) {
            float4 xa = *(const float4*)&As[buf][k][ty*8];
            float4 xb = *(const float4*)&As[buf][k][ty*8+4];
            float4 ya = *(const float4*)&Bs[buf][k][tx*8];
            float4 yb = *(const float4*)&Bs[buf][k][tx*8+4];
            float ar[8] = {xa.x,xa.y,xa.z,xa.w,xb.x,xb.y,xb.z,xb.w};
            float br[8] = {ya.x,ya.y,ya.z,ya.w,yb.x,yb.y,yb.z,yb.w};
            #pragma unroll
            for (int i = 0; i < 8; i++)
                #pragma unroll
                for (int j = 0; j < 8; j++)
                    acc[i][j] = fmaf(ar[i], br[j], acc[i][j]);
        }
        if (kt + 1 < KT) {
            int nb = buf ^ 1;
            As[nb][acol+0][arow] = a0.x; As[nb][acol+1][arow] = a0.y;
            As[nb][acol+2][arow] = a0.z; As[nb][acol+3][arow] = a0.w;
            As[nb][acol+0][arow+64] = a1.x; As[nb][acol+1][arow+64] = a1.y;
            As[nb][acol+2][arow+64] = a1.z; As[nb][acol+3][arow+64] = a1.w;
            *(float4*)&Bs[nb][brow][bcol]   = b0;
            *(float4*)&Bs[nb][brow+8][bcol] = b1;
        }
        __syncthreads();
        buf ^= 1;
    }

    const int gc0 = bn * 128 + tx * 8;
    #pragma unroll
    for (int i = 0; i < 8; i++) {
        int gr = bm * 128 + ty * 8 + i;
        int h = gc0 >> 6, d = gc0 & 63;
        int b = gr >> 11, s = gr & 2047;
        float* op = out + ((((size_t)b * NH + h) * NS + s) * NDK + d);
        #pragma unroll
        for (int j = 0; j < 8; j++) op[j] = acc[i][j] + bias[gc0 + j];
    }
}

// ---------------- fp32 -> bf16 hi/lo planes --------------------------------
__global__ void __launch_bounds__(256)
a_convert(const float* __restrict__ x, __nv_bfloat16* __restrict__ p0,
          __nv_bfloat16* __restrict__ p1)
{
    size_t i = ((size_t)blockIdx.x * 256 + threadIdx.x) * 8;
    float4 v0 = *(const float4*)(x + i);
    float4 v1 = *(const float4*)(x + i + 4);
    float vv[8] = {v0.x, v0.y, v0.z, v0.w, v1.x, v1.y, v1.z, v1.w};
    __align__(16) __nv_bfloat16 hh[8], ll[8];
    #pragma unroll
    for (int j = 0; j < 8; j++) {
        __nv_bfloat16 h = __float2bfloat16(vv[j]);
        hh[j] = h;
        ll[j] = __float2bfloat16(vv[j] - __bfloat162float(h));
    }
    *(uint4*)(p0 + i) = *(uint4*)hh;
    *(uint4*)(p1 + i) = *(uint4*)ll;
}

__global__ void __launch_bounds__(256)
wt_convert(const float* __restrict__ W, __nv_bfloat16* __restrict__ t0,
           __nv_bfloat16* __restrict__ t1, int K, int N)
{
    __shared__ float tile[32][33];
    int n0 = blockIdx.x * 32, k0 = blockIdx.y * 32;
    int tx = threadIdx.x & 31, ty = threadIdx.x >> 5;
    #pragma unroll
    for (int i = 0; i < 4; i++)
        tile[ty + i * 8][tx] = W[(size_t)(k0 + ty + i * 8) * N + n0 + tx];
    __syncthreads();
    #pragma unroll
    for (int i = 0; i < 4; i++) {
        float v = tile[tx][ty + i * 8];
        size_t o = (size_t)(n0 + ty + i * 8) * K + k0 + tx;
        __nv_bfloat16 h = __float2bfloat16(v);
        t0[o] = h;
        t1[o] = __float2bfloat16(v - __bfloat162float(h));
    }
}

// ---------------- split-bf16 HMMA GEMM (3-pass), 128-thr CTA, 64x128 tile --
// occupancy 3 CTAs/SM (regs capped 170, smem 3x60=180KB) for phase overlap.
#define A_PLANE 5120
#define B_PLANE 10240
#define STAGE_B 30720
#define GSMEM   (2 * STAGE_B)

template<int MODE>   // 0 plain fp32, 2 scatter [B,H,S,DK], 3 relu -> bf16 planes
__global__ void __launch_bounds__(128, 3)
mma_gemm(const __nv_bfloat16* __restrict__ ah, const __nv_bfloat16* __restrict__ al,
         const __nv_bfloat16* __restrict__ bh, const __nv_bfloat16* __restrict__ bl,
         const float* __restrict__ bias, float* __restrict__ out,
         __nv_bfloat16* __restrict__ ph, __nv_bfloat16* __restrict__ pl,
         int K, int Nt)
{
    extern __shared__ char dsm[];
    const uint32_t sb = smem_u32(dsm);
    const int t = threadIdx.x, wid = t >> 5, lane = t & 31;
    const int warp_m = wid & 1, warp_n = wid >> 1;
    const int m0 = blockIdx.y * 64, n0 = blockIdx.x * 128;

    const __nv_bfloat16* srcs[4] = {
        ah + (size_t)m0 * K, al + (size_t)m0 * K,
        bh + (size_t)n0 * K, bl + (size_t)n0 * K };

    uint32_t dsts[12], rowK[12], segO[12];
    int plid[12];
    #pragma unroll
    for (int u = 0; u < 12; u++) {
        int g = t + (u << 7);
        int rr = g >> 2, seg = g & 3;
        int pl_, row, off;
        if (rr < 64)       { pl_ = 0; row = rr;       off = 0; }
        else if (rr < 128) { pl_ = 1; row = rr - 64;  off = A_PLANE; }
        else if (rr < 256) { pl_ = 2; row = rr - 128; off = 2 * A_PLANE; }
        else               { pl_ = 3; row = rr - 256; off = 2 * A_PLANE + B_PLANE; }
        dsts[u] = off + row * 80 + seg * 16;
        rowK[u] = row; segO[u] = seg << 3; plid[u] = pl_;
    }

    const int a_row = warp_m * 32 + (lane & 15);
    const uint32_t a_col = (lane >> 4) * 16;
    const int b_row = warp_n * 64 + ((lane >> 4) << 3) + (lane & 7);
    const uint32_t b_col = ((lane >> 3) & 1) * 16;

    float acc[2][8][4];
    #pragma unroll
    for (int i = 0; i < 2; i++)
        #pragma unroll
        for (int j = 0; j < 8; j++)
            #pragma unroll
            for (int q = 0; q < 4; q++) acc[i][j][q] = 0.f;

    const int KT = K >> 5;
    int buf = 0;
    #pragma unroll
    for (int u = 0; u < 12; u++)
        CP_ASYNC16(sb + dsts[u], srcs[plid[u]] + (size_t)rowK[u] * K + segO[u]);
    CP_COMMIT();

    for (int kt = 0; kt < KT; ++kt) {
        if (kt + 1 < KT) {
            const int k0 = (kt + 1) << 5;
            const uint32_t base = sb + (buf ^ 1) * STAGE_B;
            #pragma unroll
            for (int u = 0; u < 12; u++)
                CP_ASYNC16(base + dsts[u],
                           srcs[plid[u]] + (size_t)rowK[u] * K + k0 + segO[u]);
            CP_COMMIT();
            CP_WAIT1();
        } else {
            CP_WAIT0();
        }
        __syncthreads();

        const uint32_t st = sb + buf * STAGE_B;
        #pragma unroll
        for (int ks = 0; ks < 2; ++ks) {
            const uint32_t kb = ks * 32;
            uint32_t ahf[2][4], alf[2][4];
            #pragma unroll
            for (int i = 0; i < 2; i++) {
                uint32_t ra = st + (a_row + i * 16) * 80 + kb + a_col;
                ldsm4(ahf[i][0], ahf[i][1], ahf[i][2], ahf[i][3], ra);
                ldsm4(alf[i][0], alf[i][1], alf[i][2], alf[i][3], ra + A_PLANE);
            }
            uint32_t bhf[8][2], blf[8][2];
            #pragma unroll
            for (int jj = 0; jj < 4; jj++) {
                uint32_t rb = st + 2 * A_PLANE + (b_row + jj * 16) * 80 + kb + b_col;
                ldsm4(bhf[2*jj][0], bhf[2*jj][1], bhf[2*jj+1][0], bhf[2*jj+1][1], rb);
                ldsm4(blf[2*jj][0], blf[2*jj][1], blf[2*jj+1][0], blf[2*jj+1][1],
                      rb + B_PLANE);
            }
            #pragma unroll
            for (int i = 0; i < 2; i++)
                #pragma unroll
                for (int j = 0; j < 8; j++) {
                    mma16816(acc[i][j], ahf[i], bhf[j]);
                    mma16816(acc[i][j], ahf[i], blf[j]);
                    mma16816(acc[i][j], alf[i], bhf[j]);
                }
        }
        __syncthreads();
        buf ^= 1;
    }

    const int rb0 = m0 + warp_m * 32 + (lane >> 2);
    const int cb0 = n0 + warp_n * 64 + (lane & 3) * 2;
    #pragma unroll
    for (int i = 0; i < 2; i++) {
        #pragma unroll
        for (int j = 0; j < 8; j++) {
            const int col = cb0 + j * 8;
            const float bb0 = bias[col], bb1 = bias[col + 1];
            #pragma unroll
            for (int half = 0; half < 2; half++) {
                const int row = rb0 + i * 16 + half * 8;
                float v0 = acc[i][j][half * 2 + 0] + bb0;
                float v1 = acc[i][j][half * 2 + 1] + bb1;
                if (MODE == 3) {
                    v0 = fmaxf(v0, 0.f); v1 = fmaxf(v1, 0.f);
                    __nv_bfloat16 h0 = __float2bfloat16(v0);
                    __nv_bfloat16 h1 = __float2bfloat16(v1);
                    __nv_bfloat16 l0 = __float2bfloat16(v0 - __bfloat162float(h0));
                    __nv_bfloat16 l1 = __float2bfloat16(v1 - __bfloat162float(h1));
                    size_t o = (size_t)row * Nt + col;
                    __nv_bfloat162 hp; hp.x = h0; hp.y = h1;
                    __nv_bfloat162 lp; lp.x = l0; lp.y = l1;
                    *(__nv_bfloat162*)(ph + o) = hp;
                    *(__nv_bfloat162*)(pl + o) = lp;
                } else {
                    float* op;
                    if (MODE == 2) {
                        int h = col >> 6, d = col & 63;
                        int b = row >> 11, s = row & 2047;
                        op = out + ((((size_t)b * NH + h) * NS + s) * NDK + d);
                    } else {
                        op = out + (size_t)row * Nt + col;
                    }
                    float2 r2; r2.x = v0; r2.y = v1;
                    *(float2*)op = r2;
                }
            }
        }
    }
}

// ---------------- flash attention: 32 rows/CTA, 4 rows/warp ----------------
// ctx epilogue writes bf16 hi/lo planes directly (bit-exact vs a_convert).
#define AF_SMEM (25600 * 4)

__device__ __forceinline__ void stage_kv(uint32_t dst, const float* __restrict__ src,
                                         int c0, int t) {
    #pragma unroll
    for (int i = 0; i < 8; i++) {
        int idx = t + (i << 8);
        int c = idx >> 4, gd = idx & 15;
        CP_ASYNC16(dst + (c << 8) + ((gd ^ (c & 15)) << 4),
                   src + (size_t)(c0 + c) * NDK + (gd << 2));
    }
}

__global__ void __launch_bounds__(256, 2)
attn_flash(float* __restrict__ attw)
{
    extern __shared__ float sm[];
    float* dtab = sm;            // 2048
    float* qs   = sm + 2048;     // 2048
    float* ksm  = sm + 4096;     // 8192
    float* vsm  = sm + 12288;    // 8192
    float* ws   = sm + 20480;    // 4096
    float* mch  = sm + 24576;    // 512
    float* fs   = sm + 25088;    // 512

    const int t = threadIdx.x, lane = t & 31, w = t >> 5;
    const int bh = blockIdx.y, hh = bh & 15, bb = bh >> 4;
    const int qi0 = blockIdx.x << 5;

    const float* qb = g_q + (size_t)bh * NS * NDK;
    const float* kb = g_k + (size_t)bh * NS * NDK;
    const float* vb = g_v + (size_t)bh * NS * NDK;
    const uint32_t ku = smem_u32(ksm), vu = smem_u32(vsm);
    const int nch = (qi0 >> 7) + 1;

    stage_kv(ku, kb, 0, t);
    stage_kv(vu, vb, 0, t);
    CP_COMMIT();

    {
        const float* dt = g_decay + hh * NS;
        *(float4*)&dtab[t * 8]     = *(const float4*)(dt + t * 8);
        *(float4*)&dtab[t * 8 + 4] = *(const float4*)(dt + t * 8 + 4);
        const float* qsrc = qb + (size_t)qi0 * NDK;
        *(float4*)&qs[t * 8]       = *(const float4*)(qsrc + t * 8);
        *(float4*)&qs[t * 8 + 4]   = *(const float4*)(qsrc + t * 8 + 4);
    }

    float m[4], Z[4], ax[4], ay[4];
    #pragma unroll
    for (int r = 0; r < 4; r++) { m[r] = -3.0e38f; Z[r] = 0.f; ax[r] = 0.f; ay[r] = 0.f; }

    const int gd3 = lane >> 1, half = (lane & 1) << 1;
    const int sw = lane & 15;
    float* wsw = ws + w * 512;

    for (int ch = 0; ch < nch; ++ch) {
        const int c0 = ch << 7;
        CP_WAIT0();
        __syncthreads();

        float acc[4][4];
        #pragma unroll
        for (int r = 0; r < 4; r++)
            #pragma unroll
            for (int j = 0; j < 4; j++) acc[r][j] = 0.f;

        #pragma unroll
        for (int gd = 0; gd < 16; ++gd) {
            float4 qv[4];
            #pragma unroll
            for (int r = 0; r < 4; r++)
                qv[r] = *(const float4*)&qs[((w * 4 + r) << 6) + (gd << 2)];
            const int g2 = (gd ^ sw) << 2;
            #pragma unroll
            for (int j = 0; j < 4; j++) {
                float4 kv = *(const float4*)&ksm[((lane + (j << 5)) << 6) + g2];
                #pragma unroll
                for (int r = 0; r < 4; r++)
                    acc[r][j] += qv[r].x*kv.x + qv[r].y*kv.y + qv[r].z*kv.z + qv[r].w*kv.w;
            }
        }

        #pragma unroll
        for (int r = 0; r < 4; r++) {
            const int qi = qi0 + w * 4 + r;
            float s[4];
            #pragma unroll
            for (int j = 0; j < 4; j++) {
                int c = c0 + lane + (j << 5);
                s[j] = (c <= qi) ? acc[r][j] * 0.125f * dtab[qi - c] : -3.0e38f;
            }
            float cm = fmaxf(fmaxf(s[0], s[1]), fmaxf(s[2], s[3]));
            #pragma unroll
            for (int o = 16; o; o >>= 1)
                cm = fmaxf(cm, __shfl_xor_sync(0xffffffffu, cm, o));
            const float mnew = fmaxf(m[r], cm);
            const float scale = __expf(m[r] - mnew);
            float e[4], zs = 0.f;
            #pragma unroll
            for (int j = 0; j < 4; j++) {
                int c = c0 + lane + (j << 5);
                e[j] = (c <= qi) ? __expf(s[j] - mnew) : 0.f;
                zs += e[j];
            }
            #pragma unroll
            for (int o = 16; o; o >>= 1)
                zs += __shfl_xor_sync(0xffffffffu, zs, o);
            Z[r] = Z[r] * scale + zs;
            ax[r] *= scale; ay[r] *= scale;
            m[r] = mnew;
            if (lane == 0) mch[(w * 4 + r) * 16 + ch] = mnew;
            float* arow = attw + ((size_t)bh * NS + qi) * NS + c0;
            #pragma unroll
            for (int j = 0; j < 4; j++) {
                wsw[((lane + (j << 5)) << 2) + r] = e[j];
                arow[lane + (j << 5)] = e[j];
            }
        }
        __syncwarp();

        #pragma unroll 2
        for (int c = 0; c < 128; ++c) {
            float4 wv = *(const float4*)&wsw[c << 2];
            float2 vv = *(const float2*)&vsm[(c << 6) + ((gd3 ^ (c & 15)) << 2) + half];
            ax[0] += wv.x * vv.x; ay[0] += wv.x * vv.y;
            ax[1] += wv.y * vv.x; ay[1] += wv.y * vv.y;
            ax[2] += wv.z * vv.x; ay[2] += wv.z * vv.y;
            ax[3] += wv.w * vv.x; ay[3] += wv.w * vv.y;
        }
        __syncthreads();
        if (ch + 1 < nch) {
            stage_kv(ku, kb, c0 + 128, t);
            stage_kv(vu, vb, c0 + 128, t);
            CP_COMMIT();
        }
    }

    // ctx out: write bf16 hi/lo planes directly (same split as a_convert)
    #pragma unroll
    for (int r = 0; r < 4; r++) {
        const int qi = qi0 + w * 4 + r;
        const float iz = 1.0f / Z[r];
        float v0 = ax[r] * iz, v1 = ay[r] * iz;
        __nv_bfloat16 h0 = __float2bfloat16(v0);
        __nv_bfloat16 h1 = __float2bfloat16(v1);
        __nv_bfloat16 l0 = __float2bfloat16(v0 - __bfloat162float(h0));
        __nv_bfloat16 l1 = __float2bfloat16(v1 - __bfloat162float(h1));
        size_t o = ((size_t)bb * NS + qi) * ND + hh * NDK + (lane << 1);
        __nv_bfloat162 hp; hp.x = h0; hp.y = h1;
        __nv_bfloat162 lp; lp.x = l0; lp.y = l1;
        *(__nv_bfloat162*)(g_ah + o) = hp;
        *(__nv_bfloat162*)(g_al + o) = lp;
    }
    #pragma unroll
    for (int u = 0; u < 2; u++) {
        int idx = lane + u * 32;
        int r2 = idx >> 4, ch = idx & 15;
        fs[w * 64 + idx] = __expf(mch[(w * 4 + r2) * 16 + ch] - m[r2]) / Z[r2];
    }
    __syncwarp();

    #pragma unroll
    for (int r = 0; r < 4; r++) {
        const int qi = qi0 + w * 4 + r;
        const int bch = qi >> 7;
        float* arow = attw + ((size_t)bh * NS + qi) * NS;
        #pragma unroll 4
        for (int it = 0; it < 16; it++) {
            int c = it * 128 + lane * 4;
            float4 v;
            if (it > bch) {
                v.x = 0.f; v.y = 0.f; v.z = 0.f; v.w = 0.f;
            } else {
                float f = fs[w * 64 + r * 16 + it];
                v = *(float4*)(arow + c);
                v.x = (c + 0 <= qi) ? v.x * f : 0.f;
                v.y = (c + 1 <= qi) ? v.y * f : 0.f;
                v.z = (c + 2 <= qi) ? v.z * f : 0.f;
                v.w = (c + 3 <= qi) ? v.w * f : 0.f;
            }
            *(float4*)(arow + c) = v;
        }
    }
}

// ---------------- residual + layernorm -------------------------------------
__global__ void __launch_bounds__(256)
ln_kernel(const float* __restrict__ xa, const float* __restrict__ xb,
          const float* __restrict__ sg, const float* __restrict__ bg,
          float* __restrict__ out)
{
    __shared__ float red[16];
    const int row = blockIdx.x, t = threadIdx.x;
    const int lane = t & 31, wid = t >> 5;
    const size_t base = (size_t)row * ND;

    float v[4];
    #pragma unroll
    for (int i = 0; i < 4; i++) {
        int idx = t + (i << 8);
        v[i] = xa[base + idx] + xb[base + idx];
    }
    float s = v[0] + v[1] + v[2] + v[3];
    #pragma unroll
    for (int o = 16; o; o >>= 1) s += __shfl_xor_sync(0xffffffffu, s, o);
    if (lane == 0) red[wid] = s;
    __syncthreads();
    if (t == 0) {
        float tot = 0.f;
        for (int i = 0; i < 8; i++) tot += red[i];
        red[8] = tot;
    }
    __syncthreads();
    const float mean = red[8] * (1.0f / ND);

    float q = 0.f;
    #pragma unroll
    for (int i = 0; i < 4; i++) { float d = v[i] - mean; q += d * d; }
    #pragma unroll
    for (int o = 16; o; o >>= 1) q += __shfl_xor_sync(0xffffffffu, q, o);
    if (lane == 0) red[wid] = q;
    __syncthreads();
    if (t == 0) {
        float tot = 0.f;
        for (int i = 0; i < 8; i++) tot += red[i];
        red[9] = tot;
    }
    __syncthreads();
    const float rs = rsqrtf(red[9] * (1.0f / ND) + LN_EPS);

    #pragma unroll
    for (int i = 0; i < 4; i++) {
        int idx = t + (i << 8);
        out[base + idx] = (v[i] - mean) * rs * sg[idx] + bg[idx];
    }
}

// ---------------- launcher --------------------------------------------------
extern "C" void kernel_launch(void* const* d_in, const int* in_sizes, int n_in,
                              void* d_out, int out_size)
{
    const float* query  = (const float*)d_in[0];
    const float* key    = (const float*)d_in[1];
    const float* values = (const float*)d_in[2];
    const float* Wk     = (const float*)d_in[3];
    const float* bk     = (const float*)d_in[4];
    const float* Wv     = (const float*)d_in[5];
    const float* bv     = (const float*)d_in[6];
    const float* Wout   = (const float*)d_in[7];
    const float* bout   = (const float*)d_in[8];
    const float* gammas = (const float*)d_in[9];
    const float* ln1_s  = (const float*)d_in[10];
    const float* ln1_b  = (const float*)d_in[11];
    const float* W1     = (const float*)d_in[12];
    const float* b1     = (const float*)d_in[13];
    const float* W2     = (const float*)d_in[14];
    const float* b2     = (const float*)d_in[15];
    const float* ln2_s  = (const float*)d_in[16];
    const float* ln2_b  = (const float*)d_in[17];

    float* out  = (float*)d_out;
    float* attw = out + (size_t)NM * ND;

    float *pq, *pk, *pv, *ptmp, *px1;
    __nv_bfloat16 *pah, *pal, *pfh, *pfl, *pwh, *pwl;
    cudaGetSymbolAddress((void**)&pq,   g_q);
    cudaGetSymbolAddress((void**)&pk,   g_k);
    cudaGetSymbolAddress((void**)&pv,   g_v);
    cudaGetSymbolAddress((void**)&ptmp, g_tmp);
    cudaGetSymbolAddress((void**)&px1,  g_x1);
    cudaGetSymbolAddress((void**)&pah,  g_ah);
    cudaGetSymbolAddress((void**)&pal,  g_al);
    cudaGetSymbolAddress((void**)&pfh,  g_fh);
    cudaGetSymbolAddress((void**)&pfl,  g_fl);
    cudaGetSymbolAddress((void**)&pwh,  g_wh);
    cudaGetSymbolAddress((void**)&pwl,  g_wl);

    cudaFuncSetAttribute(attn_flash,
                         cudaFuncAttributeMaxDynamicSharedMemorySize, AF_SMEM);
    cudaFuncSetAttribute(mma_gemm<0>,
                         cudaFuncAttributeMaxDynamicSharedMemorySize, GSMEM);
    cudaFuncSetAttribute(mma_gemm<2>,
                         cudaFuncAttributeMaxDynamicSharedMemorySize, GSMEM);
    cudaFuncSetAttribute(mma_gemm<3>,
                         cudaFuncAttributeMaxDynamicSharedMemorySize, GSMEM);

    const int CONV_A = (int)(((size_t)NM * ND) / 2048);

    // V-chain first (independent) -> launch index 3 = mma_gemm (ncu slot)
    prep_decay<<<NH, 256>>>(gammas);                                     // 0
    wt_convert<<<dim3(32, 32), 256>>>(Wv, pwh, pwl, ND, ND);             // 1
    a_convert<<<CONV_A, 256>>>(values, pah, pal);                        // 2
    mma_gemm<2><<<dim3(8, 128), 128, GSMEM>>>(                           // 3 (ncu)
        pah, pal, pwh, pwl, bv, pv, nullptr, nullptr, ND, ND);

    // Q+K projections: fp32 FFMA (bit-exact precision path), one launch
    gemm_f32qk<<<dim3(8, 64, 2), 256>>>(query, key, Wk, bk, pq, pk);     // 4

    // attention writes attw + concat bf16 planes (g_ah/g_al) directly
    attn_flash<<<dim3(NS / 32, NB * NH), 256, AF_SMEM>>>(attw);          // 5

    wt_convert<<<dim3(32, 32), 256>>>(Wout, pwh, pwl, ND, ND);           // 6
    mma_gemm<0><<<dim3(8, 128), 128, GSMEM>>>(                           // 7
        pah, pal, pwh, pwl, bout, ptmp, nullptr, nullptr, ND, ND);
    ln_kernel<<<NM, 256>>>(query, ptmp, ln1_s, ln1_b, px1);              // 8

    wt_convert<<<dim3(128, 32), 256>>>(W1, pwh, pwl, ND, NDF);           // 9
    a_convert<<<CONV_A, 256>>>(px1, pah, pal);                           // 10
    mma_gemm<3><<<dim3(32, 128), 128, GSMEM>>>(                          // 11: FFN1 -> planes
        pah, pal, pwh, pwl, b1, nullptr, pfh, pfl, ND, NDF);
    wt_convert<<<dim3(32, 128), 256>>>(W2, pwh, pwl, NDF, ND);           // 12
    mma_gemm<0><<<dim3(8, 128), 128, GSMEM>>>(                           // 13: FFN2 reads planes
        pfh, pfl, pwh, pwl, b2, ptmp, nullptr, nullptr, NDF, ND);
    ln_kernel<<<NM, 256>>>(px1, ptmp, ln2_s, ln2_b, out);                // 14
}

// round 17
// speedup vs baseline: 2.2688x; 1.0009x over previous
#include <cuda_runtime.h>
#include <cuda_bf16.h>
#include <math.h>
#include <stdint.h>

#define NB 4
#define NS 2048
#define ND 1024
#define NH 16
#define NDK 64
#define NDF 4096
#define NM (NB*NS)
#define LN_EPS 1e-5f

static __device__ float g_q[(size_t)NM*ND];
static __device__ float g_k[(size_t)NM*ND];
static __device__ float g_v[(size_t)NM*ND];
static __device__ float g_tmp[(size_t)NM*ND];
static __device__ float g_x1[(size_t)NM*ND];
static __device__ float g_decay[NH*NS];
static __device__ __nv_bfloat16 g_ah[(size_t)NM*ND];    // A hi plane
static __device__ __nv_bfloat16 g_al[(size_t)NM*ND];    // A lo plane
static __device__ __nv_bfloat16 g_fh[(size_t)NM*NDF];   // FFN hidden hi
static __device__ __nv_bfloat16 g_fl[(size_t)NM*NDF];   // FFN hidden lo
static __device__ __nv_bfloat16 g_wh[(size_t)NDF*ND];   // W^T hi
static __device__ __nv_bfloat16 g_wl[(size_t)NDF*ND];   // W^T lo

__device__ __forceinline__ uint32_t smem_u32(const void* p) {
    uint32_t a;
    asm("{ .reg .u64 t; cvta.to.shared.u64 t, %1; cvt.u32.u64 %0, t; }"
        : "=r"(a) : "l"(p));
    return a;
}
#define CP_ASYNC16(dst, src) \
    asm volatile("cp.async.cg.shared.global [%0], [%1], 16;" \
                 :: "r"(dst), "l"(src) : "memory")
#define CP_COMMIT() asm volatile("cp.async.commit_group;" ::: "memory")
#define CP_WAIT0()  asm volatile("cp.async.wait_group 0;" ::: "memory")
#define CP_WAIT1()  asm volatile("cp.async.wait_group 1;" ::: "memory")

__device__ __forceinline__ void ldsm4(uint32_t& r0, uint32_t& r1,
                                      uint32_t& r2, uint32_t& r3, uint32_t a) {
    asm volatile("ldmatrix.sync.aligned.m8n8.x4.shared.b16 {%0,%1,%2,%3}, [%4];"
                 : "=r"(r0), "=r"(r1), "=r"(r2), "=r"(r3) : "r"(a));
}
__device__ __forceinline__ void mma16816(float* c, const uint32_t* a,
                                         const uint32_t* b) {
    asm volatile("mma.sync.aligned.m16n8k16.row.col.f32.bf16.bf16.f32 "
                 "{%0,%1,%2,%3}, {%4,%5,%6,%7}, {%8,%9}, {%0,%1,%2,%3};"
                 : "+f"(c[0]), "+f"(c[1]), "+f"(c[2]), "+f"(c[3])
                 : "r"(a[0]), "r"(a[1]), "r"(a[2]), "r"(a[3]),
                   "r"(b[0]), "r"(b[1]));
}

// ---------------- decay table ----------------------------------------------
__global__ void prep_decay(const float* __restrict__ gammas) {
    int h = blockIdx.x;
    float x = gammas[h];
    float sp = (x > 0.f) ? (x + log1pf(expf(-x))) : log1pf(expf(x));
    float g21 = sp * (1.0f / 21.0f);
    for (int i = threadIdx.x; i < NS; i += blockDim.x)
        g_decay[h * NS + i] = fminf(__expf((float)i * g21), 1e5f);
}

// ---------------- fp32 FFMA GEMM for Q+K (one launch, z selects) ----------
__global__ void __launch_bounds__(256)
gemm_f32qk(const float* __restrict__ A0, const float* __restrict__ A1,
           const float* __restrict__ W, const float* __restrict__ bias,
           float* __restrict__ out0, float* __restrict__ out1)
{
    const int K = ND, N = ND;
    __shared__ float As[2][16][132];
    __shared__ float Bs[2][16][132];
    const int t  = threadIdx.x;
    const int bm = blockIdx.y, bn = blockIdx.x;
    const float* A  = blockIdx.z ? A1 : A0;
    float* out      = blockIdx.z ? out1 : out0;
    const int arow = t >> 2, acol = (t & 3) << 2;
    const int brow = t >> 5, bcol = (t & 31) << 2;
    const float* Ab = A + (size_t)(bm * 128) * K;
    const float* Wb = W + bn * 128;

    float4 a0, a1, b0, b1;
    a0 = *(const float4*)(Ab + (size_t)arow * K + acol);
    a1 = *(const float4*)(Ab + (size_t)(arow + 64) * K + acol);
    b0 = *(const float4*)(Wb + (size_t)brow * N + bcol);
    b1 = *(const float4*)(Wb + (size_t)(brow + 8) * N + bcol);
    As[0][acol+0][arow] = a0.x; As[0][acol+1][arow] = a0.y;
    As[0][acol+2][arow] = a0.z; As[0][acol+3][arow] = a0.w;
    As[0][acol+0][arow+64] = a1.x; As[0][acol+1][arow+64] = a1.y;
    As[0][acol+2][arow+64] = a1.z; As[0][acol+3][arow+64] = a1.w;
    *(float4*)&Bs[0][brow][bcol]   = b0;
    *(float4*)&Bs[0][brow+8][bcol] = b1;
    __syncthreads();

    const int ty = t >> 4, tx = t & 15;
    float acc[8][8];
    #pragma unroll
    for (int i = 0; i < 8; i++)
        #pragma unroll
        for (int j = 0; j < 8; j++) acc[i][j] = 0.f;

    const int KT = K >> 4;
    int buf = 0;
    for (int kt = 0; kt < KT; ++kt) {
        if (kt + 1 < KT) {
            int k0 = (kt + 1) << 4;
            a0 = *(const float4*)(Ab + (size_t)arow * K + k0 + acol);
            a1 = *(const float4*)(Ab + (size_t)(arow + 64) * K + k0 + acol);
            b0 = *(const float4*)(Wb + (size_t)(k0 + brow) * N + bcol);
            b1 = *(const float4*)(Wb + (size_t)(k0 + brow + 8) * N + bcol);
        }
        #pragma unroll
        for (int k = 0; k < 16; k++) {
            float4 xa = *(const float4*)&As[buf][k][ty*8];
            float4 xb = *(const float4*)&As[buf][k][ty*8+4];
            float4 ya = *(const float4*)&Bs[buf][k][tx*8];
            float4 yb = *(const float4*)&Bs[buf][k][tx*8+4];
            float ar[8] = {xa.x,xa.y,xa.z,xa.w,xb.x,xb.y,xb.z,xb.w};
            float br[8] = {ya.x,ya.y,ya.z,ya.w,yb.x,yb.y,yb.z,yb.w};
            #pragma unroll
            for (int i = 0; i < 8; i++)
                #pragma unroll
                for (int j = 0; j < 8; j++)
                    acc[i][j] = fmaf(ar[i], br[j], acc[i][j]);
        }
        if (kt + 1 < KT) {
            int nb = buf ^ 1;
            As[nb][acol+0][arow] = a0.x; As[nb][acol+1][arow] = a0.y;
            As[nb][acol+2][arow] = a0.z; As[nb][acol+3][arow] = a0.w;
            As[nb][acol+0][arow+64] = a1.x; As[nb][acol+1][arow+64] = a1.y;
            As[nb][acol+2][arow+64] = a1.z; As[nb][acol+3][arow+64] = a1.w;
            *(float4*)&Bs[nb][brow][bcol]   = b0;
            *(float4*)&Bs[nb][brow+8][bcol] = b1;
        }
        __syncthreads();
        buf ^= 1;
    }

    const int gc0 = bn * 128 + tx * 8;
    #pragma unroll
    for (int i = 0; i < 8; i++) {
        int gr = bm * 128 + ty * 8 + i;
        int h = gc0 >> 6, d = gc0 & 63;
        int b = gr >> 11, s = gr & 2047;
        float* op = out + ((((size_t)b * NH + h) * NS + s) * NDK + d);
        #pragma unroll
        for (int j = 0; j < 8; j++) op[j] = acc[i][j] + bias[gc0 + j];
    }
}

// ---------------- fp32 -> bf16 hi/lo planes --------------------------------
__global__ void __launch_bounds__(256)
a_convert(const float* __restrict__ x, __nv_bfloat16* __restrict__ p0,
          __nv_bfloat16* __restrict__ p1)
{
    size_t i = ((size_t)blockIdx.x * 256 + threadIdx.x) * 8;
    float4 v0 = *(const float4*)(x + i);
    float4 v1 = *(const float4*)(x + i + 4);
    float vv[8] = {v0.x, v0.y, v0.z, v0.w, v1.x, v1.y, v1.z, v1.w};
    __align__(16) __nv_bfloat16 hh[8], ll[8];
    #pragma unroll
    for (int j = 0; j < 8; j++) {
        __nv_bfloat16 h = __float2bfloat16(vv[j]);
        hh[j] = h;
        ll[j] = __float2bfloat16(vv[j] - __bfloat162float(h));
    }
    *(uint4*)(p0 + i) = *(uint4*)hh;
    *(uint4*)(p1 + i) = *(uint4*)ll;
}

__global__ void __launch_bounds__(256)
wt_convert(const float* __restrict__ W, __nv_bfloat16* __restrict__ t0,
           __nv_bfloat16* __restrict__ t1, int K, int N)
{
    __shared__ float tile[32][33];
    int n0 = blockIdx.x * 32, k0 = blockIdx.y * 32;
    int tx = threadIdx.x & 31, ty = threadIdx.x >> 5;
    #pragma unroll
    for (int i = 0; i < 4; i++)
        tile[ty + i * 8][tx] = W[(size_t)(k0 + ty + i * 8) * N + n0 + tx];
    __syncthreads();
    #pragma unroll
    for (int i = 0; i < 4; i++) {
        float v = tile[tx][ty + i * 8];
        size_t o = (size_t)(n0 + ty + i * 8) * K + k0 + tx;
        __nv_bfloat16 h = __float2bfloat16(v);
        t0[o] = h;
        t1[o] = __float2bfloat16(v - __bfloat162float(h));
    }
}

// ---------------- split-bf16 HMMA GEMM (3-pass), 128-thr CTA, 64x128 tile --
// MMA issue is PASS-MAJOR (all hh, then hl, then lh): per-accumulator order
// unchanged (bit-exact) but 15 independent MMAs between RAW reuses.
#define A_PLANE 5120
#define B_PLANE 10240
#define STAGE_B 30720
#define GSMEM   (2 * STAGE_B)

template<int MODE>   // 0 plain fp32, 2 scatter [B,H,S,DK], 3 relu -> bf16 planes
__global__ void __launch_bounds__(128, 3)
mma_gemm(const __nv_bfloat16* __restrict__ ah, const __nv_bfloat16* __restrict__ al,
         const __nv_bfloat16* __restrict__ bh, const __nv_bfloat16* __restrict__ bl,
         const float* __restrict__ bias, float* __restrict__ out,
         __nv_bfloat16* __restrict__ ph, __nv_bfloat16* __restrict__ pl,
         int K, int Nt)
{
    extern __shared__ char dsm[];
    const uint32_t sb = smem_u32(dsm);
    const int t = threadIdx.x, wid = t >> 5, lane = t & 31;
    const int warp_m = wid & 1, warp_n = wid >> 1;
    const int m0 = blockIdx.y * 64, n0 = blockIdx.x * 128;

    const __nv_bfloat16* srcs[4] = {
        ah + (size_t)m0 * K, al + (size_t)m0 * K,
        bh + (size_t)n0 * K, bl + (size_t)n0 * K };

    uint32_t dsts[12], rowK[12], segO[12];
    int plid[12];
    #pragma unroll
    for (int u = 0; u < 12; u++) {
        int g = t + (u << 7);
        int rr = g >> 2, seg = g & 3;
        int pl_, row, off;
        if (rr < 64)       { pl_ = 0; row = rr;       off = 0; }
        else if (rr < 128) { pl_ = 1; row = rr - 64;  off = A_PLANE; }
        else if (rr < 256) { pl_ = 2; row = rr - 128; off = 2 * A_PLANE; }
        else               { pl_ = 3; row = rr - 256; off = 2 * A_PLANE + B_PLANE; }
        dsts[u] = off + row * 80 + seg * 16;
        rowK[u] = row; segO[u] = seg << 3; plid[u] = pl_;
    }

    const int a_row = warp_m * 32 + (lane & 15);
    const uint32_t a_col = (lane >> 4) * 16;
    const int b_row = warp_n * 64 + ((lane >> 4) << 3) + (lane & 7);
    const uint32_t b_col = ((lane >> 3) & 1) * 16;

    float acc[2][8][4];
    #pragma unroll
    for (int i = 0; i < 2; i++)
        #pragma unroll
        for (int j = 0; j < 8; j++)
            #pragma unroll
            for (int q = 0; q < 4; q++) acc[i][j][q] = 0.f;

    const int KT = K >> 5;
    int buf = 0;
    #pragma unroll
    for (int u = 0; u < 12; u++)
        CP_ASYNC16(sb + dsts[u], srcs[plid[u]] + (size_t)rowK[u] * K + segO[u]);
    CP_COMMIT();

    for (int kt = 0; kt < KT; ++kt) {
        if (kt + 1 < KT) {
            const int k0 = (kt + 1) << 5;
            const uint32_t base = sb + (buf ^ 1) * STAGE_B;
            #pragma unroll
            for (int u = 0; u < 12; u++)
                CP_ASYNC16(base + dsts[u],
                           srcs[plid[u]] + (size_t)rowK[u] * K + k0 + segO[u]);
            CP_COMMIT();
            CP_WAIT1();
        } else {
            CP_WAIT0();
        }
        __syncthreads();

        const uint32_t st = sb + buf * STAGE_B;
        #pragma unroll
        for (int ks = 0; ks < 2; ++ks) {
            const uint32_t kb = ks * 32;
            uint32_t ahf[2][4], alf[2][4];
            #pragma unroll
            for (int i = 0; i < 2; i++) {
                uint32_t ra = st + (a_row + i * 16) * 80 + kb + a_col;
                ldsm4(ahf[i][0], ahf[i][1], ahf[i][2], ahf[i][3], ra);
                ldsm4(alf[i][0], alf[i][1], alf[i][2], alf[i][3], ra + A_PLANE);
            }
            uint32_t bhf[8][2], blf[8][2];
            #pragma unroll
            for (int jj = 0; jj < 4; jj++) {
                uint32_t rb = st + 2 * A_PLANE + (b_row + jj * 16) * 80 + kb + b_col;
                ldsm4(bhf[2*jj][0], bhf[2*jj][1], bhf[2*jj+1][0], bhf[2*jj+1][1], rb);
                ldsm4(blf[2*jj][0], blf[2*jj][1], blf[2*jj+1][0], blf[2*jj+1][1],
                      rb + B_PLANE);
            }
            // pass-major: hh sweep, hl sweep, lh sweep (bit-exact per acc)
            #pragma unroll
            for (int i = 0; i < 2; i++)
                #pragma unroll
                for (int j = 0; j < 8; j++)
                    mma16816(acc[i][j], ahf[i], bhf[j]);
            #pragma unroll
            for (int i = 0; i < 2; i++)
                #pragma unroll
                for (int j = 0; j < 8; j++)
                    mma16816(acc[i][j], ahf[i], blf[j]);
            #pragma unroll
            for (int i = 0; i < 2; i++)
                #pragma unroll
                for (int j = 0; j < 8; j++)
                    mma16816(acc[i][j], alf[i], bhf[j]);
        }
        __syncthreads();
        buf ^= 1;
    }

    const int rb0 = m0 + warp_m * 32 + (lane >> 2);
    const int cb0 = n0 + warp_n * 64 + (lane & 3) * 2;
    #pragma unroll
    for (int i = 0; i < 2; i++) {
        #pragma unroll
        for (int j = 0; j < 8; j++) {
            const int col = cb0 + j * 8;
            const float bb0 = bias[col], bb1 = bias[col + 1];
            #pragma unroll
            for (int half = 0; half < 2; half++) {
                const int row = rb0 + i * 16 + half * 8;
                float v0 = acc[i][j][half * 2 + 0] + bb0;
                float v1 = acc[i][j][half * 2 + 1] + bb1;
                if (MODE == 3) {
                    v0 = fmaxf(v0, 0.f); v1 = fmaxf(v1, 0.f);
                    __nv_bfloat16 h0 = __float2bfloat16(v0);
                    __nv_bfloat16 h1 = __float2bfloat16(v1);
                    __nv_bfloat16 l0 = __float2bfloat16(v0 - __bfloat162float(h0));
                    __nv_bfloat16 l1 = __float2bfloat16(v1 - __bfloat162float(h1));
                    size_t o = (size_t)row * Nt + col;
                    __nv_bfloat162 hp; hp.x = h0; hp.y = h1;
                    __nv_bfloat162 lp; lp.x = l0; lp.y = l1;
                    *(__nv_bfloat162*)(ph + o) = hp;
                    *(__nv_bfloat162*)(pl + o) = lp;
                } else {
                    float* op;
                    if (MODE == 2) {
                        int h = col >> 6, d = col & 63;
                        int b = row >> 11, s = row & 2047;
                        op = out + ((((size_t)b * NH + h) * NS + s) * NDK + d);
                    } else {
                        op = out + (size_t)row * Nt + col;
                    }
                    float2 r2; r2.x = v0; r2.y = v1;
                    *(float2*)op = r2;
                }
            }
        }
    }
}

// ---------------- flash attention: 32 rows/CTA, 4 rows/warp ----------------
#define AF_SMEM (25600 * 4)

__device__ __forceinline__ void stage_kv(uint32_t dst, const float* __restrict__ src,
                                         int c0, int t) {
    #pragma unroll
    for (int i = 0; i < 8; i++) {
        int idx = t + (i << 8);
        int c = idx >> 4, gd = idx & 15;
        CP_ASYNC16(dst + (c << 8) + ((gd ^ (c & 15)) << 4),
                   src + (size_t)(c0 + c) * NDK + (gd << 2));
    }
}

__global__ void __launch_bounds__(256, 2)
attn_flash(float* __restrict__ attw)
{
    extern __shared__ float sm[];
    float* dtab = sm;            // 2048
    float* qs   = sm + 2048;     // 2048
    float* ksm  = sm + 4096;     // 8192
    float* vsm  = sm + 12288;    // 8192
    float* ws   = sm + 20480;    // 4096
    float* mch  = sm + 24576;    // 512
    float* fs   = sm + 25088;    // 512

    const int t = threadIdx.x, lane = t & 31, w = t >> 5;
    const int bh = blockIdx.y, hh = bh & 15, bb = bh >> 4;
    const int qi0 = blockIdx.x << 5;

    const float* qb = g_q + (size_t)bh * NS * NDK;
    const float* kb = g_k + (size_t)bh * NS * NDK;
    const float* vb = g_v + (size_t)bh * NS * NDK;
    const uint32_t ku = smem_u32(ksm), vu = smem_u32(vsm);
    const int nch = (qi0 >> 7) + 1;

    stage_kv(ku, kb, 0, t);
    stage_kv(vu, vb, 0, t);
    CP_COMMIT();

    {
        const float* dt = g_decay + hh * NS;
        *(float4*)&dtab[t * 8]     = *(const float4*)(dt + t * 8);
        *(float4*)&dtab[t * 8 + 4] = *(const float4*)(dt + t * 8 + 4);
        const float* qsrc = qb + (size_t)qi0 * NDK;
        *(float4*)&qs[t * 8]       = *(const float4*)(qsrc + t * 8);
        *(float4*)&qs[t * 8 + 4]   = *(const float4*)(qsrc + t * 8 + 4);
    }

    float m[4], Z[4], ax[4], ay[4];
    #pragma unroll
    for (int r = 0; r < 4; r++) { m[r] = -3.0e38f; Z[r] = 0.f; ax[r] = 0.f; ay[r] = 0.f; }

    const int gd3 = lane >> 1, half = (lane & 1) << 1;
    const int sw = lane & 15;
    float* wsw = ws + w * 512;

    for (int ch = 0; ch < nch; ++ch) {
        const int c0 = ch << 7;
        CP_WAIT0();
        __syncthreads();

        float acc[4][4];
        #pragma unroll
        for (int r = 0; r < 4; r++)
            #pragma unroll
            for (int j = 0; j < 4; j++) acc[r][j] = 0.f;

        #pragma unroll
        for (int gd = 0; gd < 16; ++gd) {
            float4 qv[4];
            #pragma unroll
            for (int r = 0; r < 4; r++)
                qv[r] = *(const float4*)&qs[((w * 4 + r) << 6) + (gd << 2)];
            const int g2 = (gd ^ sw) << 2;
            #pragma unroll
            for (int j = 0; j < 4; j++) {
                float4 kv = *(const float4*)&ksm[((lane + (j << 5)) << 6) + g2];
                #pragma unroll
                for (int r = 0; r < 4; r++)
                    acc[r][j] += qv[r].x*kv.x + qv[r].y*kv.y + qv[r].z*kv.z + qv[r].w*kv.w;
            }
        }

        #pragma unroll
        for (int r = 0; r < 4; r++) {
            const int qi = qi0 + w * 4 + r;
            float s[4];
            #pragma unroll
            for (int j = 0; j < 4; j++) {
                int c = c0 + lane + (j << 5);
                s[j] = (c <= qi) ? acc[r][j] * 0.125f * dtab[qi - c] : -3.0e38f;
            }
            float cm = fmaxf(fmaxf(s[0], s[1]), fmaxf(s[2], s[3]));
            #pragma unroll
            for (int o = 16; o; o >>= 1)
                cm = fmaxf(cm, __shfl_xor_sync(0xffffffffu, cm, o));
            const float mnew = fmaxf(m[r], cm);
            const float scale = __expf(m[r] - mnew);
            float e[4], zs = 0.f;
            #pragma unroll
            for (int j = 0; j < 4; j++) {
                int c = c0 + lane + (j << 5);
                e[j] = (c <= qi) ? __expf(s[j] - mnew) : 0.f;
                zs += e[j];
            }
            #pragma unroll
            for (int o = 16; o; o >>= 1)
                zs += __shfl_xor_sync(0xffffffffu, zs, o);
            Z[r] = Z[r] * scale + zs;
            ax[r] *= scale; ay[r] *= scale;
            m[r] = mnew;
            if (lane == 0) mch[(w * 4 + r) * 16 + ch] = mnew;
            float* arow = attw + ((size_t)bh * NS + qi) * NS + c0;
            #pragma unroll
            for (int j = 0; j < 4; j++) {
                wsw[((lane + (j << 5)) << 2) + r] = e[j];
                arow[lane + (j << 5)] = e[j];
            }
        }
        __syncwarp();

        #pragma unroll 2
        for (int c = 0; c < 128; ++c) {
            float4 wv = *(const float4*)&wsw[c << 2];
            float2 vv = *(const float2*)&vsm[(c << 6) + ((gd3 ^ (c & 15)) << 2) + half];
            ax[0] += wv.x * vv.x; ay[0] += wv.x * vv.y;
            ax[1] += wv.y * vv.x; ay[1] += wv.y * vv.y;
            ax[2] += wv.z * vv.x; ay[2] += wv.z * vv.y;
            ax[3] += wv.w * vv.x; ay[3] += wv.w * vv.y;
        }
        __syncthreads();
        if (ch + 1 < nch) {
            stage_kv(ku, kb, c0 + 128, t);
            stage_kv(vu, vb, c0 + 128, t);
            CP_COMMIT();
        }
    }

    // ctx out: write bf16 hi/lo planes directly (same split as a_convert)
    #pragma unroll
    for (int r = 0; r < 4; r++) {
        const int qi = qi0 + w * 4 + r;
        const float iz = 1.0f / Z[r];
        float v0 = ax[r] * iz, v1 = ay[r] * iz;
        __nv_bfloat16 h0 = __float2bfloat16(v0);
        __nv_bfloat16 h1 = __float2bfloat16(v1);
        __nv_bfloat16 l0 = __float2bfloat16(v0 - __bfloat162float(h0));
        __nv_bfloat16 l1 = __float2bfloat16(v1 - __bfloat162float(h1));
        size_t o = ((size_t)bb * NS + qi) * ND + hh * NDK + (lane << 1);
        __nv_bfloat162 hp; hp.x = h0; hp.y = h1;
        __nv_bfloat162 lp; lp.x = l0; lp.y = l1;
        *(__nv_bfloat162*)(g_ah + o) = hp;
        *(__nv_bfloat162*)(g_al + o) = lp;
    }
    #pragma unroll
    for (int u = 0; u < 2; u++) {
        int idx = lane + u * 32;
        int r2 = idx >> 4, ch = idx & 15;
        fs[w * 64 + idx] = __expf(mch[(w * 4 + r2) * 16 + ch] - m[r2]) / Z[r2];
    }
    __syncwarp();

    #pragma unroll
    for (int r = 0; r < 4; r++) {
        const int qi = qi0 + w * 4 + r;
        const int bch = qi >> 7;
        float* arow = attw + ((size_t)bh * NS + qi) * NS;
        #pragma unroll 4
        for (int it = 0; it < 16; it++) {
            int c = it * 128 + lane * 4;
            float4 v;
            if (it > bch) {
                v.x = 0.f; v.y = 0.f; v.z = 0.f; v.w = 0.f;
            } else {
                float f = fs[w * 64 + r * 16 + it];
                v = *(float4*)(arow + c);
                v.x = (c + 0 <= qi) ? v.x * f : 0.f;
                v.y = (c + 1 <= qi) ? v.y * f : 0.f;
                v.z = (c + 2 <= qi) ? v.z * f : 0.f;
                v.w = (c + 3 <= qi) ? v.w * f : 0.f;
            }
            *(float4*)(arow + c) = v;
        }
    }
}

// ---------------- residual + layernorm -------------------------------------
__global__ void __launch_bounds__(256)
ln_kernel(const float* __restrict__ xa, const float* __restrict__ xb,
          const float* __restrict__ sg, const float* __restrict__ bg,
          float* __restrict__ out)
{
    __shared__ float red[16];
    const int row = blockIdx.x, t = threadIdx.x;
    const int lane = t & 31, wid = t >> 5;
    const size_t base = (size_t)row * ND;

    float v[4];
    #pragma unroll
    for (int i = 0; i < 4; i++) {
        int idx = t + (i << 8);
        v[i] = xa[base + idx] + xb[base + idx];
    }
    float s = v[0] + v[1] + v[2] + v[3];
    #pragma unroll
    for (int o = 16; o; o >>= 1) s += __shfl_xor_sync(0xffffffffu, s, o);
    if (lane == 0) red[wid] = s;
    __syncthreads();
    if (t == 0) {
        float tot = 0.f;
        for (int i = 0; i < 8; i++) tot += red[i];
        red[8] = tot;
    }
    __syncthreads();
    const float mean = red[8] * (1.0f / ND);

    float q = 0.f;
    #pragma unroll
    for (int i = 0; i < 4; i++) { float d = v[i] - mean; q += d * d; }
    #pragma unroll
    for (int o = 16; o; o >>= 1) q += __shfl_xor_sync(0xffffffffu, q, o);
    if (lane == 0) red[wid] = q;
    __syncthreads();
    if (t == 0) {
        float tot = 0.f;
        for (int i = 0; i < 8; i++) tot += red[i];
        red[9] = tot;
    }
    __syncthreads();
    const float rs = rsqrtf(red[9] * (1.0f / ND) + LN_EPS);

    #pragma unroll
    for (int i = 0; i < 4; i++) {
        int idx = t + (i << 8);
        out[base + idx] = (v[i] - mean) * rs * sg[idx] + bg[idx];
    }
}

// ---------------- launcher --------------------------------------------------
extern "C" void kernel_launch(void* const* d_in, const int* in_sizes, int n_in,
                              void* d_out, int out_size)
{
    const float* query  = (const float*)d_in[0];
    const float* key    = (const float*)d_in[1];
    const float* values = (const float*)d_in[2];
    const float* Wk     = (const float*)d_in[3];
    const float* bk     = (const float*)d_in[4];
    const float* Wv     = (const float*)d_in[5];
    const float* bv     = (const float*)d_in[6];
    const float* Wout   = (const float*)d_in[7];
    const float* bout   = (const float*)d_in[8];
    const float* gammas = (const float*)d_in[9];
    const float* ln1_s  = (const float*)d_in[10];
    const float* ln1_b  = (const float*)d_in[11];
    const float* W1     = (const float*)d_in[12];
    const float* b1     = (const float*)d_in[13];
    const float* W2     = (const float*)d_in[14];
    const float* b2     = (const float*)d_in[15];
    const float* ln2_s  = (const float*)d_in[16];
    const float* ln2_b  = (const float*)d_in[17];

    float* out  = (float*)d_out;
    float* attw = out + (size_t)NM * ND;

    float *pq, *pk, *pv, *ptmp, *px1;
    __nv_bfloat16 *pah, *pal, *pfh, *pfl, *pwh, *pwl;
    cudaGetSymbolAddress((void**)&pq,   g_q);
    cudaGetSymbolAddress((void**)&pk,   g_k);
    cudaGetSymbolAddress((void**)&pv,   g_v);
    cudaGetSymbolAddress((void**)&ptmp, g_tmp);
    cudaGetSymbolAddress((void**)&px1,  g_x1);
    cudaGetSymbolAddress((void**)&pah,  g_ah);
    cudaGetSymbolAddress((void**)&pal,  g_al);
    cudaGetSymbolAddress((void**)&pfh,  g_fh);
    cudaGetSymbolAddress((void**)&pfl,  g_fl);
    cudaGetSymbolAddress((void**)&pwh,  g_wh);
    cudaGetSymbolAddress((void**)&pwl,  g_wl);

    cudaFuncSetAttribute(attn_flash,
                         cudaFuncAttributeMaxDynamicSharedMemorySize, AF_SMEM);
    cudaFuncSetAttribute(mma_gemm<0>,
                         cudaFuncAttributeMaxDynamicSharedMemorySize, GSMEM);
    cudaFuncSetAttribute(mma_gemm<2>,
                         cudaFuncAttributeMaxDynamicSharedMemorySize, GSMEM);
    cudaFuncSetAttribute(mma_gemm<3>,
                         cudaFuncAttributeMaxDynamicSharedMemorySize, GSMEM);
    // try to allow 3 co-resident CTAs (max smem carveout)
    cudaFuncSetAttribute(mma_gemm<0>,
                         cudaFuncAttributePreferredSharedMemoryCarveout, 100);
    cudaFuncSetAttribute(mma_gemm<2>,
                         cudaFuncAttributePreferredSharedMemoryCarveout, 100);
    cudaFuncSetAttribute(mma_gemm<3>,
                         cudaFuncAttributePreferredSharedMemoryCarveout, 100);

    const int CONV_A = (int)(((size_t)NM * ND) / 2048);

    // V-chain first (independent) -> launch index 3 = mma_gemm (ncu slot)
    prep_decay<<<NH, 256>>>(gammas);                                     // 0
    wt_convert<<<dim3(32, 32), 256>>>(Wv, pwh, pwl, ND, ND);             // 1
    a_convert<<<CONV_A, 256>>>(values, pah, pal);                        // 2
    mma_gemm<2><<<dim3(8, 128), 128, GSMEM>>>(                           // 3 (ncu)
        pah, pal, pwh, pwl, bv, pv, nullptr, nullptr, ND, ND);

    // Q+K projections: fp32 FFMA (bit-exact precision path), one launch
    gemm_f32qk<<<dim3(8, 64, 2), 256>>>(query, key, Wk, bk, pq, pk);     // 4

    // attention writes attw + concat bf16 planes (g_ah/g_al) directly
    attn_flash<<<dim3(NS / 32, NB * NH), 256, AF_SMEM>>>(attw);          // 5

    wt_convert<<<dim3(32, 32), 256>>>(Wout, pwh, pwl, ND, ND);           // 6
    mma_gemm<0><<<dim3(8, 128), 128, GSMEM>>>(                           // 7
        pah, pal, pwh, pwl, bout, ptmp, nullptr, nullptr, ND, ND);
    ln_kernel<<<NM, 256>>>(query, ptmp, ln1_s, ln1_b, px1);              // 8

    wt_convert<<<dim3(128, 32), 256>>>(W1, pwh, pwl, ND, NDF);           // 9
    a_convert<<<CONV_A, 256>>>(px1, pah, pal);                           // 10
    mma_gemm<3><<<dim3(32, 128), 128, GSMEM>>>(                          // 11: FFN1 -> planes
        pah, pal, pwh, pwl, b1, nullptr, pfh, pfl, ND, NDF);
    wt_convert<<<dim3(32, 128), 256>>>(W2, pwh, pwl, NDF, ND);           // 12
    mma_gemm<0><<<dim3(8, 128), 128, GSMEM>>>(                           // 13: FFN2 reads planes
        pfh, pfl, pwh, pwl, b2, ptmp, nullptr, nullptr, NDF, ND);
    ln_kernel<<<NM, 256>>>(px1, ptmp, ln2_s, ln2_b, out);                // 14
}